// round 9
// baseline (speedup 1.0000x reference)
#include <cuda_runtime.h>
#include <cuda_bf16.h>
#include <cstdint>

// ---------------------------------------------------------------------------
// B=131072, chain 512 ->(W1)512 ->(W2)128 ->(W3)32 ->(W4)8 ->(Wh)1
// Composition of best-measured variants:
//   split_x: fp32 -> bf16 hi/lo                      (~90 us)
//   GEMM1  : R6 hgemm3 (cp.async A+B, 3-stage ring, LN partials)  (466 us)
//   GEMM2  : R8 fused LN1+CELU+split -> HMMA -> LN2+CELU          (263 us)
//   tail   : layers 3/4 + spectral-norm head                       (~35 us)
// ---------------------------------------------------------------------------

#define BATCH 131072

__device__ __align__(256) __nv_bfloat16 g_xhi  [BATCH * 512];
__device__ __align__(256) __nv_bfloat16 g_xlo  [BATCH * 512];
__device__ __align__(256) float         g_h1raw[BATCH * 512];
__device__ __align__(256) float         g_h2   [BATCH * 128];
__device__ __align__(256) float2        g_part [4 * BATCH];
__device__ __align__(256) __nv_bfloat16 g_w1hi [512 * 512];
__device__ __align__(256) __nv_bfloat16 g_w1lo [512 * 512];
__device__ __align__(256) __nv_bfloat16 g_w2hi [128 * 512];
__device__ __align__(256) __nv_bfloat16 g_w2lo [128 * 512];

// ------------------------------ helpers ------------------------------------
__device__ __forceinline__ uint32_t smem_u32(const void* p) {
    uint32_t a;
    asm("{ .reg .u64 t; cvta.to.shared.u64 t, %1; cvt.u32.u64 %0, t; }"
        : "=r"(a) : "l"(p));
    return a;
}
__device__ __forceinline__ void cp_async16(uint32_t dst, const void* src) {
    asm volatile("cp.async.cg.shared.global [%0], [%1], 16;"
                 :: "r"(dst), "l"(src) : "memory");
}
#define CP_COMMIT() asm volatile("cp.async.commit_group;" ::: "memory")
#define CP_WAIT(n)  asm volatile("cp.async.wait_group %0;" :: "n"(n) : "memory")

__device__ __forceinline__ void ldmx4(uint32_t& r0, uint32_t& r1,
                                      uint32_t& r2, uint32_t& r3, uint32_t a) {
    asm volatile("ldmatrix.sync.aligned.m8n8.x4.shared.b16 {%0,%1,%2,%3}, [%4];"
                 : "=r"(r0), "=r"(r1), "=r"(r2), "=r"(r3) : "r"(a));
}
__device__ __forceinline__ void mma16816(float& c0, float& c1, float& c2, float& c3,
                                         uint32_t a0, uint32_t a1, uint32_t a2, uint32_t a3,
                                         uint32_t b0, uint32_t b1) {
    asm volatile("mma.sync.aligned.m16n8k16.row.col.f32.bf16.bf16.f32 "
                 "{%0,%1,%2,%3}, {%4,%5,%6,%7}, {%8,%9}, {%0,%1,%2,%3};"
                 : "+f"(c0), "+f"(c1), "+f"(c2), "+f"(c3)
                 : "r"(a0), "r"(a1), "r"(a2), "r"(a3), "r"(b0), "r"(b1));
}
__device__ __forceinline__ float warp_sum(float v) {
#pragma unroll
    for (int o = 16; o; o >>= 1) v += __shfl_xor_sync(0xffffffffu, v, o);
    return v;
}
__device__ __forceinline__ uint32_t swz(uint32_t row, uint32_t q) {
    return row * 64 + (q ^ ((row & 6u) >> 1)) * 16;
}
__device__ __forceinline__ float celu1(float y) {
    return (y > 0.f) ? y : expm1f(y);
}
__device__ __forceinline__ uint32_t pack_bf16(float a0, float a1) {
    __nv_bfloat162 t; t.x = __float2bfloat16(a0); t.y = __float2bfloat16(a1);
    return *reinterpret_cast<uint32_t*>(&t);
}
__device__ __forceinline__ void split2(float a0, float a1, uint32_t& hp, uint32_t& lp) {
    __nv_bfloat16 h0 = __float2bfloat16(a0), h1 = __float2bfloat16(a1);
    hp = (uint32_t)__bfloat16_as_ushort(h1) << 16 | (uint32_t)__bfloat16_as_ushort(h0);
    lp = pack_bf16(a0 - __bfloat162float(h0), a1 - __bfloat162float(h1));
}

// ---------------------------------------------------------------------------
// Split fp32 -> bf16 hi + lo.
// ---------------------------------------------------------------------------
__global__ void __launch_bounds__(256)
split_kernel(const float* __restrict__ src, __nv_bfloat16* __restrict__ hi,
             __nv_bfloat16* __restrict__ lo, int n4)
{
    int i = blockIdx.x * blockDim.x + threadIdx.x;
    if (i >= n4) return;
    float4 v = reinterpret_cast<const float4*>(src)[i];
    uint32_t h0, l0, h1, l1;
    split2(v.x, v.y, h0, l0);
    split2(v.z, v.w, h1, l1);
    reinterpret_cast<uint32_t*>(hi)[2 * i]     = h0;
    reinterpret_cast<uint32_t*>(hi)[2 * i + 1] = h1;
    reinterpret_cast<uint32_t*>(lo)[2 * i]     = l0;
    reinterpret_cast<uint32_t*>(lo)[2 * i + 1] = l1;
}

// ---------------------------------------------------------------------------
// GEMM1 (R6-proven): C[M,512] = A @ B^T + bias, bf16x3 HMMA, 3-stage ring of
// (Ahi,Alo,Bhi,Blo) each 8192 B; 1 barrier/stage; LN partials in epilogue.
// ---------------------------------------------------------------------------
__global__ void __launch_bounds__(256, 2)
hgemm3_kernel(const __nv_bfloat16* __restrict__ Ahi, const __nv_bfloat16* __restrict__ Alo,
              const __nv_bfloat16* __restrict__ Bhi, const __nv_bfloat16* __restrict__ Blo,
              const float* __restrict__ bias, float* __restrict__ C,
              float2* __restrict__ gpart, int N, int Mtot)
{
    constexpr int K = 512;
    constexpr int NSTAGES = K / 32;
    constexpr int MAT = 128 * 64;            // 8192 B
    constexpr int STG = 4 * MAT;             // 32768 B
    constexpr int NBUF = 3;

    extern __shared__ char smem[];
    __shared__ float2 sred[4][128];
    const uint32_t sb = smem_u32(smem);

    const int tid   = threadIdx.x;
    const int lane  = tid & 31;
    const int wid   = tid >> 5;
    const int warpM = wid >> 2;
    const int warpN = wid & 3;
    const size_t rowBase = (size_t)blockIdx.y * 128;
    const int    colBase = blockIdx.x * 128;

    const int c0r = tid >> 2,  cq = tid & 3;
    const int c1r = 64 + (tid >> 2);
    const uint32_t d0 = swz(c0r, cq);
    const uint32_t d1 = swz(c1r, cq);

    float acc[4][4][4];
#pragma unroll
    for (int i = 0; i < 4; i++)
#pragma unroll
        for (int j = 0; j < 4; j++)
#pragma unroll
            for (int q = 0; q < 4; q++) acc[i][j][q] = 0.f;

    auto load_stage = [&](int t) {
        const int k0 = t * 32;
        const uint32_t s = sb + (t % NBUF) * STG;
        {
            const size_t g0 = (rowBase + c0r) * K + k0 + cq * 8;
            const size_t g1 = (rowBase + c1r) * K + k0 + cq * 8;
            cp_async16(s + d0,           Ahi + g0);
            cp_async16(s + d1,           Ahi + g1);
            cp_async16(s + MAT + d0,     Alo + g0);
            cp_async16(s + MAT + d1,     Alo + g1);
        }
        {
            const size_t g0 = (size_t)(colBase + c0r) * K + k0 + cq * 8;
            const size_t g1 = (size_t)(colBase + c1r) * K + k0 + cq * 8;
            cp_async16(s + 2 * MAT + d0, Bhi + g0);
            cp_async16(s + 2 * MAT + d1, Bhi + g1);
            cp_async16(s + 3 * MAT + d0, Blo + g0);
            cp_async16(s + 3 * MAT + d1, Blo + g1);
        }
        CP_COMMIT();
    };

    load_stage(0);
    load_stage(1);

#pragma unroll 1
    for (int t = 0; t < NSTAGES; t++) {
        if (t + 1 < NSTAGES) { CP_WAIT(1); } else { CP_WAIT(0); }
        __syncthreads();
        if (t + 2 < NSTAGES) load_stage(t + 2);

        const uint32_t s = sb + (t % NBUF) * STG;
#pragma unroll
        for (int ks = 0; ks < 2; ks++) {
            uint32_t ah[4][4], al[4][4];
            const uint32_t arow = warpM * 64 + (lane & 15);
            const uint32_t aq   = ks * 2 + (lane >> 4);
#pragma unroll
            for (int mt = 0; mt < 4; mt++) {
                const uint32_t adr = s + swz(arow + mt * 16, aq);
                ldmx4(ah[mt][0], ah[mt][1], ah[mt][2], ah[mt][3], adr);
                ldmx4(al[mt][0], al[mt][1], al[mt][2], al[mt][3], adr + MAT);
            }
            const uint32_t brow0 = warpN * 32 + (lane & 7) + ((lane >> 4) & 1) * 8;
            const uint32_t bq    = ks * 2 + ((lane >> 3) & 1);
#pragma unroll
            for (int pr = 0; pr < 2; pr++) {
                uint32_t bh0, bh1, bh2, bh3, bl0, bl1, bl2, bl3;
                const uint32_t adr = s + 2 * MAT + swz(brow0 + pr * 16, bq);
                ldmx4(bh0, bh1, bh2, bh3, adr);
                ldmx4(bl0, bl1, bl2, bl3, adr + MAT);
#pragma unroll
                for (int mt = 0; mt < 4; mt++) {
                    float* c0 = acc[mt][2 * pr];
                    mma16816(c0[0], c0[1], c0[2], c0[3],
                             ah[mt][0], ah[mt][1], ah[mt][2], ah[mt][3], bh0, bh1);
                    mma16816(c0[0], c0[1], c0[2], c0[3],
                             ah[mt][0], ah[mt][1], ah[mt][2], ah[mt][3], bl0, bl1);
                    mma16816(c0[0], c0[1], c0[2], c0[3],
                             al[mt][0], al[mt][1], al[mt][2], al[mt][3], bh0, bh1);
                    float* c1 = acc[mt][2 * pr + 1];
                    mma16816(c1[0], c1[1], c1[2], c1[3],
                             ah[mt][0], ah[mt][1], ah[mt][2], ah[mt][3], bh2, bh3);
                    mma16816(c1[0], c1[1], c1[2], c1[3],
                             ah[mt][0], ah[mt][1], ah[mt][2], ah[mt][3], bl2, bl3);
                    mma16816(c1[0], c1[1], c1[2], c1[3],
                             al[mt][0], al[mt][1], al[mt][2], al[mt][3], bh2, bh3);
                }
            }
        }
    }

    // ---- epilogue: + bias, fp32 out, per-row partial (sum, ssq) ----
#pragma unroll
    for (int mt = 0; mt < 4; mt++) {
        const int rloc = warpM * 64 + mt * 16 + (lane >> 2);
        const size_t r0 = rowBase + rloc;
        float s0 = 0.f, q0 = 0.f, s1 = 0.f, q1 = 0.f;
#pragma unroll
        for (int nt = 0; nt < 4; nt++) {
            const int col = colBase + warpN * 32 + nt * 8 + (lane & 3) * 2;
            const float b0 = bias[col], b1 = bias[col + 1];
            float* c = acc[mt][nt];
            const float v00 = c[0] + b0, v01 = c[1] + b1;
            const float v10 = c[2] + b0, v11 = c[3] + b1;
            *reinterpret_cast<float2*>(C + r0 * N + col)       = make_float2(v00, v01);
            *reinterpret_cast<float2*>(C + (r0 + 8) * N + col) = make_float2(v10, v11);
            s0 += v00 + v01; q0 += v00 * v00 + v01 * v01;
            s1 += v10 + v11; q1 += v10 * v10 + v11 * v11;
        }
#pragma unroll
        for (int o = 1; o <= 2; o <<= 1) {
            s0 += __shfl_xor_sync(0xffffffffu, s0, o);
            q0 += __shfl_xor_sync(0xffffffffu, q0, o);
            s1 += __shfl_xor_sync(0xffffffffu, s1, o);
            q1 += __shfl_xor_sync(0xffffffffu, q1, o);
        }
        if ((lane & 3) == 0) {
            sred[warpN][rloc]     = make_float2(s0, q0);
            sred[warpN][rloc + 8] = make_float2(s1, q1);
        }
    }
    __syncthreads();
    if (tid < 128) {
        float s = 0.f, q = 0.f;
#pragma unroll
        for (int w = 0; w < 4; w++) { s += sred[w][tid].x; q += sred[w][tid].y; }
        gpart[(size_t)blockIdx.x * Mtot + rowBase + tid] = make_float2(s, q);
    }
}

// smem layout for GEMM2: B ring 3 x 16K at 0, A ring 3 x 16K at 49152.
#define B_STG   16384
#define OFF_BLO 8192
#define OFF_A   49152
#define A_STG   16384
#define OFF_ALO 8192
#define SMEM_DYN 98304

// ---------------------------------------------------------------------------
// GEMM2 fused (R8-proven): a1 = celu(LN1(h1raw)) in regs -> HMMA bf16x3 ->
// LN2+CELU epilogue -> h2.
// ---------------------------------------------------------------------------
__global__ void __launch_bounds__(256, 2)
gemm2_fused_kernel(const float* __restrict__ h1raw, const float2* __restrict__ gpart,
                   const float* __restrict__ g1, const float* __restrict__ be1,
                   const __nv_bfloat16* __restrict__ Bhi, const __nv_bfloat16* __restrict__ Blo,
                   const float* __restrict__ b2, const float* __restrict__ g2,
                   const float* __restrict__ be2,
                   float* __restrict__ h2, int Mtot)
{
    constexpr int K = 512;
    constexpr int NSTAGES = K / 32;
    extern __shared__ char smem[];
    __shared__ float  smu[128], srstd[128];
    __shared__ float  sg1[512], sbe1[512];
    __shared__ float  sg2[128], sbe2[128], sb2[128];
    __shared__ float2 sred[4][128];
    const uint32_t sb = smem_u32(smem);

    const int tid   = threadIdx.x;
    const int lane  = tid & 31;
    const int wid   = tid >> 5;
    const int warpM = wid >> 2;
    const int warpN = wid & 3;
    const size_t rowBase = (size_t)blockIdx.x * 128;

    if (tid < 128) {
        float s = 0.f, q = 0.f;
#pragma unroll
        for (int b = 0; b < 4; b++) {
            float2 p = gpart[(size_t)b * Mtot + rowBase + tid];
            s += p.x; q += p.y;
        }
        const float mu = s * (1.f / 512.f);
        smu[tid]   = mu;
        srstd[tid] = rsqrtf(q * (1.f / 512.f) - mu * mu + 1e-5f);
        sg2[tid] = g2[tid]; sbe2[tid] = be2[tid]; sb2[tid] = b2[tid];
    }
#pragma unroll
    for (int i = tid; i < 512; i += 256) { sg1[i] = g1[i]; sbe1[i] = be1[i]; }
    __syncthreads();

    const int c0r = tid >> 2,  cq = tid & 3;
    const int c1r = 64 + c0r;
    const uint32_t d0 = swz(c0r, cq);
    const uint32_t d1 = swz(c1r, cq);

    const float* a0p = h1raw + (rowBase + c0r) * K + cq * 8;
    const float* a1p = h1raw + (rowBase + c1r) * K + cq * 8;
    const float mu0 = smu[c0r], rs0 = srstd[c0r];
    const float mu1 = smu[c1r], rs1 = srstd[c1r];

    float acc[4][4][4];
#pragma unroll
    for (int i = 0; i < 4; i++)
#pragma unroll
        for (int j = 0; j < 4; j++)
#pragma unroll
            for (int q = 0; q < 4; q++) acc[i][j][q] = 0.f;

    float4 fA[4];
    auto prefetchA = [&](int t) {
        fA[0] = *reinterpret_cast<const float4*>(a0p + t * 32);
        fA[1] = *reinterpret_cast<const float4*>(a0p + t * 32 + 4);
        fA[2] = *reinterpret_cast<const float4*>(a1p + t * 32);
        fA[3] = *reinterpret_cast<const float4*>(a1p + t * 32 + 4);
    };
    auto load_B = [&](int t) {
        const int k0 = t * 32;
        const uint32_t s = sb + (t % 3) * B_STG;
        const size_t g0 = (size_t)c0r * K + k0 + cq * 8;
        const size_t g1 = (size_t)c1r * K + k0 + cq * 8;
        cp_async16(s + d0,           Bhi + g0);
        cp_async16(s + d1,           Bhi + g1);
        cp_async16(s + OFF_BLO + d0, Blo + g0);
        cp_async16(s + OFF_BLO + d1, Blo + g1);
        CP_COMMIT();
    };

    prefetchA(0);
    load_B(0);
    load_B(1);

#pragma unroll 1
    for (int t = 0; t < NSTAGES; t++) {
        // convert A(t): LN1 + CELU + split -> buffer t%3
        {
            const uint32_t abase = OFF_A + (t % 3) * A_STG;
            const int kcol = t * 32 + cq * 8;
            uint32_t hw[4], lw[4];
#pragma unroll
            for (int j = 0; j < 2; j++) {
                const float* v = (j == 0) ? &fA[0].x : &fA[1].x;
#pragma unroll
                for (int e = 0; e < 2; e++) {
                    const int col = kcol + j * 4 + e * 2;
                    float y0 = celu1((v[2*e]   - mu0) * rs0 * sg1[col]     + sbe1[col]);
                    float y1 = celu1((v[2*e+1] - mu0) * rs0 * sg1[col + 1] + sbe1[col + 1]);
                    split2(y0, y1, hw[2 * j + e], lw[2 * j + e]);
                }
            }
            *reinterpret_cast<uint4*>(smem + abase + d0) =
                make_uint4(hw[0], hw[1], hw[2], hw[3]);
            *reinterpret_cast<uint4*>(smem + abase + OFF_ALO + d0) =
                make_uint4(lw[0], lw[1], lw[2], lw[3]);
#pragma unroll
            for (int j = 0; j < 2; j++) {
                const float* v = (j == 0) ? &fA[2].x : &fA[3].x;
#pragma unroll
                for (int e = 0; e < 2; e++) {
                    const int col = kcol + j * 4 + e * 2;
                    float y0 = celu1((v[2*e]   - mu1) * rs1 * sg1[col]     + sbe1[col]);
                    float y1 = celu1((v[2*e+1] - mu1) * rs1 * sg1[col + 1] + sbe1[col + 1]);
                    split2(y0, y1, hw[2 * j + e], lw[2 * j + e]);
                }
            }
            *reinterpret_cast<uint4*>(smem + abase + d1) =
                make_uint4(hw[0], hw[1], hw[2], hw[3]);
            *reinterpret_cast<uint4*>(smem + abase + OFF_ALO + d1) =
                make_uint4(lw[0], lw[1], lw[2], lw[3]);
        }
        if (t + 1 < NSTAGES) prefetchA(t + 1);
        if (t + 1 < NSTAGES) { CP_WAIT(1); } else { CP_WAIT(0); }
        __syncthreads();
        if (t + 2 < NSTAGES) load_B(t + 2);

        // MMA over buffer t%3 (A ring depth 3 -> no trailing barrier needed)
        const uint32_t sa = sb + OFF_A + (t % 3) * A_STG;
        const uint32_t sB = sb + (t % 3) * B_STG;
#pragma unroll
        for (int ks = 0; ks < 2; ks++) {
            uint32_t ah[4][4], al[4][4];
            const uint32_t arow = warpM * 64 + (lane & 15);
            const uint32_t aq   = ks * 2 + (lane >> 4);
#pragma unroll
            for (int mt = 0; mt < 4; mt++) {
                const uint32_t adr = sa + swz(arow + mt * 16, aq);
                ldmx4(ah[mt][0], ah[mt][1], ah[mt][2], ah[mt][3], adr);
                ldmx4(al[mt][0], al[mt][1], al[mt][2], al[mt][3], adr + OFF_ALO);
            }
            const uint32_t brow0 = warpN * 32 + (lane & 7) + ((lane >> 4) & 1) * 8;
            const uint32_t bq    = ks * 2 + ((lane >> 3) & 1);
#pragma unroll
            for (int pr = 0; pr < 2; pr++) {
                uint32_t bh0, bh1, bh2, bh3, bl0, bl1, bl2, bl3;
                const uint32_t adr = sB + swz(brow0 + pr * 16, bq);
                ldmx4(bh0, bh1, bh2, bh3, adr);
                ldmx4(bl0, bl1, bl2, bl3, adr + OFF_BLO);
#pragma unroll
                for (int mt = 0; mt < 4; mt++) {
                    float* c0 = acc[mt][2 * pr];
                    mma16816(c0[0], c0[1], c0[2], c0[3],
                             ah[mt][0], ah[mt][1], ah[mt][2], ah[mt][3], bh0, bh1);
                    mma16816(c0[0], c0[1], c0[2], c0[3],
                             ah[mt][0], ah[mt][1], ah[mt][2], ah[mt][3], bl0, bl1);
                    mma16816(c0[0], c0[1], c0[2], c0[3],
                             al[mt][0], al[mt][1], al[mt][2], al[mt][3], bh0, bh1);
                    float* c1 = acc[mt][2 * pr + 1];
                    mma16816(c1[0], c1[1], c1[2], c1[3],
                             ah[mt][0], ah[mt][1], ah[mt][2], ah[mt][3], bh2, bh3);
                    mma16816(c1[0], c1[1], c1[2], c1[3],
                             ah[mt][0], ah[mt][1], ah[mt][2], ah[mt][3], bl2, bl3);
                    mma16816(c1[0], c1[1], c1[2], c1[3],
                             al[mt][0], al[mt][1], al[mt][2], al[mt][3], bh2, bh3);
                }
            }
        }
    }

    // ---- epilogue: bias2, LN2 over full rows, CELU -> h2 ----
#pragma unroll
    for (int mt = 0; mt < 4; mt++) {
        const int rloc = warpM * 64 + mt * 16 + (lane >> 2);
        float s0 = 0.f, q0 = 0.f, s1 = 0.f, q1 = 0.f;
#pragma unroll
        for (int nt = 0; nt < 4; nt++) {
            const int col = warpN * 32 + nt * 8 + (lane & 3) * 2;
            const float b0 = sb2[col], b1 = sb2[col + 1];
            float* c = acc[mt][nt];
            const float v00 = c[0] + b0, v01 = c[1] + b1;
            const float v10 = c[2] + b0, v11 = c[3] + b1;
            s0 += v00 + v01; q0 += v00 * v00 + v01 * v01;
            s1 += v10 + v11; q1 += v10 * v10 + v11 * v11;
        }
#pragma unroll
        for (int o = 1; o <= 2; o <<= 1) {
            s0 += __shfl_xor_sync(0xffffffffu, s0, o);
            q0 += __shfl_xor_sync(0xffffffffu, q0, o);
            s1 += __shfl_xor_sync(0xffffffffu, s1, o);
            q1 += __shfl_xor_sync(0xffffffffu, q1, o);
        }
        if ((lane & 3) == 0) {
            sred[warpN][rloc]     = make_float2(s0, q0);
            sred[warpN][rloc + 8] = make_float2(s1, q1);
        }
    }
    __syncthreads();
    if (tid < 128) {
        float s = 0.f, q = 0.f;
#pragma unroll
        for (int w = 0; w < 4; w++) { s += sred[w][tid].x; q += sred[w][tid].y; }
        const float mu = s * (1.f / 128.f);
        smu[tid]   = mu;
        srstd[tid] = rsqrtf(q * (1.f / 128.f) - mu * mu + 1e-5f);
    }
    __syncthreads();
#pragma unroll
    for (int mt = 0; mt < 4; mt++) {
        const int rloc = warpM * 64 + mt * 16 + (lane >> 2);
        const float m0 = smu[rloc],     r0s = srstd[rloc];
        const float m1 = smu[rloc + 8], r1s = srstd[rloc + 8];
        const size_t r0 = rowBase + rloc;
#pragma unroll
        for (int nt = 0; nt < 4; nt++) {
            const int col = warpN * 32 + nt * 8 + (lane & 3) * 2;
            const float b0 = sb2[col], b1 = sb2[col + 1];
            float* c = acc[mt][nt];
            float y00 = (c[0] + b0 - m0) * r0s * sg2[col]     + sbe2[col];
            float y01 = (c[1] + b1 - m0) * r0s * sg2[col + 1] + sbe2[col + 1];
            float y10 = (c[2] + b0 - m1) * r1s * sg2[col]     + sbe2[col];
            float y11 = (c[3] + b1 - m1) * r1s * sg2[col + 1] + sbe2[col + 1];
            *reinterpret_cast<float2*>(h2 + r0 * 128 + col) =
                make_float2(celu1(y00), celu1(y01));
            *reinterpret_cast<float2*>(h2 + (r0 + 8) * 128 + col) =
                make_float2(celu1(y10), celu1(y11));
        }
    }
}

// ---------------------------------------------------------------------------
// Tail: layer3 (128->32)+LN+CELU, layer4 (32->8)+LN+CELU, spectral-norm head.
// ---------------------------------------------------------------------------
__global__ void __launch_bounds__(256)
tail_kernel(const float* __restrict__ h2,
            const float* __restrict__ W3, const float* __restrict__ b3,
            const float* __restrict__ g3, const float* __restrict__ be3,
            const float* __restrict__ W4, const float* __restrict__ b4,
            const float* __restrict__ g4, const float* __restrict__ be4,
            const float* __restrict__ Wh, const float* __restrict__ bh,
            const float* __restrict__ u, float* __restrict__ out)
{
    __shared__ float sW3[32 * 128];
    __shared__ float sW4[8 * 32];
    const int tid = threadIdx.x;
    for (int i = tid; i < 32 * 128; i += 256) sW3[i] = W3[i];
    if (tid < 8 * 32) sW4[tid] = W4[tid];
    __syncthreads();

    const int lane = tid & 31;
    const size_t row = (size_t)blockIdx.x * 8 + (tid >> 5);
    const float* rp = h2 + row * 128;
    const float r0 = rp[lane], r1 = rp[lane + 32], r2 = rp[lane + 64], r3 = rp[lane + 96];

    float h3 = 0.f;
#pragma unroll
    for (int j = 0; j < 32; j++) {
        const float* w = sW3 + j * 128;
        float p = r0 * w[lane] + r1 * w[lane + 32] + r2 * w[lane + 64] + r3 * w[lane + 96];
        p = warp_sum(p);
        if (lane == j) h3 = p + b3[j];
    }
    float mu  = warp_sum(h3) * (1.f / 32.f);
    float d   = h3 - mu;
    float var = warp_sum(d * d) * (1.f / 32.f);
    float y3  = d * rsqrtf(var + 1e-5f) * g3[lane] + be3[lane];
    const float c3 = (y3 > 0.f) ? y3 : expm1f(y3);

    float h4 = 0.f;
#pragma unroll
    for (int j = 0; j < 8; j++) {
        float p = warp_sum(c3 * sW4[j * 32 + lane]);
        if (lane == j) h4 = p + b4[j];
    }
    const bool act = (lane < 8);
    float hv = act ? h4 : 0.f;
    mu  = warp_sum(hv) * 0.125f;
    d   = act ? (h4 - mu) : 0.f;
    var = warp_sum(d * d) * 0.125f;
    float c4 = 0.f;
    if (act) {
        float y4 = d * rsqrtf(var + 1e-5f) * g4[lane] + be4[lane];
        c4 = (y4 > 0.f) ? y4 : expm1f(y4);
    }

    const float wh  = act ? Wh[lane] : 0.f;
    const float nrm = sqrtf(warp_sum(wh * wh));
    const float u0  = u[0];
    const float vden = fabsf(u0) * nrm + 1e-12f;
    const float t    = u0 * nrm * nrm / vden;
    const float u2n  = t / (fabsf(t) + 1e-12f);
    const float sigma = u2n * t;

    float p = warp_sum(c4 * wh / sigma);
    if (lane == 0) out[row] = p + bh[0];
}

// ---------------------------------------------------------------------------
extern "C" void kernel_launch(void* const* d_in, const int* in_sizes, int n_in,
                              void* d_out, int out_size)
{
    const float* x   = (const float*)d_in[0];
    const float* W1  = (const float*)d_in[1];
    const float* b1  = (const float*)d_in[2];
    const float* g1  = (const float*)d_in[3];
    const float* be1 = (const float*)d_in[4];
    const float* W2  = (const float*)d_in[5];
    const float* b2  = (const float*)d_in[6];
    const float* g2  = (const float*)d_in[7];
    const float* be2 = (const float*)d_in[8];
    const float* W3  = (const float*)d_in[9];
    const float* b3  = (const float*)d_in[10];
    const float* g3  = (const float*)d_in[11];
    const float* be3 = (const float*)d_in[12];
    const float* W4  = (const float*)d_in[13];
    const float* b4  = (const float*)d_in[14];
    const float* g4  = (const float*)d_in[15];
    const float* be4 = (const float*)d_in[16];
    const float* Wh  = (const float*)d_in[17];
    const float* bh  = (const float*)d_in[18];
    const float* u   = (const float*)d_in[19];
    float* out = (float*)d_out;

    const int M = in_sizes[0] / 512;   // 131072

    __nv_bfloat16 *xhi, *xlo, *w1hi, *w1lo, *w2hi, *w2lo;
    float *h1raw, *h2;
    float2* part;
    cudaGetSymbolAddress((void**)&xhi,   g_xhi);
    cudaGetSymbolAddress((void**)&xlo,   g_xlo);
    cudaGetSymbolAddress((void**)&h1raw, g_h1raw);
    cudaGetSymbolAddress((void**)&h2,    g_h2);
    cudaGetSymbolAddress((void**)&part,  g_part);
    cudaGetSymbolAddress((void**)&w1hi,  g_w1hi);
    cudaGetSymbolAddress((void**)&w1lo,  g_w1lo);
    cudaGetSymbolAddress((void**)&w2hi,  g_w2hi);
    cudaGetSymbolAddress((void**)&w2lo,  g_w2lo);

    constexpr int SMEM1 = 3 * 4 * 128 * 64;    // 98304 (GEMM1 3-stage ring)
    cudaFuncSetAttribute(hgemm3_kernel,
                         cudaFuncAttributeMaxDynamicSharedMemorySize, SMEM1);
    cudaFuncSetAttribute(gemm2_fused_kernel,
                         cudaFuncAttributeMaxDynamicSharedMemorySize, SMEM_DYN);

    // Splits: x (large) and weights (small)
    const int n4x = M * 512 / 4;
    split_kernel<<<(n4x + 255) / 256, 256>>>(x, xhi, xlo, n4x);
    split_kernel<<<(512 * 512 / 4 + 255) / 256, 256>>>(W1, w1hi, w1lo, 512 * 512 / 4);
    split_kernel<<<(128 * 512 / 4 + 255) / 256, 256>>>(W2, w2hi, w2lo, 128 * 512 / 4);

    // Layer 1: GEMM (cp.async bf16 A+B) -> h1raw fp32 + LN partials
    hgemm3_kernel<<<dim3(4, M / 128), 256, SMEM1>>>(
        xhi, xlo, w1hi, w1lo, b1, h1raw, part, 512, M);

    // Layer 2: fused LN1+CELU+split -> GEMM -> LN2+CELU -> h2
    gemm2_fused_kernel<<<M / 128, 256, SMEM_DYN>>>(
        h1raw, part, g1, be1, w2hi, w2lo, b2, g2, be2, h2, M);

    // Layers 3+4 + spectral-norm head
    tail_kernel<<<M / 8, 256>>>(h2, W3, b3, g3, be3, W4, b4, g4, be4, Wh, bh, u, out);
}

// round 10
// speedup vs baseline: 1.0146x; 1.0146x over previous
#include <cuda_runtime.h>
#include <cuda_bf16.h>
#include <cstdint>

// ---------------------------------------------------------------------------
// B=131072, chain 512 ->(W1)512 ->(W2)128 ->(W3)32 ->(W4)8 ->(Wh)1
// GEMM1: A = raw fp32 x via cp.async staging -> smem-local split -> bf16 tiles
//        (split_x kernel ELIMINATED), B = W1 bf16 hi/lo 3-ring, HMMA bf16x3,
//        1 barrier/stage, 2 CTAs/SM, LN partials in epilogue.
// GEMM2: R8-proven fused LN1+CELU+split -> HMMA -> LN2+CELU.
// ---------------------------------------------------------------------------

#define BATCH 131072

__device__ __align__(256) float         g_h1raw[BATCH * 512];
__device__ __align__(256) float         g_h2   [BATCH * 128];
__device__ __align__(256) float2        g_part [4 * BATCH];
__device__ __align__(256) __nv_bfloat16 g_w1hi [512 * 512];
__device__ __align__(256) __nv_bfloat16 g_w1lo [512 * 512];
__device__ __align__(256) __nv_bfloat16 g_w2hi [128 * 512];
__device__ __align__(256) __nv_bfloat16 g_w2lo [128 * 512];

// ------------------------------ helpers ------------------------------------
__device__ __forceinline__ uint32_t smem_u32(const void* p) {
    uint32_t a;
    asm("{ .reg .u64 t; cvta.to.shared.u64 t, %1; cvt.u32.u64 %0, t; }"
        : "=r"(a) : "l"(p));
    return a;
}
__device__ __forceinline__ void cp_async16(uint32_t dst, const void* src) {
    asm volatile("cp.async.cg.shared.global [%0], [%1], 16;"
                 :: "r"(dst), "l"(src) : "memory");
}
#define CP_COMMIT() asm volatile("cp.async.commit_group;" ::: "memory")
#define CP_WAIT(n)  asm volatile("cp.async.wait_group %0;" :: "n"(n) : "memory")

__device__ __forceinline__ void ldmx4(uint32_t& r0, uint32_t& r1,
                                      uint32_t& r2, uint32_t& r3, uint32_t a) {
    asm volatile("ldmatrix.sync.aligned.m8n8.x4.shared.b16 {%0,%1,%2,%3}, [%4];"
                 : "=r"(r0), "=r"(r1), "=r"(r2), "=r"(r3) : "r"(a));
}
__device__ __forceinline__ void mma16816(float& c0, float& c1, float& c2, float& c3,
                                         uint32_t a0, uint32_t a1, uint32_t a2, uint32_t a3,
                                         uint32_t b0, uint32_t b1) {
    asm volatile("mma.sync.aligned.m16n8k16.row.col.f32.bf16.bf16.f32 "
                 "{%0,%1,%2,%3}, {%4,%5,%6,%7}, {%8,%9}, {%0,%1,%2,%3};"
                 : "+f"(c0), "+f"(c1), "+f"(c2), "+f"(c3)
                 : "r"(a0), "r"(a1), "r"(a2), "r"(a3), "r"(b0), "r"(b1));
}
__device__ __forceinline__ float warp_sum(float v) {
#pragma unroll
    for (int o = 16; o; o >>= 1) v += __shfl_xor_sync(0xffffffffu, v, o);
    return v;
}
__device__ __forceinline__ uint32_t swz(uint32_t row, uint32_t q) {
    return row * 64 + (q ^ ((row & 6u) >> 1)) * 16;
}
__device__ __forceinline__ uint32_t swzf(uint32_t row, uint32_t q) {
    return row * 128 + (q ^ (row & 7u)) * 16;
}
__device__ __forceinline__ float celu1(float y) {
    return (y > 0.f) ? y : expm1f(y);
}
__device__ __forceinline__ uint32_t pack_bf16(float a0, float a1) {
    __nv_bfloat162 t; t.x = __float2bfloat16(a0); t.y = __float2bfloat16(a1);
    return *reinterpret_cast<uint32_t*>(&t);
}
__device__ __forceinline__ void split2(float a0, float a1, uint32_t& hp, uint32_t& lp) {
    __nv_bfloat16 h0 = __float2bfloat16(a0), h1 = __float2bfloat16(a1);
    hp = (uint32_t)__bfloat16_as_ushort(h1) << 16 | (uint32_t)__bfloat16_as_ushort(h0);
    lp = pack_bf16(a0 - __bfloat162float(h0), a1 - __bfloat162float(h1));
}

// GEMM1 smem layout (112K dynamic, no static):
//  [0, 49152)        B ring: 3 x (Bhi 8192 + Blo 8192)
//  [49152, 81920)    A fp32 staging: 2 x 16384
//  [81920, 114688)   A bf16 tiles:   2 x (Ahi 8192 + Alo 8192)
//  sred reuses offset 0 after the mainloop.
#define B_STG     16384
#define OFF_BLO   8192
#define OFF_STAGE 49152
#define STAGE_SZ  16384
#define OFF_ABF   81920
#define A_STG     16384
#define OFF_ALO   8192
#define SMEM_G1   114688

// GEMM2 smem layout (R8): B ring 3 x 16K at 0, A bf16 ring 3 x 16K at 49152.
#define OFF_A2    49152
#define SMEM_G2   98304

// ---------------------------------------------------------------------------
__global__ void __launch_bounds__(256)
split_kernel(const float* __restrict__ src, __nv_bfloat16* __restrict__ hi,
             __nv_bfloat16* __restrict__ lo, int n4)
{
    int i = blockIdx.x * blockDim.x + threadIdx.x;
    if (i >= n4) return;
    float4 v = reinterpret_cast<const float4*>(src)[i];
    uint32_t h0, l0, h1, l1;
    split2(v.x, v.y, h0, l0);
    split2(v.z, v.w, h1, l1);
    reinterpret_cast<uint32_t*>(hi)[2 * i]     = h0;
    reinterpret_cast<uint32_t*>(hi)[2 * i + 1] = h1;
    reinterpret_cast<uint32_t*>(lo)[2 * i]     = l0;
    reinterpret_cast<uint32_t*>(lo)[2 * i + 1] = l1;
}

// ---------------------------------------------------------------------------
// Shared MMA inner step: A tiles at sa (hi, lo at +OFF_ALO), B at sbB.
// ---------------------------------------------------------------------------
__device__ __forceinline__ void mma_stage(uint32_t sa, uint32_t sbB,
                                          int lane, int warpM, int warpN,
                                          float acc[4][4][4])
{
#pragma unroll
    for (int ks = 0; ks < 2; ks++) {
        uint32_t ah[4][4], al[4][4];
        const uint32_t arow = warpM * 64 + (lane & 15);
        const uint32_t aq   = ks * 2 + (lane >> 4);
#pragma unroll
        for (int mt = 0; mt < 4; mt++) {
            const uint32_t adr = sa + swz(arow + mt * 16, aq);
            ldmx4(ah[mt][0], ah[mt][1], ah[mt][2], ah[mt][3], adr);
            ldmx4(al[mt][0], al[mt][1], al[mt][2], al[mt][3], adr + OFF_ALO);
        }
        const uint32_t brow0 = warpN * 32 + (lane & 7) + ((lane >> 4) & 1) * 8;
        const uint32_t bq    = ks * 2 + ((lane >> 3) & 1);
#pragma unroll
        for (int pr = 0; pr < 2; pr++) {
            uint32_t bh0, bh1, bh2, bh3, bl0, bl1, bl2, bl3;
            const uint32_t adr = sbB + swz(brow0 + pr * 16, bq);
            ldmx4(bh0, bh1, bh2, bh3, adr);
            ldmx4(bl0, bl1, bl2, bl3, adr + OFF_BLO);
#pragma unroll
            for (int mt = 0; mt < 4; mt++) {
                float* c0 = acc[mt][2 * pr];
                mma16816(c0[0], c0[1], c0[2], c0[3],
                         ah[mt][0], ah[mt][1], ah[mt][2], ah[mt][3], bh0, bh1);
                mma16816(c0[0], c0[1], c0[2], c0[3],
                         ah[mt][0], ah[mt][1], ah[mt][2], ah[mt][3], bl0, bl1);
                mma16816(c0[0], c0[1], c0[2], c0[3],
                         al[mt][0], al[mt][1], al[mt][2], al[mt][3], bh0, bh1);
                float* c1 = acc[mt][2 * pr + 1];
                mma16816(c1[0], c1[1], c1[2], c1[3],
                         ah[mt][0], ah[mt][1], ah[mt][2], ah[mt][3], bh2, bh3);
                mma16816(c1[0], c1[1], c1[2], c1[3],
                         ah[mt][0], ah[mt][1], ah[mt][2], ah[mt][3], bl2, bl3);
                mma16816(c1[0], c1[1], c1[2], c1[3],
                         al[mt][0], al[mt][1], al[mt][2], al[mt][3], bh2, bh3);
            }
        }
    }
}

// ---------------------------------------------------------------------------
// GEMM1 fused-split: h1raw = x @ W1^T + b1 (fp32) + per-colblock LN partials.
// A path: cp.async fp32 x -> staging(2) -> per-thread smem convert -> bf16(2).
// Single barrier per stage (safety argument in header comment).
// ---------------------------------------------------------------------------
__global__ void __launch_bounds__(256, 2)
gemm1_fused_kernel(const float* __restrict__ X,
                   const __nv_bfloat16* __restrict__ Bhi, const __nv_bfloat16* __restrict__ Blo,
                   const float* __restrict__ bias, float* __restrict__ C,
                   float2* __restrict__ gpart, int Mtot)
{
    constexpr int K = 512;
    constexpr int NSTAGES = K / 32;
    extern __shared__ char smem[];
    const uint32_t sb = smem_u32(smem);

    const int tid   = threadIdx.x;
    const int lane  = tid & 31;
    const int wid   = tid >> 5;
    const int warpM = wid >> 2;
    const int warpN = wid & 3;
    const size_t rowBase = (size_t)blockIdx.y * 128;
    const int    colBase = blockIdx.x * 128;

    const int c0r = tid >> 2,  cq = tid & 3;
    const int c1r = 64 + c0r;
    const uint32_t d0 = swz(c0r, cq);
    const uint32_t d1 = swz(c1r, cq);
    // fp32 staging chunk offsets (own data)
    const uint32_t f00 = swzf(c0r, 2 * cq),     f01 = swzf(c0r, 2 * cq + 1);
    const uint32_t f10 = swzf(c1r, 2 * cq),     f11 = swzf(c1r, 2 * cq + 1);
    const float* x0p = X + (rowBase + c0r) * K + cq * 8;
    const float* x1p = X + (rowBase + c1r) * K + cq * 8;

    float acc[4][4][4];
#pragma unroll
    for (int i = 0; i < 4; i++)
#pragma unroll
        for (int j = 0; j < 4; j++)
#pragma unroll
            for (int q = 0; q < 4; q++) acc[i][j][q] = 0.f;

    auto load_stage = [&](int t) {
        const int k0 = t * 32;
        // A fp32 -> staging slot t&1
        const uint32_t sA = sb + OFF_STAGE + (t & 1) * STAGE_SZ;
        cp_async16(sA + f00, x0p + k0);
        cp_async16(sA + f01, x0p + k0 + 4);
        cp_async16(sA + f10, x1p + k0);
        cp_async16(sA + f11, x1p + k0 + 4);
        // B bf16 hi/lo -> ring slot t%3
        const uint32_t sB = sb + (t % 3) * B_STG;
        const size_t g0 = (size_t)(colBase + c0r) * K + k0 + cq * 8;
        const size_t g1 = (size_t)(colBase + c1r) * K + k0 + cq * 8;
        cp_async16(sB + d0,           Bhi + g0);
        cp_async16(sB + d1,           Bhi + g1);
        cp_async16(sB + OFF_BLO + d0, Blo + g0);
        cp_async16(sB + OFF_BLO + d1, Blo + g1);
        CP_COMMIT();
    };

    load_stage(0);
    load_stage(1);

#pragma unroll 1
    for (int t = 0; t < NSTAGES; t++) {
        if (t + 1 < NSTAGES) { CP_WAIT(1); } else { CP_WAIT(0); }
        // convert A(t): read OWN staged fp32 chunks, split, STS bf16 tiles.
        // Safe pre-barrier: peers are at worst in mma(t-1) on the other A buf.
        {
            const char* stg = smem + OFF_STAGE + (t & 1) * STAGE_SZ;
            const uint32_t abase = OFF_ABF + (t & 1) * A_STG;
            const float4 v0 = *reinterpret_cast<const float4*>(stg + f00);
            const float4 v1 = *reinterpret_cast<const float4*>(stg + f01);
            const float4 v2 = *reinterpret_cast<const float4*>(stg + f10);
            const float4 v3 = *reinterpret_cast<const float4*>(stg + f11);
            uint32_t hw[4], lw[4];
            split2(v0.x, v0.y, hw[0], lw[0]);
            split2(v0.z, v0.w, hw[1], lw[1]);
            split2(v1.x, v1.y, hw[2], lw[2]);
            split2(v1.z, v1.w, hw[3], lw[3]);
            *reinterpret_cast<uint4*>(smem + abase + d0) =
                make_uint4(hw[0], hw[1], hw[2], hw[3]);
            *reinterpret_cast<uint4*>(smem + abase + OFF_ALO + d0) =
                make_uint4(lw[0], lw[1], lw[2], lw[3]);
            split2(v2.x, v2.y, hw[0], lw[0]);
            split2(v2.z, v2.w, hw[1], lw[1]);
            split2(v3.x, v3.y, hw[2], lw[2]);
            split2(v3.z, v3.w, hw[3], lw[3]);
            *reinterpret_cast<uint4*>(smem + abase + d1) =
                make_uint4(hw[0], hw[1], hw[2], hw[3]);
            *reinterpret_cast<uint4*>(smem + abase + OFF_ALO + d1) =
                make_uint4(lw[0], lw[1], lw[2], lw[3]);
        }
        __syncthreads();
        if (t + 2 < NSTAGES) load_stage(t + 2);

        mma_stage(sb + OFF_ABF + (t & 1) * A_STG, sb + (t % 3) * B_STG,
                  lane, warpM, warpN, acc);
    }
    __syncthreads();   // before reusing smem offset 0 as sred

    // ---- epilogue: + bias, fp32 out, per-row partial (sum, ssq) ----
    float2* sred = reinterpret_cast<float2*>(smem);   // [4][128], reused ring
#pragma unroll
    for (int mt = 0; mt < 4; mt++) {
        const int rloc = warpM * 64 + mt * 16 + (lane >> 2);
        const size_t r0 = rowBase + rloc;
        float s0 = 0.f, q0 = 0.f, s1 = 0.f, q1 = 0.f;
#pragma unroll
        for (int nt = 0; nt < 4; nt++) {
            const int col = colBase + warpN * 32 + nt * 8 + (lane & 3) * 2;
            const float b0 = bias[col], b1 = bias[col + 1];
            float* c = acc[mt][nt];
            const float v00 = c[0] + b0, v01 = c[1] + b1;
            const float v10 = c[2] + b0, v11 = c[3] + b1;
            *reinterpret_cast<float2*>(C + r0 * 512 + col)       = make_float2(v00, v01);
            *reinterpret_cast<float2*>(C + (r0 + 8) * 512 + col) = make_float2(v10, v11);
            s0 += v00 + v01; q0 += v00 * v00 + v01 * v01;
            s1 += v10 + v11; q1 += v10 * v10 + v11 * v11;
        }
#pragma unroll
        for (int o = 1; o <= 2; o <<= 1) {
            s0 += __shfl_xor_sync(0xffffffffu, s0, o);
            q0 += __shfl_xor_sync(0xffffffffu, q0, o);
            s1 += __shfl_xor_sync(0xffffffffu, s1, o);
            q1 += __shfl_xor_sync(0xffffffffu, q1, o);
        }
        if ((lane & 3) == 0) {
            sred[warpN * 128 + rloc]     = make_float2(s0, q0);
            sred[warpN * 128 + rloc + 8] = make_float2(s1, q1);
        }
    }
    __syncthreads();
    if (tid < 128) {
        float s = 0.f, q = 0.f;
#pragma unroll
        for (int w = 0; w < 4; w++) { s += sred[w * 128 + tid].x; q += sred[w * 128 + tid].y; }
        gpart[(size_t)blockIdx.x * Mtot + rowBase + tid] = make_float2(s, q);
    }
}

// ---------------------------------------------------------------------------
// GEMM2 fused (R8-proven): a1 = celu(LN1(h1raw)) in regs -> HMMA bf16x3 ->
// LN2+CELU epilogue -> h2.
// ---------------------------------------------------------------------------
__global__ void __launch_bounds__(256, 2)
gemm2_fused_kernel(const float* __restrict__ h1raw, const float2* __restrict__ gpart,
                   const float* __restrict__ g1, const float* __restrict__ be1,
                   const __nv_bfloat16* __restrict__ Bhi, const __nv_bfloat16* __restrict__ Blo,
                   const float* __restrict__ b2, const float* __restrict__ g2,
                   const float* __restrict__ be2,
                   float* __restrict__ h2, int Mtot)
{
    constexpr int K = 512;
    constexpr int NSTAGES = K / 32;
    extern __shared__ char smem[];
    __shared__ float  smu[128], srstd[128];
    __shared__ float  sg1[512], sbe1[512];
    __shared__ float  sg2[128], sbe2[128], sb2[128];
    __shared__ float2 sred[4][128];
    const uint32_t sb = smem_u32(smem);

    const int tid   = threadIdx.x;
    const int lane  = tid & 31;
    const int wid   = tid >> 5;
    const int warpM = wid >> 2;
    const int warpN = wid & 3;
    const size_t rowBase = (size_t)blockIdx.x * 128;

    if (tid < 128) {
        float s = 0.f, q = 0.f;
#pragma unroll
        for (int b = 0; b < 4; b++) {
            float2 p = gpart[(size_t)b * Mtot + rowBase + tid];
            s += p.x; q += p.y;
        }
        const float mu = s * (1.f / 512.f);
        smu[tid]   = mu;
        srstd[tid] = rsqrtf(q * (1.f / 512.f) - mu * mu + 1e-5f);
        sg2[tid] = g2[tid]; sbe2[tid] = be2[tid]; sb2[tid] = b2[tid];
    }
#pragma unroll
    for (int i = tid; i < 512; i += 256) { sg1[i] = g1[i]; sbe1[i] = be1[i]; }
    __syncthreads();

    const int c0r = tid >> 2,  cq = tid & 3;
    const int c1r = 64 + c0r;
    const uint32_t d0 = swz(c0r, cq);
    const uint32_t d1 = swz(c1r, cq);

    const float* a0p = h1raw + (rowBase + c0r) * K + cq * 8;
    const float* a1p = h1raw + (rowBase + c1r) * K + cq * 8;
    const float mu0 = smu[c0r], rs0 = srstd[c0r];
    const float mu1 = smu[c1r], rs1 = srstd[c1r];

    float acc[4][4][4];
#pragma unroll
    for (int i = 0; i < 4; i++)
#pragma unroll
        for (int j = 0; j < 4; j++)
#pragma unroll
            for (int q = 0; q < 4; q++) acc[i][j][q] = 0.f;

    float4 fA[4];
    auto prefetchA = [&](int t) {
        fA[0] = *reinterpret_cast<const float4*>(a0p + t * 32);
        fA[1] = *reinterpret_cast<const float4*>(a0p + t * 32 + 4);
        fA[2] = *reinterpret_cast<const float4*>(a1p + t * 32);
        fA[3] = *reinterpret_cast<const float4*>(a1p + t * 32 + 4);
    };
    auto load_B = [&](int t) {
        const int k0 = t * 32;
        const uint32_t s = sb + (t % 3) * B_STG;
        const size_t g0 = (size_t)c0r * K + k0 + cq * 8;
        const size_t g1 = (size_t)c1r * K + k0 + cq * 8;
        cp_async16(s + d0,           Bhi + g0);
        cp_async16(s + d1,           Bhi + g1);
        cp_async16(s + OFF_BLO + d0, Blo + g0);
        cp_async16(s + OFF_BLO + d1, Blo + g1);
        CP_COMMIT();
    };

    prefetchA(0);
    load_B(0);
    load_B(1);

#pragma unroll 1
    for (int t = 0; t < NSTAGES; t++) {
        // convert A(t): LN1 + CELU + split -> A ring buffer t%3
        {
            const uint32_t abase = OFF_A2 + (t % 3) * A_STG;
            const int kcol = t * 32 + cq * 8;
            uint32_t hw[4], lw[4];
#pragma unroll
            for (int j = 0; j < 2; j++) {
                const float* v = (j == 0) ? &fA[0].x : &fA[1].x;
#pragma unroll
                for (int e = 0; e < 2; e++) {
                    const int col = kcol + j * 4 + e * 2;
                    float y0 = celu1((v[2*e]   - mu0) * rs0 * sg1[col]     + sbe1[col]);
                    float y1 = celu1((v[2*e+1] - mu0) * rs0 * sg1[col + 1] + sbe1[col + 1]);
                    split2(y0, y1, hw[2 * j + e], lw[2 * j + e]);
                }
            }
            *reinterpret_cast<uint4*>(smem + abase + d0) =
                make_uint4(hw[0], hw[1], hw[2], hw[3]);
            *reinterpret_cast<uint4*>(smem + abase + OFF_ALO + d0) =
                make_uint4(lw[0], lw[1], lw[2], lw[3]);
#pragma unroll
            for (int j = 0; j < 2; j++) {
                const float* v = (j == 0) ? &fA[2].x : &fA[3].x;
#pragma unroll
                for (int e = 0; e < 2; e++) {
                    const int col = kcol + j * 4 + e * 2;
                    float y0 = celu1((v[2*e]   - mu1) * rs1 * sg1[col]     + sbe1[col]);
                    float y1 = celu1((v[2*e+1] - mu1) * rs1 * sg1[col + 1] + sbe1[col + 1]);
                    split2(y0, y1, hw[2 * j + e], lw[2 * j + e]);
                }
            }
            *reinterpret_cast<uint4*>(smem + abase + d1) =
                make_uint4(hw[0], hw[1], hw[2], hw[3]);
            *reinterpret_cast<uint4*>(smem + abase + OFF_ALO + d1) =
                make_uint4(lw[0], lw[1], lw[2], lw[3]);
        }
        if (t + 1 < NSTAGES) prefetchA(t + 1);
        if (t + 1 < NSTAGES) { CP_WAIT(1); } else { CP_WAIT(0); }
        __syncthreads();
        if (t + 2 < NSTAGES) load_B(t + 2);

        mma_stage(sb + OFF_A2 + (t % 3) * A_STG, sb + (t % 3) * B_STG,
                  lane, warpM, warpN, acc);
    }

    // ---- epilogue: bias2, LN2 over full rows, CELU -> h2 ----
#pragma unroll
    for (int mt = 0; mt < 4; mt++) {
        const int rloc = warpM * 64 + mt * 16 + (lane >> 2);
        float s0 = 0.f, q0 = 0.f, s1 = 0.f, q1 = 0.f;
#pragma unroll
        for (int nt = 0; nt < 4; nt++) {
            const int col = warpN * 32 + nt * 8 + (lane & 3) * 2;
            const float b0 = sb2[col], b1 = sb2[col + 1];
            float* c = acc[mt][nt];
            const float v00 = c[0] + b0, v01 = c[1] + b1;
            const float v10 = c[2] + b0, v11 = c[3] + b1;
            s0 += v00 + v01; q0 += v00 * v00 + v01 * v01;
            s1 += v10 + v11; q1 += v10 * v10 + v11 * v11;
        }
#pragma unroll
        for (int o = 1; o <= 2; o <<= 1) {
            s0 += __shfl_xor_sync(0xffffffffu, s0, o);
            q0 += __shfl_xor_sync(0xffffffffu, q0, o);
            s1 += __shfl_xor_sync(0xffffffffu, s1, o);
            q1 += __shfl_xor_sync(0xffffffffu, q1, o);
        }
        if ((lane & 3) == 0) {
            sred[warpN][rloc]     = make_float2(s0, q0);
            sred[warpN][rloc + 8] = make_float2(s1, q1);
        }
    }
    __syncthreads();
    if (tid < 128) {
        float s = 0.f, q = 0.f;
#pragma unroll
        for (int w = 0; w < 4; w++) { s += sred[w][tid].x; q += sred[w][tid].y; }
        const float mu = s * (1.f / 128.f);
        smu[tid]   = mu;
        srstd[tid] = rsqrtf(q * (1.f / 128.f) - mu * mu + 1e-5f);
    }
    __syncthreads();
#pragma unroll
    for (int mt = 0; mt < 4; mt++) {
        const int rloc = warpM * 64 + mt * 16 + (lane >> 2);
        const float m0 = smu[rloc],     r0s = srstd[rloc];
        const float m1 = smu[rloc + 8], r1s = srstd[rloc + 8];
        const size_t r0 = rowBase + rloc;
#pragma unroll
        for (int nt = 0; nt < 4; nt++) {
            const int col = warpN * 32 + nt * 8 + (lane & 3) * 2;
            const float b0 = sb2[col], b1 = sb2[col + 1];
            float* c = acc[mt][nt];
            float y00 = (c[0] + b0 - m0) * r0s * sg2[col]     + sbe2[col];
            float y01 = (c[1] + b1 - m0) * r0s * sg2[col + 1] + sbe2[col + 1];
            float y10 = (c[2] + b0 - m1) * r1s * sg2[col]     + sbe2[col];
            float y11 = (c[3] + b1 - m1) * r1s * sg2[col + 1] + sbe2[col + 1];
            *reinterpret_cast<float2*>(h2 + r0 * 128 + col) =
                make_float2(celu1(y00), celu1(y01));
            *reinterpret_cast<float2*>(h2 + (r0 + 8) * 128 + col) =
                make_float2(celu1(y10), celu1(y11));
        }
    }
}

// ---------------------------------------------------------------------------
// Tail: layer3 (128->32)+LN+CELU, layer4 (32->8)+LN+CELU, spectral-norm head.
// ---------------------------------------------------------------------------
__global__ void __launch_bounds__(256)
tail_kernel(const float* __restrict__ h2,
            const float* __restrict__ W3, const float* __restrict__ b3,
            const float* __restrict__ g3, const float* __restrict__ be3,
            const float* __restrict__ W4, const float* __restrict__ b4,
            const float* __restrict__ g4, const float* __restrict__ be4,
            const float* __restrict__ Wh, const float* __restrict__ bh,
            const float* __restrict__ u, float* __restrict__ out)
{
    __shared__ float sW3[32 * 128];
    __shared__ float sW4[8 * 32];
    const int tid = threadIdx.x;
    for (int i = tid; i < 32 * 128; i += 256) sW3[i] = W3[i];
    if (tid < 8 * 32) sW4[tid] = W4[tid];
    __syncthreads();

    const int lane = tid & 31;
    const size_t row = (size_t)blockIdx.x * 8 + (tid >> 5);
    const float* rp = h2 + row * 128;
    const float r0 = rp[lane], r1 = rp[lane + 32], r2 = rp[lane + 64], r3 = rp[lane + 96];

    float h3 = 0.f;
#pragma unroll
    for (int j = 0; j < 32; j++) {
        const float* w = sW3 + j * 128;
        float p = r0 * w[lane] + r1 * w[lane + 32] + r2 * w[lane + 64] + r3 * w[lane + 96];
        p = warp_sum(p);
        if (lane == j) h3 = p + b3[j];
    }
    float mu  = warp_sum(h3) * (1.f / 32.f);
    float d   = h3 - mu;
    float var = warp_sum(d * d) * (1.f / 32.f);
    float y3  = d * rsqrtf(var + 1e-5f) * g3[lane] + be3[lane];
    const float c3 = (y3 > 0.f) ? y3 : expm1f(y3);

    float h4 = 0.f;
#pragma unroll
    for (int j = 0; j < 8; j++) {
        float p = warp_sum(c3 * sW4[j * 32 + lane]);
        if (lane == j) h4 = p + b4[j];
    }
    const bool act = (lane < 8);
    float hv = act ? h4 : 0.f;
    mu  = warp_sum(hv) * 0.125f;
    d   = act ? (h4 - mu) : 0.f;
    var = warp_sum(d * d) * 0.125f;
    float c4 = 0.f;
    if (act) {
        float y4 = d * rsqrtf(var + 1e-5f) * g4[lane] + be4[lane];
        c4 = (y4 > 0.f) ? y4 : expm1f(y4);
    }

    const float wh  = act ? Wh[lane] : 0.f;
    const float nrm = sqrtf(warp_sum(wh * wh));
    const float u0  = u[0];
    const float vden = fabsf(u0) * nrm + 1e-12f;
    const float t    = u0 * nrm * nrm / vden;
    const float u2n  = t / (fabsf(t) + 1e-12f);
    const float sigma = u2n * t;

    float p = warp_sum(c4 * wh / sigma);
    if (lane == 0) out[row] = p + bh[0];
}

// ---------------------------------------------------------------------------
extern "C" void kernel_launch(void* const* d_in, const int* in_sizes, int n_in,
                              void* d_out, int out_size)
{
    const float* x   = (const float*)d_in[0];
    const float* W1  = (const float*)d_in[1];
    const float* b1  = (const float*)d_in[2];
    const float* g1  = (const float*)d_in[3];
    const float* be1 = (const float*)d_in[4];
    const float* W2  = (const float*)d_in[5];
    const float* b2  = (const float*)d_in[6];
    const float* g2  = (const float*)d_in[7];
    const float* be2 = (const float*)d_in[8];
    const float* W3  = (const float*)d_in[9];
    const float* b3  = (const float*)d_in[10];
    const float* g3  = (const float*)d_in[11];
    const float* be3 = (const float*)d_in[12];
    const float* W4  = (const float*)d_in[13];
    const float* b4  = (const float*)d_in[14];
    const float* g4  = (const float*)d_in[15];
    const float* be4 = (const float*)d_in[16];
    const float* Wh  = (const float*)d_in[17];
    const float* bh  = (const float*)d_in[18];
    const float* u   = (const float*)d_in[19];
    float* out = (float*)d_out;

    const int M = in_sizes[0] / 512;   // 131072

    __nv_bfloat16 *w1hi, *w1lo, *w2hi, *w2lo;
    float *h1raw, *h2;
    float2* part;
    cudaGetSymbolAddress((void**)&h1raw, g_h1raw);
    cudaGetSymbolAddress((void**)&h2,    g_h2);
    cudaGetSymbolAddress((void**)&part,  g_part);
    cudaGetSymbolAddress((void**)&w1hi,  g_w1hi);
    cudaGetSymbolAddress((void**)&w1lo,  g_w1lo);
    cudaGetSymbolAddress((void**)&w2hi,  g_w2hi);
    cudaGetSymbolAddress((void**)&w2lo,  g_w2lo);

    cudaFuncSetAttribute(gemm1_fused_kernel,
                         cudaFuncAttributeMaxDynamicSharedMemorySize, SMEM_G1);
    cudaFuncSetAttribute(gemm2_fused_kernel,
                         cudaFuncAttributeMaxDynamicSharedMemorySize, SMEM_G2);

    // Split weights to bf16 hi/lo (small, one-time per launch)
    split_kernel<<<(512 * 512 / 4 + 255) / 256, 256>>>(W1, w1hi, w1lo, 512 * 512 / 4);
    split_kernel<<<(128 * 512 / 4 + 255) / 256, 256>>>(W2, w2hi, w2lo, 128 * 512 / 4);

    // Layer 1: fused x-split GEMM -> h1raw fp32 + LN partials (no split_x pass)
    gemm1_fused_kernel<<<dim3(4, M / 128), 256, SMEM_G1>>>(
        x, w1hi, w1lo, b1, h1raw, part, M);

    // Layer 2: fused LN1+CELU+split -> GEMM -> LN2+CELU -> h2
    gemm2_fused_kernel<<<M / 128, 256, SMEM_G2>>>(
        h1raw, part, g1, be1, w2hi, w2lo, b2, g2, be2, h2, M);

    // Layers 3+4 + spectral-norm head
    tail_kernel<<<M / 8, 256>>>(h2, W3, b3, g3, be3, W4, b4, g4, be4, Wh, bh, u, out);
}

// round 11
// speedup vs baseline: 1.2497x; 1.2316x over previous
#include <cuda_runtime.h>
#include <cuda_fp16.h>
#include <cstdint>

// ---------------------------------------------------------------------------
// B=131072, chain 512 ->(W1)512 ->(W2)128 ->(W3)32 ->(W4)8 ->(Wh)1
// fp16 asymmetric-split HMMA (2 passes): W = Whi + Wlo (fp16 x2, exact to
// ~2^-24), activations single fp16 (2^-12 rel). D = a*Whi + a*Wlo.
// GEMM1: A = raw fp32 x via cp.async staging -> smem convert -> fp16 tile.
// GEMM2: A = h1raw, LN1+CELU in regs -> fp16 tile; LN2+CELU epilogue.
// ---------------------------------------------------------------------------

#define BATCH 131072

__device__ __align__(256) float  g_h1raw[BATCH * 512];
__device__ __align__(256) float  g_h2   [BATCH * 128];
__device__ __align__(256) float2 g_part [4 * BATCH];
__device__ __align__(256) __half g_w1hi [512 * 512];
__device__ __align__(256) __half g_w1lo [512 * 512];
__device__ __align__(256) __half g_w2hi [128 * 512];
__device__ __align__(256) __half g_w2lo [128 * 512];

// ------------------------------ helpers ------------------------------------
__device__ __forceinline__ uint32_t smem_u32(const void* p) {
    uint32_t a;
    asm("{ .reg .u64 t; cvta.to.shared.u64 t, %1; cvt.u32.u64 %0, t; }"
        : "=r"(a) : "l"(p));
    return a;
}
__device__ __forceinline__ void cp_async16(uint32_t dst, const void* src) {
    asm volatile("cp.async.cg.shared.global [%0], [%1], 16;"
                 :: "r"(dst), "l"(src) : "memory");
}
#define CP_COMMIT() asm volatile("cp.async.commit_group;" ::: "memory")
#define CP_WAIT(n)  asm volatile("cp.async.wait_group %0;" :: "n"(n) : "memory")

__device__ __forceinline__ void ldmx4(uint32_t& r0, uint32_t& r1,
                                      uint32_t& r2, uint32_t& r3, uint32_t a) {
    asm volatile("ldmatrix.sync.aligned.m8n8.x4.shared.b16 {%0,%1,%2,%3}, [%4];"
                 : "=r"(r0), "=r"(r1), "=r"(r2), "=r"(r3) : "r"(a));
}
__device__ __forceinline__ void mma16816(float& c0, float& c1, float& c2, float& c3,
                                         uint32_t a0, uint32_t a1, uint32_t a2, uint32_t a3,
                                         uint32_t b0, uint32_t b1) {
    asm volatile("mma.sync.aligned.m16n8k16.row.col.f32.f16.f16.f32 "
                 "{%0,%1,%2,%3}, {%4,%5,%6,%7}, {%8,%9}, {%0,%1,%2,%3};"
                 : "+f"(c0), "+f"(c1), "+f"(c2), "+f"(c3)
                 : "r"(a0), "r"(a1), "r"(a2), "r"(a3), "r"(b0), "r"(b1));
}
__device__ __forceinline__ float warp_sum(float v) {
#pragma unroll
    for (int o = 16; o; o >>= 1) v += __shfl_xor_sync(0xffffffffu, v, o);
    return v;
}
__device__ __forceinline__ uint32_t swz(uint32_t row, uint32_t q) {
    return row * 64 + (q ^ ((row & 6u) >> 1)) * 16;
}
__device__ __forceinline__ uint32_t swzf(uint32_t row, uint32_t q) {
    return row * 128 + (q ^ (row & 7u)) * 16;
}
__device__ __forceinline__ float celu1(float y) {
    return (y > 0.f) ? y : expm1f(y);
}
__device__ __forceinline__ uint32_t pack_half2(float a0, float a1) {
    __half2 t = __floats2half2_rn(a0, a1);
    return *reinterpret_cast<uint32_t*>(&t);
}
// weight split: hi = fp16(w), lo = fp16(w - hi); packed pairs
__device__ __forceinline__ void wsplit2(float a0, float a1, uint32_t& hp, uint32_t& lp) {
    __half h0 = __float2half_rn(a0), h1 = __float2half_rn(a1);
    __half2 hh; hh.x = h0; hh.y = h1;
    hp = *reinterpret_cast<uint32_t*>(&hh);
    lp = pack_half2(a0 - __half2float(h0), a1 - __half2float(h1));
}

// GEMM1 smem (98304 dynamic):
//  [0, 49152)      B ring: 3 x (Whi 8192 + Wlo 8192)
//  [49152, 81920)  A fp32 staging: 2 x 16384
//  [81920, 98304)  A fp16 tiles:   2 x 8192
#define B_STG     16384
#define OFF_BLO   8192
#define OFF_STAGE 49152
#define STAGE_SZ  16384
#define OFF_ABF   81920
#define A_STG     8192
#define SMEM_G1   98304
// GEMM2 smem (73728 dynamic): B ring 3x16K at 0, A fp16 ring 3x8K at 49152.
#define OFF_A2    49152
#define SMEM_G2   73728

// ---------------------------------------------------------------------------
// Weight split fp32 -> fp16 hi + lo.
// ---------------------------------------------------------------------------
__global__ void __launch_bounds__(256)
wsplit_kernel(const float* __restrict__ src, __half* __restrict__ hi,
              __half* __restrict__ lo, int n4)
{
    int i = blockIdx.x * blockDim.x + threadIdx.x;
    if (i >= n4) return;
    float4 v = reinterpret_cast<const float4*>(src)[i];
    uint32_t h0, l0, h1, l1;
    wsplit2(v.x, v.y, h0, l0);
    wsplit2(v.z, v.w, h1, l1);
    reinterpret_cast<uint32_t*>(hi)[2 * i]     = h0;
    reinterpret_cast<uint32_t*>(hi)[2 * i + 1] = h1;
    reinterpret_cast<uint32_t*>(lo)[2 * i]     = l0;
    reinterpret_cast<uint32_t*>(lo)[2 * i + 1] = l1;
}

// ---------------------------------------------------------------------------
// MMA stage: A single fp16 tile at sa; W hi at sbB, lo at sbB+OFF_BLO.
// 2 MMA passes per (mt, n-tile): c += a*whi; c += a*wlo.
// ---------------------------------------------------------------------------
__device__ __forceinline__ void mma_stage(uint32_t sa, uint32_t sbB,
                                          int lane, int warpM, int warpN,
                                          float acc[4][4][4])
{
#pragma unroll
    for (int ks = 0; ks < 2; ks++) {
        uint32_t a[4][4];
        const uint32_t arow = warpM * 64 + (lane & 15);
        const uint32_t aq   = ks * 2 + (lane >> 4);
#pragma unroll
        for (int mt = 0; mt < 4; mt++) {
            const uint32_t adr = sa + swz(arow + mt * 16, aq);
            ldmx4(a[mt][0], a[mt][1], a[mt][2], a[mt][3], adr);
        }
        const uint32_t brow0 = warpN * 32 + (lane & 7) + ((lane >> 4) & 1) * 8;
        const uint32_t bq    = ks * 2 + ((lane >> 3) & 1);
#pragma unroll
        for (int pr = 0; pr < 2; pr++) {
            uint32_t bh0, bh1, bh2, bh3, bl0, bl1, bl2, bl3;
            const uint32_t adr = sbB + swz(brow0 + pr * 16, bq);
            ldmx4(bh0, bh1, bh2, bh3, adr);
            ldmx4(bl0, bl1, bl2, bl3, adr + OFF_BLO);
#pragma unroll
            for (int mt = 0; mt < 4; mt++) {
                float* c0 = acc[mt][2 * pr];
                mma16816(c0[0], c0[1], c0[2], c0[3],
                         a[mt][0], a[mt][1], a[mt][2], a[mt][3], bh0, bh1);
                mma16816(c0[0], c0[1], c0[2], c0[3],
                         a[mt][0], a[mt][1], a[mt][2], a[mt][3], bl0, bl1);
                float* c1 = acc[mt][2 * pr + 1];
                mma16816(c1[0], c1[1], c1[2], c1[3],
                         a[mt][0], a[mt][1], a[mt][2], a[mt][3], bh2, bh3);
                mma16816(c1[0], c1[1], c1[2], c1[3],
                         a[mt][0], a[mt][1], a[mt][2], a[mt][3], bl2, bl3);
            }
        }
    }
}

// ---------------------------------------------------------------------------
// GEMM1 fused-split: h1raw = x @ W1^T + b1 (fp32) + per-colblock LN partials.
// A: cp.async fp32 x -> staging(2) -> per-thread convert -> fp16 tile(2).
// ---------------------------------------------------------------------------
__global__ void __launch_bounds__(256, 2)
gemm1_fused_kernel(const float* __restrict__ X,
                   const __half* __restrict__ Bhi, const __half* __restrict__ Blo,
                   const float* __restrict__ bias, float* __restrict__ C,
                   float2* __restrict__ gpart, int Mtot)
{
    constexpr int K = 512;
    constexpr int NSTAGES = K / 32;
    extern __shared__ char smem[];
    const uint32_t sb = smem_u32(smem);

    const int tid   = threadIdx.x;
    const int lane  = tid & 31;
    const int wid   = tid >> 5;
    const int warpM = wid >> 2;
    const int warpN = wid & 3;
    const size_t rowBase = (size_t)blockIdx.y * 128;
    const int    colBase = blockIdx.x * 128;

    const int c0r = tid >> 2,  cq = tid & 3;
    const int c1r = 64 + c0r;
    const uint32_t d0 = swz(c0r, cq);
    const uint32_t d1 = swz(c1r, cq);
    const uint32_t f00 = swzf(c0r, 2 * cq), f01 = swzf(c0r, 2 * cq + 1);
    const uint32_t f10 = swzf(c1r, 2 * cq), f11 = swzf(c1r, 2 * cq + 1);
    const float* x0p = X + (rowBase + c0r) * K + cq * 8;
    const float* x1p = X + (rowBase + c1r) * K + cq * 8;

    float acc[4][4][4];
#pragma unroll
    for (int i = 0; i < 4; i++)
#pragma unroll
        for (int j = 0; j < 4; j++)
#pragma unroll
            for (int q = 0; q < 4; q++) acc[i][j][q] = 0.f;

    auto load_stage = [&](int t) {
        const int k0 = t * 32;
        const uint32_t sA = sb + OFF_STAGE + (t & 1) * STAGE_SZ;
        cp_async16(sA + f00, x0p + k0);
        cp_async16(sA + f01, x0p + k0 + 4);
        cp_async16(sA + f10, x1p + k0);
        cp_async16(sA + f11, x1p + k0 + 4);
        const uint32_t sB = sb + (t % 3) * B_STG;
        const size_t g0 = (size_t)(colBase + c0r) * K + k0 + cq * 8;
        const size_t g1 = (size_t)(colBase + c1r) * K + k0 + cq * 8;
        cp_async16(sB + d0,           Bhi + g0);
        cp_async16(sB + d1,           Bhi + g1);
        cp_async16(sB + OFF_BLO + d0, Blo + g0);
        cp_async16(sB + OFF_BLO + d1, Blo + g1);
        CP_COMMIT();
    };

    load_stage(0);
    load_stage(1);

#pragma unroll 1
    for (int t = 0; t < NSTAGES; t++) {
        if (t + 1 < NSTAGES) { CP_WAIT(1); } else { CP_WAIT(0); }
        // convert A(t): own staged fp32 -> fp16, STS one 16B chunk per row-slot
        {
            const char* stg = smem + OFF_STAGE + (t & 1) * STAGE_SZ;
            const uint32_t abase = OFF_ABF + (t & 1) * A_STG;
            const float4 v0 = *reinterpret_cast<const float4*>(stg + f00);
            const float4 v1 = *reinterpret_cast<const float4*>(stg + f01);
            const float4 v2 = *reinterpret_cast<const float4*>(stg + f10);
            const float4 v3 = *reinterpret_cast<const float4*>(stg + f11);
            *reinterpret_cast<uint4*>(smem + abase + d0) = make_uint4(
                pack_half2(v0.x, v0.y), pack_half2(v0.z, v0.w),
                pack_half2(v1.x, v1.y), pack_half2(v1.z, v1.w));
            *reinterpret_cast<uint4*>(smem + abase + d1) = make_uint4(
                pack_half2(v2.x, v2.y), pack_half2(v2.z, v2.w),
                pack_half2(v3.x, v3.y), pack_half2(v3.z, v3.w));
        }
        __syncthreads();
        if (t + 2 < NSTAGES) load_stage(t + 2);

        mma_stage(sb + OFF_ABF + (t & 1) * A_STG, sb + (t % 3) * B_STG,
                  lane, warpM, warpN, acc);
    }
    __syncthreads();   // before reusing smem offset 0 as sred

    float2* sred = reinterpret_cast<float2*>(smem);
#pragma unroll
    for (int mt = 0; mt < 4; mt++) {
        const int rloc = warpM * 64 + mt * 16 + (lane >> 2);
        const size_t r0 = rowBase + rloc;
        float s0 = 0.f, q0 = 0.f, s1 = 0.f, q1 = 0.f;
#pragma unroll
        for (int nt = 0; nt < 4; nt++) {
            const int col = colBase + warpN * 32 + nt * 8 + (lane & 3) * 2;
            const float b0 = bias[col], b1 = bias[col + 1];
            float* c = acc[mt][nt];
            const float v00 = c[0] + b0, v01 = c[1] + b1;
            const float v10 = c[2] + b0, v11 = c[3] + b1;
            *reinterpret_cast<float2*>(C + r0 * 512 + col)       = make_float2(v00, v01);
            *reinterpret_cast<float2*>(C + (r0 + 8) * 512 + col) = make_float2(v10, v11);
            s0 += v00 + v01; q0 += v00 * v00 + v01 * v01;
            s1 += v10 + v11; q1 += v10 * v10 + v11 * v11;
        }
#pragma unroll
        for (int o = 1; o <= 2; o <<= 1) {
            s0 += __shfl_xor_sync(0xffffffffu, s0, o);
            q0 += __shfl_xor_sync(0xffffffffu, q0, o);
            s1 += __shfl_xor_sync(0xffffffffu, s1, o);
            q1 += __shfl_xor_sync(0xffffffffu, q1, o);
        }
        if ((lane & 3) == 0) {
            sred[warpN * 128 + rloc]     = make_float2(s0, q0);
            sred[warpN * 128 + rloc + 8] = make_float2(s1, q1);
        }
    }
    __syncthreads();
    if (tid < 128) {
        float s = 0.f, q = 0.f;
#pragma unroll
        for (int w = 0; w < 4; w++) { s += sred[w * 128 + tid].x; q += sred[w * 128 + tid].y; }
        gpart[(size_t)blockIdx.x * Mtot + rowBase + tid] = make_float2(s, q);
    }
}

// ---------------------------------------------------------------------------
// GEMM2 fused: a1 = celu(LN1(h1raw)) fp16 in regs -> HMMA fp16x2 ->
// LN2+CELU epilogue -> h2.
// ---------------------------------------------------------------------------
__global__ void __launch_bounds__(256, 2)
gemm2_fused_kernel(const float* __restrict__ h1raw, const float2* __restrict__ gpart,
                   const float* __restrict__ g1, const float* __restrict__ be1,
                   const __half* __restrict__ Bhi, const __half* __restrict__ Blo,
                   const float* __restrict__ b2, const float* __restrict__ g2,
                   const float* __restrict__ be2,
                   float* __restrict__ h2, int Mtot)
{
    constexpr int K = 512;
    constexpr int NSTAGES = K / 32;
    extern __shared__ char smem[];
    __shared__ float  smu[128], srstd[128];
    __shared__ float  sg1[512], sbe1[512];
    __shared__ float  sg2[128], sbe2[128], sb2[128];
    __shared__ float2 sred[4][128];
    const uint32_t sb = smem_u32(smem);

    const int tid   = threadIdx.x;
    const int lane  = tid & 31;
    const int wid   = tid >> 5;
    const int warpM = wid >> 2;
    const int warpN = wid & 3;
    const size_t rowBase = (size_t)blockIdx.x * 128;

    if (tid < 128) {
        float s = 0.f, q = 0.f;
#pragma unroll
        for (int b = 0; b < 4; b++) {
            float2 p = gpart[(size_t)b * Mtot + rowBase + tid];
            s += p.x; q += p.y;
        }
        const float mu = s * (1.f / 512.f);
        smu[tid]   = mu;
        srstd[tid] = rsqrtf(q * (1.f / 512.f) - mu * mu + 1e-5f);
        sg2[tid] = g2[tid]; sbe2[tid] = be2[tid]; sb2[tid] = b2[tid];
    }
#pragma unroll
    for (int i = tid; i < 512; i += 256) { sg1[i] = g1[i]; sbe1[i] = be1[i]; }
    __syncthreads();

    const int c0r = tid >> 2,  cq = tid & 3;
    const int c1r = 64 + c0r;
    const uint32_t d0 = swz(c0r, cq);
    const uint32_t d1 = swz(c1r, cq);

    const float* a0p = h1raw + (rowBase + c0r) * K + cq * 8;
    const float* a1p = h1raw + (rowBase + c1r) * K + cq * 8;
    const float mu0 = smu[c0r], rs0 = srstd[c0r];
    const float mu1 = smu[c1r], rs1 = srstd[c1r];

    float acc[4][4][4];
#pragma unroll
    for (int i = 0; i < 4; i++)
#pragma unroll
        for (int j = 0; j < 4; j++)
#pragma unroll
            for (int q = 0; q < 4; q++) acc[i][j][q] = 0.f;

    float4 fA[4];
    auto prefetchA = [&](int t) {
        fA[0] = *reinterpret_cast<const float4*>(a0p + t * 32);
        fA[1] = *reinterpret_cast<const float4*>(a0p + t * 32 + 4);
        fA[2] = *reinterpret_cast<const float4*>(a1p + t * 32);
        fA[3] = *reinterpret_cast<const float4*>(a1p + t * 32 + 4);
    };
    auto load_B = [&](int t) {
        const int k0 = t * 32;
        const uint32_t s = sb + (t % 3) * B_STG;
        const size_t g0 = (size_t)c0r * K + k0 + cq * 8;
        const size_t g1 = (size_t)c1r * K + k0 + cq * 8;
        cp_async16(s + d0,           Bhi + g0);
        cp_async16(s + d1,           Bhi + g1);
        cp_async16(s + OFF_BLO + d0, Blo + g0);
        cp_async16(s + OFF_BLO + d1, Blo + g1);
        CP_COMMIT();
    };

    prefetchA(0);
    load_B(0);
    load_B(1);

#pragma unroll 1
    for (int t = 0; t < NSTAGES; t++) {
        // convert A(t): LN1 + CELU + fp16 -> A ring buffer t%3
        {
            const uint32_t abase = OFF_A2 + (t % 3) * A_STG;
            const int kcol = t * 32 + cq * 8;
            uint32_t p[4];
#pragma unroll
            for (int j = 0; j < 2; j++) {
                const float* v = (j == 0) ? &fA[0].x : &fA[1].x;
#pragma unroll
                for (int e = 0; e < 2; e++) {
                    const int col = kcol + j * 4 + e * 2;
                    float y0 = celu1((v[2*e]   - mu0) * rs0 * sg1[col]     + sbe1[col]);
                    float y1 = celu1((v[2*e+1] - mu0) * rs0 * sg1[col + 1] + sbe1[col + 1]);
                    p[2 * j + e] = pack_half2(y0, y1);
                }
            }
            *reinterpret_cast<uint4*>(smem + abase + d0) = make_uint4(p[0], p[1], p[2], p[3]);
#pragma unroll
            for (int j = 0; j < 2; j++) {
                const float* v = (j == 0) ? &fA[2].x : &fA[3].x;
#pragma unroll
                for (int e = 0; e < 2; e++) {
                    const int col = kcol + j * 4 + e * 2;
                    float y0 = celu1((v[2*e]   - mu1) * rs1 * sg1[col]     + sbe1[col]);
                    float y1 = celu1((v[2*e+1] - mu1) * rs1 * sg1[col + 1] + sbe1[col + 1]);
                    p[2 * j + e] = pack_half2(y0, y1);
                }
            }
            *reinterpret_cast<uint4*>(smem + abase + d1) = make_uint4(p[0], p[1], p[2], p[3]);
        }
        if (t + 1 < NSTAGES) prefetchA(t + 1);
        if (t + 1 < NSTAGES) { CP_WAIT(1); } else { CP_WAIT(0); }
        __syncthreads();
        if (t + 2 < NSTAGES) load_B(t + 2);

        mma_stage(sb + OFF_A2 + (t % 3) * A_STG, sb + (t % 3) * B_STG,
                  lane, warpM, warpN, acc);
    }

    // ---- epilogue: bias2, LN2 over full rows, CELU -> h2 ----
#pragma unroll
    for (int mt = 0; mt < 4; mt++) {
        const int rloc = warpM * 64 + mt * 16 + (lane >> 2);
        float s0 = 0.f, q0 = 0.f, s1 = 0.f, q1 = 0.f;
#pragma unroll
        for (int nt = 0; nt < 4; nt++) {
            const int col = warpN * 32 + nt * 8 + (lane & 3) * 2;
            const float b0 = sb2[col], b1 = sb2[col + 1];
            float* c = acc[mt][nt];
            const float v00 = c[0] + b0, v01 = c[1] + b1;
            const float v10 = c[2] + b0, v11 = c[3] + b1;
            s0 += v00 + v01; q0 += v00 * v00 + v01 * v01;
            s1 += v10 + v11; q1 += v10 * v10 + v11 * v11;
        }
#pragma unroll
        for (int o = 1; o <= 2; o <<= 1) {
            s0 += __shfl_xor_sync(0xffffffffu, s0, o);
            q0 += __shfl_xor_sync(0xffffffffu, q0, o);
            s1 += __shfl_xor_sync(0xffffffffu, s1, o);
            q1 += __shfl_xor_sync(0xffffffffu, q1, o);
        }
        if ((lane & 3) == 0) {
            sred[warpN][rloc]     = make_float2(s0, q0);
            sred[warpN][rloc + 8] = make_float2(s1, q1);
        }
    }
    __syncthreads();
    if (tid < 128) {
        float s = 0.f, q = 0.f;
#pragma unroll
        for (int w = 0; w < 4; w++) { s += sred[w][tid].x; q += sred[w][tid].y; }
        const float mu = s * (1.f / 128.f);
        smu[tid]   = mu;
        srstd[tid] = rsqrtf(q * (1.f / 128.f) - mu * mu + 1e-5f);
    }
    __syncthreads();
#pragma unroll
    for (int mt = 0; mt < 4; mt++) {
        const int rloc = warpM * 64 + mt * 16 + (lane >> 2);
        const float m0 = smu[rloc],     r0s = srstd[rloc];
        const float m1 = smu[rloc + 8], r1s = srstd[rloc + 8];
        const size_t r0 = rowBase + rloc;
#pragma unroll
        for (int nt = 0; nt < 4; nt++) {
            const int col = warpN * 32 + nt * 8 + (lane & 3) * 2;
            const float b0 = sb2[col], b1 = sb2[col + 1];
            float* c = acc[mt][nt];
            float y00 = (c[0] + b0 - m0) * r0s * sg2[col]     + sbe2[col];
            float y01 = (c[1] + b1 - m0) * r0s * sg2[col + 1] + sbe2[col + 1];
            float y10 = (c[2] + b0 - m1) * r1s * sg2[col]     + sbe2[col];
            float y11 = (c[3] + b1 - m1) * r1s * sg2[col + 1] + sbe2[col + 1];
            *reinterpret_cast<float2*>(h2 + r0 * 128 + col) =
                make_float2(celu1(y00), celu1(y01));
            *reinterpret_cast<float2*>(h2 + (r0 + 8) * 128 + col) =
                make_float2(celu1(y10), celu1(y11));
        }
    }
}

// ---------------------------------------------------------------------------
// Tail: layer3 (128->32)+LN+CELU, layer4 (32->8)+LN+CELU, spectral-norm head.
// ---------------------------------------------------------------------------
__global__ void __launch_bounds__(256)
tail_kernel(const float* __restrict__ h2,
            const float* __restrict__ W3, const float* __restrict__ b3,
            const float* __restrict__ g3, const float* __restrict__ be3,
            const float* __restrict__ W4, const float* __restrict__ b4,
            const float* __restrict__ g4, const float* __restrict__ be4,
            const float* __restrict__ Wh, const float* __restrict__ bh,
            const float* __restrict__ u, float* __restrict__ out)
{
    __shared__ float sW3[32 * 128];
    __shared__ float sW4[8 * 32];
    const int tid = threadIdx.x;
    for (int i = tid; i < 32 * 128; i += 256) sW3[i] = W3[i];
    if (tid < 8 * 32) sW4[tid] = W4[tid];
    __syncthreads();

    const int lane = tid & 31;
    const size_t row = (size_t)blockIdx.x * 8 + (tid >> 5);
    const float* rp = h2 + row * 128;
    const float r0 = rp[lane], r1 = rp[lane + 32], r2 = rp[lane + 64], r3 = rp[lane + 96];

    float h3 = 0.f;
#pragma unroll
    for (int j = 0; j < 32; j++) {
        const float* w = sW3 + j * 128;
        float p = r0 * w[lane] + r1 * w[lane + 32] + r2 * w[lane + 64] + r3 * w[lane + 96];
        p = warp_sum(p);
        if (lane == j) h3 = p + b3[j];
    }
    float mu  = warp_sum(h3) * (1.f / 32.f);
    float d   = h3 - mu;
    float var = warp_sum(d * d) * (1.f / 32.f);
    float y3  = d * rsqrtf(var + 1e-5f) * g3[lane] + be3[lane];
    const float c3 = (y3 > 0.f) ? y3 : expm1f(y3);

    float h4 = 0.f;
#pragma unroll
    for (int j = 0; j < 8; j++) {
        float p = warp_sum(c3 * sW4[j * 32 + lane]);
        if (lane == j) h4 = p + b4[j];
    }
    const bool act = (lane < 8);
    float hv = act ? h4 : 0.f;
    mu  = warp_sum(hv) * 0.125f;
    d   = act ? (h4 - mu) : 0.f;
    var = warp_sum(d * d) * 0.125f;
    float c4 = 0.f;
    if (act) {
        float y4 = d * rsqrtf(var + 1e-5f) * g4[lane] + be4[lane];
        c4 = (y4 > 0.f) ? y4 : expm1f(y4);
    }

    const float wh  = act ? Wh[lane] : 0.f;
    const float nrm = sqrtf(warp_sum(wh * wh));
    const float u0  = u[0];
    const float vden = fabsf(u0) * nrm + 1e-12f;
    const float t    = u0 * nrm * nrm / vden;
    const float u2n  = t / (fabsf(t) + 1e-12f);
    const float sigma = u2n * t;

    float p = warp_sum(c4 * wh / sigma);
    if (lane == 0) out[row] = p + bh[0];
}

// ---------------------------------------------------------------------------
extern "C" void kernel_launch(void* const* d_in, const int* in_sizes, int n_in,
                              void* d_out, int out_size)
{
    const float* x   = (const float*)d_in[0];
    const float* W1  = (const float*)d_in[1];
    const float* b1  = (const float*)d_in[2];
    const float* g1  = (const float*)d_in[3];
    const float* be1 = (const float*)d_in[4];
    const float* W2  = (const float*)d_in[5];
    const float* b2  = (const float*)d_in[6];
    const float* g2  = (const float*)d_in[7];
    const float* be2 = (const float*)d_in[8];
    const float* W3  = (const float*)d_in[9];
    const float* b3  = (const float*)d_in[10];
    const float* g3  = (const float*)d_in[11];
    const float* be3 = (const float*)d_in[12];
    const float* W4  = (const float*)d_in[13];
    const float* b4  = (const float*)d_in[14];
    const float* g4  = (const float*)d_in[15];
    const float* be4 = (const float*)d_in[16];
    const float* Wh  = (const float*)d_in[17];
    const float* bh  = (const float*)d_in[18];
    const float* u   = (const float*)d_in[19];
    float* out = (float*)d_out;

    const int M = in_sizes[0] / 512;   // 131072

    __half *w1hi, *w1lo, *w2hi, *w2lo;
    float *h1raw, *h2;
    float2* part;
    cudaGetSymbolAddress((void**)&h1raw, g_h1raw);
    cudaGetSymbolAddress((void**)&h2,    g_h2);
    cudaGetSymbolAddress((void**)&part,  g_part);
    cudaGetSymbolAddress((void**)&w1hi,  g_w1hi);
    cudaGetSymbolAddress((void**)&w1lo,  g_w1lo);
    cudaGetSymbolAddress((void**)&w2hi,  g_w2hi);
    cudaGetSymbolAddress((void**)&w2lo,  g_w2lo);

    cudaFuncSetAttribute(gemm1_fused_kernel,
                         cudaFuncAttributeMaxDynamicSharedMemorySize, SMEM_G1);
    cudaFuncSetAttribute(gemm2_fused_kernel,
                         cudaFuncAttributeMaxDynamicSharedMemorySize, SMEM_G2);

    // Split weights to fp16 hi/lo (small, exact to ~2^-24)
    wsplit_kernel<<<(512 * 512 / 4 + 255) / 256, 256>>>(W1, w1hi, w1lo, 512 * 512 / 4);
    wsplit_kernel<<<(128 * 512 / 4 + 255) / 256, 256>>>(W2, w2hi, w2lo, 128 * 512 / 4);

    // Layer 1: fused x->fp16 GEMM -> h1raw fp32 + LN partials
    gemm1_fused_kernel<<<dim3(4, M / 128), 256, SMEM_G1>>>(
        x, w1hi, w1lo, b1, h1raw, part, M);

    // Layer 2: fused LN1+CELU+fp16 -> GEMM -> LN2+CELU -> h2
    gemm2_fused_kernel<<<M / 128, 256, SMEM_G2>>>(
        h1raw, part, g1, be1, w2hi, w2lo, b2, g2, be2, h2, M);

    // Layers 3+4 + spectral-norm head
    tail_kernel<<<M / 8, 256>>>(h2, W3, b3, g3, be3, W4, b4, g4, be4, Wh, bh, u, out);
}

// round 12
// speedup vs baseline: 1.3612x; 1.0893x over previous
#include <cuda_runtime.h>
#include <cuda_fp16.h>
#include <cstdint>

// ---------------------------------------------------------------------------
// B=131072, chain 512 ->(W1)512 ->(W2)128 ->(W3)32 ->(W4)8 ->(Wh)1
// fp16 asymmetric-split HMMA (2 passes): W = Whi + Wlo; activations fp16.
// xcvt: x fp32 -> fp16 (single).  GEMM1: pure cp.async pipeline (R5 struct),
// A fp16 + W1 hi/lo, LN partials epilogue.  GEMM2: fused LN1+CELU(fast)+fp16
// convert -> HMMA -> LN2+CELU epilogue.  Tail unchanged.
// ---------------------------------------------------------------------------

#define BATCH 131072

__device__ __align__(256) __half g_xh   [BATCH * 512];
__device__ __align__(256) float  g_h1raw[BATCH * 512];
__device__ __align__(256) float  g_h2   [BATCH * 128];
__device__ __align__(256) float2 g_part [4 * BATCH];
__device__ __align__(256) __half g_w1hi [512 * 512];
__device__ __align__(256) __half g_w1lo [512 * 512];
__device__ __align__(256) __half g_w2hi [128 * 512];
__device__ __align__(256) __half g_w2lo [128 * 512];

// ------------------------------ helpers ------------------------------------
__device__ __forceinline__ uint32_t smem_u32(const void* p) {
    uint32_t a;
    asm("{ .reg .u64 t; cvta.to.shared.u64 t, %1; cvt.u32.u64 %0, t; }"
        : "=r"(a) : "l"(p));
    return a;
}
__device__ __forceinline__ void cp_async16(uint32_t dst, const void* src) {
    asm volatile("cp.async.cg.shared.global [%0], [%1], 16;"
                 :: "r"(dst), "l"(src) : "memory");
}
#define CP_COMMIT() asm volatile("cp.async.commit_group;" ::: "memory")
#define CP_WAIT(n)  asm volatile("cp.async.wait_group %0;" :: "n"(n) : "memory")

__device__ __forceinline__ void ldmx4(uint32_t& r0, uint32_t& r1,
                                      uint32_t& r2, uint32_t& r3, uint32_t a) {
    asm volatile("ldmatrix.sync.aligned.m8n8.x4.shared.b16 {%0,%1,%2,%3}, [%4];"
                 : "=r"(r0), "=r"(r1), "=r"(r2), "=r"(r3) : "r"(a));
}
__device__ __forceinline__ void mma16816(float& c0, float& c1, float& c2, float& c3,
                                         uint32_t a0, uint32_t a1, uint32_t a2, uint32_t a3,
                                         uint32_t b0, uint32_t b1) {
    asm volatile("mma.sync.aligned.m16n8k16.row.col.f32.f16.f16.f32 "
                 "{%0,%1,%2,%3}, {%4,%5,%6,%7}, {%8,%9}, {%0,%1,%2,%3};"
                 : "+f"(c0), "+f"(c1), "+f"(c2), "+f"(c3)
                 : "r"(a0), "r"(a1), "r"(a2), "r"(a3), "r"(b0), "r"(b1));
}
__device__ __forceinline__ float warp_sum(float v) {
#pragma unroll
    for (int o = 16; o; o >>= 1) v += __shfl_xor_sync(0xffffffffu, v, o);
    return v;
}
__device__ __forceinline__ uint32_t swz(uint32_t row, uint32_t q) {
    return row * 64 + (q ^ ((row & 6u) >> 1)) * 16;
}
// exact celu for the tail
__device__ __forceinline__ float celu1(float y) {
    return (y > 0.f) ? y : expm1f(y);
}
// fast celu for GEMM2 convert/epilogue: __expf error ~1e-7 abs << fp16 quant
__device__ __forceinline__ float celu_fast(float y) {
    return (y > 0.f) ? y : (__expf(y) - 1.f);
}
__device__ __forceinline__ uint32_t pack_half2(float a0, float a1) {
    __half2 t = __floats2half2_rn(a0, a1);
    return *reinterpret_cast<uint32_t*>(&t);
}
__device__ __forceinline__ void wsplit2(float a0, float a1, uint32_t& hp, uint32_t& lp) {
    __half h0 = __float2half_rn(a0), h1 = __float2half_rn(a1);
    __half2 hh; hh.x = h0; hh.y = h1;
    hp = *reinterpret_cast<uint32_t*>(&hh);
    lp = pack_half2(a0 - __half2float(h0), a1 - __half2float(h1));
}

// GEMM1 smem: 3-ring of (A 8192 + Whi 8192 + Wlo 8192) = 73728 B dynamic.
#define G1_STG    24576
#define G1_OFF_BH 8192
#define G1_OFF_BL 16384
#define SMEM_G1   73728
// GEMM2 smem: B ring 3 x 16384 at 0, A fp16 ring 3 x 8192 at 49152 = 73728.
#define B_STG     16384
#define OFF_BLO   8192
#define OFF_A2    49152
#define A_STG     8192
#define SMEM_G2   73728

// ---------------------------------------------------------------------------
// x fp32 -> fp16 (single value).
// ---------------------------------------------------------------------------
__global__ void __launch_bounds__(256)
xcvt_kernel(const float* __restrict__ src, __half* __restrict__ dst, int n4)
{
    int i = blockIdx.x * blockDim.x + threadIdx.x;
    if (i >= n4) return;
    float4 v = reinterpret_cast<const float4*>(src)[i];
    uint2 o;
    o.x = pack_half2(v.x, v.y);
    o.y = pack_half2(v.z, v.w);
    reinterpret_cast<uint2*>(dst)[i] = o;
}

// ---------------------------------------------------------------------------
// Weight split fp32 -> fp16 hi + lo.
// ---------------------------------------------------------------------------
__global__ void __launch_bounds__(256)
wsplit_kernel(const float* __restrict__ src, __half* __restrict__ hi,
              __half* __restrict__ lo, int n4)
{
    int i = blockIdx.x * blockDim.x + threadIdx.x;
    if (i >= n4) return;
    float4 v = reinterpret_cast<const float4*>(src)[i];
    uint32_t h0, l0, h1, l1;
    wsplit2(v.x, v.y, h0, l0);
    wsplit2(v.z, v.w, h1, l1);
    reinterpret_cast<uint32_t*>(hi)[2 * i]     = h0;
    reinterpret_cast<uint32_t*>(hi)[2 * i + 1] = h1;
    reinterpret_cast<uint32_t*>(lo)[2 * i]     = l0;
    reinterpret_cast<uint32_t*>(lo)[2 * i + 1] = l1;
}

// ---------------------------------------------------------------------------
// MMA stage: A fp16 tile at sa; W hi at sbB, lo at sbB + blo_off.
// ---------------------------------------------------------------------------
__device__ __forceinline__ void mma_stage(uint32_t sa, uint32_t sbB, uint32_t blo_off,
                                          int lane, int warpM, int warpN,
                                          float acc[4][4][4])
{
#pragma unroll
    for (int ks = 0; ks < 2; ks++) {
        uint32_t a[4][4];
        const uint32_t arow = warpM * 64 + (lane & 15);
        const uint32_t aq   = ks * 2 + (lane >> 4);
#pragma unroll
        for (int mt = 0; mt < 4; mt++) {
            const uint32_t adr = sa + swz(arow + mt * 16, aq);
            ldmx4(a[mt][0], a[mt][1], a[mt][2], a[mt][3], adr);
        }
        const uint32_t brow0 = warpN * 32 + (lane & 7) + ((lane >> 4) & 1) * 8;
        const uint32_t bq    = ks * 2 + ((lane >> 3) & 1);
#pragma unroll
        for (int pr = 0; pr < 2; pr++) {
            uint32_t bh0, bh1, bh2, bh3, bl0, bl1, bl2, bl3;
            const uint32_t adr = sbB + swz(brow0 + pr * 16, bq);
            ldmx4(bh0, bh1, bh2, bh3, adr);
            ldmx4(bl0, bl1, bl2, bl3, adr + blo_off);
#pragma unroll
            for (int mt = 0; mt < 4; mt++) {
                float* c0 = acc[mt][2 * pr];
                mma16816(c0[0], c0[1], c0[2], c0[3],
                         a[mt][0], a[mt][1], a[mt][2], a[mt][3], bh0, bh1);
                mma16816(c0[0], c0[1], c0[2], c0[3],
                         a[mt][0], a[mt][1], a[mt][2], a[mt][3], bl0, bl1);
                float* c1 = acc[mt][2 * pr + 1];
                mma16816(c1[0], c1[1], c1[2], c1[3],
                         a[mt][0], a[mt][1], a[mt][2], a[mt][3], bh2, bh3);
                mma16816(c1[0], c1[1], c1[2], c1[3],
                         a[mt][0], a[mt][1], a[mt][2], a[mt][3], bl2, bl3);
            }
        }
    }
}

// ---------------------------------------------------------------------------
// GEMM1 (R5 structure): h1raw = xh @ W1^T + b1 (fp32) + LN partials.
// All operands cp.async; 3-stage ring; 1 barrier/stage; 2 CTAs/SM.
// ---------------------------------------------------------------------------
__global__ void __launch_bounds__(256, 2)
gemm1_kernel(const __half* __restrict__ A,
             const __half* __restrict__ Bhi, const __half* __restrict__ Blo,
             const float* __restrict__ bias, float* __restrict__ C,
             float2* __restrict__ gpart, int Mtot)
{
    constexpr int K = 512;
    constexpr int NSTAGES = K / 32;
    extern __shared__ char smem[];
    __shared__ float2 sred[4][128];
    const uint32_t sb = smem_u32(smem);

    const int tid   = threadIdx.x;
    const int lane  = tid & 31;
    const int wid   = tid >> 5;
    const int warpM = wid >> 2;
    const int warpN = wid & 3;
    const size_t rowBase = (size_t)blockIdx.y * 128;
    const int    colBase = blockIdx.x * 128;

    const int c0r = tid >> 2,  cq = tid & 3;
    const int c1r = 64 + c0r;
    const uint32_t d0 = swz(c0r, cq);
    const uint32_t d1 = swz(c1r, cq);

    float acc[4][4][4];
#pragma unroll
    for (int i = 0; i < 4; i++)
#pragma unroll
        for (int j = 0; j < 4; j++)
#pragma unroll
            for (int q = 0; q < 4; q++) acc[i][j][q] = 0.f;

    auto load_stage = [&](int t) {
        const int k0 = t * 32;
        const uint32_t s = sb + (t % 3) * G1_STG;
        {
            const size_t g0 = (rowBase + c0r) * K + k0 + cq * 8;
            const size_t g1 = (rowBase + c1r) * K + k0 + cq * 8;
            cp_async16(s + d0, A + g0);
            cp_async16(s + d1, A + g1);
        }
        {
            const size_t g0 = (size_t)(colBase + c0r) * K + k0 + cq * 8;
            const size_t g1 = (size_t)(colBase + c1r) * K + k0 + cq * 8;
            cp_async16(s + G1_OFF_BH + d0, Bhi + g0);
            cp_async16(s + G1_OFF_BH + d1, Bhi + g1);
            cp_async16(s + G1_OFF_BL + d0, Blo + g0);
            cp_async16(s + G1_OFF_BL + d1, Blo + g1);
        }
        CP_COMMIT();
    };

    load_stage(0);
    load_stage(1);

#pragma unroll 1
    for (int t = 0; t < NSTAGES; t++) {
        if (t + 1 < NSTAGES) { CP_WAIT(1); } else { CP_WAIT(0); }
        __syncthreads();
        if (t + 2 < NSTAGES) load_stage(t + 2);

        const uint32_t s = sb + (t % 3) * G1_STG;
        mma_stage(s, s + G1_OFF_BH, G1_OFF_BL - G1_OFF_BH,
                  lane, warpM, warpN, acc);
    }

    // ---- epilogue: + bias, fp32 out, per-row partial (sum, ssq) ----
#pragma unroll
    for (int mt = 0; mt < 4; mt++) {
        const int rloc = warpM * 64 + mt * 16 + (lane >> 2);
        const size_t r0 = rowBase + rloc;
        float s0 = 0.f, q0 = 0.f, s1 = 0.f, q1 = 0.f;
#pragma unroll
        for (int nt = 0; nt < 4; nt++) {
            const int col = colBase + warpN * 32 + nt * 8 + (lane & 3) * 2;
            const float b0 = bias[col], b1 = bias[col + 1];
            float* c = acc[mt][nt];
            const float v00 = c[0] + b0, v01 = c[1] + b1;
            const float v10 = c[2] + b0, v11 = c[3] + b1;
            *reinterpret_cast<float2*>(C + r0 * 512 + col)       = make_float2(v00, v01);
            *reinterpret_cast<float2*>(C + (r0 + 8) * 512 + col) = make_float2(v10, v11);
            s0 += v00 + v01; q0 += v00 * v00 + v01 * v01;
            s1 += v10 + v11; q1 += v10 * v10 + v11 * v11;
        }
#pragma unroll
        for (int o = 1; o <= 2; o <<= 1) {
            s0 += __shfl_xor_sync(0xffffffffu, s0, o);
            q0 += __shfl_xor_sync(0xffffffffu, q0, o);
            s1 += __shfl_xor_sync(0xffffffffu, s1, o);
            q1 += __shfl_xor_sync(0xffffffffu, q1, o);
        }
        if ((lane & 3) == 0) {
            sred[warpN][rloc]     = make_float2(s0, q0);
            sred[warpN][rloc + 8] = make_float2(s1, q1);
        }
    }
    __syncthreads();
    if (tid < 128) {
        float s = 0.f, q = 0.f;
#pragma unroll
        for (int w = 0; w < 4; w++) { s += sred[w][tid].x; q += sred[w][tid].y; }
        gpart[(size_t)blockIdx.x * Mtot + rowBase + tid] = make_float2(s, q);
    }
}

// ---------------------------------------------------------------------------
// GEMM2 fused: a1 = celu_fast(LN1(h1raw)) fp16 in regs -> HMMA fp16x2 ->
// LN2 + celu_fast epilogue -> h2.  LN1 folded to per-(row,col) affine.
// ---------------------------------------------------------------------------
__global__ void __launch_bounds__(256, 2)
gemm2_fused_kernel(const float* __restrict__ h1raw, const float2* __restrict__ gpart,
                   const float* __restrict__ g1, const float* __restrict__ be1,
                   const __half* __restrict__ Bhi, const __half* __restrict__ Blo,
                   const float* __restrict__ b2, const float* __restrict__ g2,
                   const float* __restrict__ be2,
                   float* __restrict__ h2, int Mtot)
{
    constexpr int K = 512;
    constexpr int NSTAGES = K / 32;
    extern __shared__ char smem[];
    __shared__ float  smu[128], srstd[128];
    __shared__ float  sg1[512], sbe1[512];
    __shared__ float  sg2[128], sbe2[128], sb2[128];
    __shared__ float2 sred[4][128];
    const uint32_t sb = smem_u32(smem);

    const int tid   = threadIdx.x;
    const int lane  = tid & 31;
    const int wid   = tid >> 5;
    const int warpM = wid >> 2;
    const int warpN = wid & 3;
    const size_t rowBase = (size_t)blockIdx.x * 128;

    if (tid < 128) {
        float s = 0.f, q = 0.f;
#pragma unroll
        for (int b = 0; b < 4; b++) {
            float2 p = gpart[(size_t)b * Mtot + rowBase + tid];
            s += p.x; q += p.y;
        }
        const float mu = s * (1.f / 512.f);
        smu[tid]   = mu;
        srstd[tid] = rsqrtf(q * (1.f / 512.f) - mu * mu + 1e-5f);
        sg2[tid] = g2[tid]; sbe2[tid] = be2[tid]; sb2[tid] = b2[tid];
    }
#pragma unroll
    for (int i = tid; i < 512; i += 256) { sg1[i] = g1[i]; sbe1[i] = be1[i]; }
    __syncthreads();

    const int c0r = tid >> 2,  cq = tid & 3;
    const int c1r = 64 + c0r;
    const uint32_t d0 = swz(c0r, cq);
    const uint32_t d1 = swz(c1r, cq);

    const float* a0p = h1raw + (rowBase + c0r) * K + cq * 8;
    const float* a1p = h1raw + (rowBase + c1r) * K + cq * 8;
    const float mu0 = smu[c0r], rs0 = srstd[c0r];
    const float mu1 = smu[c1r], rs1 = srstd[c1r];

    float acc[4][4][4];
#pragma unroll
    for (int i = 0; i < 4; i++)
#pragma unroll
        for (int j = 0; j < 4; j++)
#pragma unroll
            for (int q = 0; q < 4; q++) acc[i][j][q] = 0.f;

    float4 fA[4];
    auto prefetchA = [&](int t) {
        fA[0] = *reinterpret_cast<const float4*>(a0p + t * 32);
        fA[1] = *reinterpret_cast<const float4*>(a0p + t * 32 + 4);
        fA[2] = *reinterpret_cast<const float4*>(a1p + t * 32);
        fA[3] = *reinterpret_cast<const float4*>(a1p + t * 32 + 4);
    };
    auto load_B = [&](int t) {
        const int k0 = t * 32;
        const uint32_t s = sb + (t % 3) * B_STG;
        const size_t g0 = (size_t)c0r * K + k0 + cq * 8;
        const size_t g1 = (size_t)c1r * K + k0 + cq * 8;
        cp_async16(s + d0,           Bhi + g0);
        cp_async16(s + d1,           Bhi + g1);
        cp_async16(s + OFF_BLO + d0, Blo + g0);
        cp_async16(s + OFF_BLO + d1, Blo + g1);
        CP_COMMIT();
    };

    prefetchA(0);
    load_B(0);
    load_B(1);

#pragma unroll 1
    for (int t = 0; t < NSTAGES; t++) {
        // convert A(t): affine-LN1 + fast-CELU + fp16 -> A ring buffer t%3
        {
            const uint32_t abase = OFF_A2 + (t % 3) * A_STG;
            const int kcol = t * 32 + cq * 8;
            uint32_t p[4];
#pragma unroll
            for (int j = 0; j < 2; j++) {
                const float* v = (j == 0) ? &fA[0].x : &fA[1].x;
#pragma unroll
                for (int e = 0; e < 2; e++) {
                    const int col = kcol + j * 4 + e * 2;
                    const float a0c = rs0 * sg1[col],     b0c = sbe1[col]     - mu0 * a0c;
                    const float a1c = rs0 * sg1[col + 1], b1c = sbe1[col + 1] - mu0 * a1c;
                    float y0 = celu_fast(v[2*e]   * a0c + b0c);
                    float y1 = celu_fast(v[2*e+1] * a1c + b1c);
                    p[2 * j + e] = pack_half2(y0, y1);
                }
            }
            *reinterpret_cast<uint4*>(smem + abase + d0) = make_uint4(p[0], p[1], p[2], p[3]);
#pragma unroll
            for (int j = 0; j < 2; j++) {
                const float* v = (j == 0) ? &fA[2].x : &fA[3].x;
#pragma unroll
                for (int e = 0; e < 2; e++) {
                    const int col = kcol + j * 4 + e * 2;
                    const float a0c = rs1 * sg1[col],     b0c = sbe1[col]     - mu1 * a0c;
                    const float a1c = rs1 * sg1[col + 1], b1c = sbe1[col + 1] - mu1 * a1c;
                    float y0 = celu_fast(v[2*e]   * a0c + b0c);
                    float y1 = celu_fast(v[2*e+1] * a1c + b1c);
                    p[2 * j + e] = pack_half2(y0, y1);
                }
            }
            *reinterpret_cast<uint4*>(smem + abase + d1) = make_uint4(p[0], p[1], p[2], p[3]);
        }
        if (t + 1 < NSTAGES) prefetchA(t + 1);
        if (t + 1 < NSTAGES) { CP_WAIT(1); } else { CP_WAIT(0); }
        __syncthreads();
        if (t + 2 < NSTAGES) load_B(t + 2);

        mma_stage(sb + OFF_A2 + (t % 3) * A_STG, sb + (t % 3) * B_STG, OFF_BLO,
                  lane, warpM, warpN, acc);
    }

    // ---- epilogue: bias2, LN2 over full rows, fast CELU -> h2 ----
#pragma unroll
    for (int mt = 0; mt < 4; mt++) {
        const int rloc = warpM * 64 + mt * 16 + (lane >> 2);
        float s0 = 0.f, q0 = 0.f, s1 = 0.f, q1 = 0.f;
#pragma unroll
        for (int nt = 0; nt < 4; nt++) {
            const int col = warpN * 32 + nt * 8 + (lane & 3) * 2;
            const float b0 = sb2[col], b1 = sb2[col + 1];
            float* c = acc[mt][nt];
            const float v00 = c[0] + b0, v01 = c[1] + b1;
            const float v10 = c[2] + b0, v11 = c[3] + b1;
            s0 += v00 + v01; q0 += v00 * v00 + v01 * v01;
            s1 += v10 + v11; q1 += v10 * v10 + v11 * v11;
        }
#pragma unroll
        for (int o = 1; o <= 2; o <<= 1) {
            s0 += __shfl_xor_sync(0xffffffffu, s0, o);
            q0 += __shfl_xor_sync(0xffffffffu, q0, o);
            s1 += __shfl_xor_sync(0xffffffffu, s1, o);
            q1 += __shfl_xor_sync(0xffffffffu, q1, o);
        }
        if ((lane & 3) == 0) {
            sred[warpN][rloc]     = make_float2(s0, q0);
            sred[warpN][rloc + 8] = make_float2(s1, q1);
        }
    }
    __syncthreads();
    if (tid < 128) {
        float s = 0.f, q = 0.f;
#pragma unroll
        for (int w = 0; w < 4; w++) { s += sred[w][tid].x; q += sred[w][tid].y; }
        const float mu = s * (1.f / 128.f);
        smu[tid]   = mu;
        srstd[tid] = rsqrtf(q * (1.f / 128.f) - mu * mu + 1e-5f);
    }
    __syncthreads();
#pragma unroll
    for (int mt = 0; mt < 4; mt++) {
        const int rloc = warpM * 64 + mt * 16 + (lane >> 2);
        const float m0 = smu[rloc],     r0s = srstd[rloc];
        const float m1 = smu[rloc + 8], r1s = srstd[rloc + 8];
        const size_t r0 = rowBase + rloc;
#pragma unroll
        for (int nt = 0; nt < 4; nt++) {
            const int col = warpN * 32 + nt * 8 + (lane & 3) * 2;
            const float b0 = sb2[col], b1 = sb2[col + 1];
            float* c = acc[mt][nt];
            float y00 = (c[0] + b0 - m0) * r0s * sg2[col]     + sbe2[col];
            float y01 = (c[1] + b1 - m0) * r0s * sg2[col + 1] + sbe2[col + 1];
            float y10 = (c[2] + b0 - m1) * r1s * sg2[col]     + sbe2[col];
            float y11 = (c[3] + b1 - m1) * r1s * sg2[col + 1] + sbe2[col + 1];
            *reinterpret_cast<float2*>(h2 + r0 * 128 + col) =
                make_float2(celu_fast(y00), celu_fast(y01));
            *reinterpret_cast<float2*>(h2 + (r0 + 8) * 128 + col) =
                make_float2(celu_fast(y10), celu_fast(y11));
        }
    }
}

// ---------------------------------------------------------------------------
// Tail: layer3 (128->32)+LN+CELU, layer4 (32->8)+LN+CELU, spectral-norm head.
// ---------------------------------------------------------------------------
__global__ void __launch_bounds__(256)
tail_kernel(const float* __restrict__ h2,
            const float* __restrict__ W3, const float* __restrict__ b3,
            const float* __restrict__ g3, const float* __restrict__ be3,
            const float* __restrict__ W4, const float* __restrict__ b4,
            const float* __restrict__ g4, const float* __restrict__ be4,
            const float* __restrict__ Wh, const float* __restrict__ bh,
            const float* __restrict__ u, float* __restrict__ out)
{
    __shared__ float sW3[32 * 128];
    __shared__ float sW4[8 * 32];
    const int tid = threadIdx.x;
    for (int i = tid; i < 32 * 128; i += 256) sW3[i] = W3[i];
    if (tid < 8 * 32) sW4[tid] = W4[tid];
    __syncthreads();

    const int lane = tid & 31;
    const size_t row = (size_t)blockIdx.x * 8 + (tid >> 5);
    const float* rp = h2 + row * 128;
    const float r0 = rp[lane], r1 = rp[lane + 32], r2 = rp[lane + 64], r3 = rp[lane + 96];

    float h3 = 0.f;
#pragma unroll
    for (int j = 0; j < 32; j++) {
        const float* w = sW3 + j * 128;
        float p = r0 * w[lane] + r1 * w[lane + 32] + r2 * w[lane + 64] + r3 * w[lane + 96];
        p = warp_sum(p);
        if (lane == j) h3 = p + b3[j];
    }
    float mu  = warp_sum(h3) * (1.f / 32.f);
    float d   = h3 - mu;
    float var = warp_sum(d * d) * (1.f / 32.f);
    float y3  = d * rsqrtf(var + 1e-5f) * g3[lane] + be3[lane];
    const float c3 = celu1(y3);

    float h4 = 0.f;
#pragma unroll
    for (int j = 0; j < 8; j++) {
        float p = warp_sum(c3 * sW4[j * 32 + lane]);
        if (lane == j) h4 = p + b4[j];
    }
    const bool act = (lane < 8);
    float hv = act ? h4 : 0.f;
    mu  = warp_sum(hv) * 0.125f;
    d   = act ? (h4 - mu) : 0.f;
    var = warp_sum(d * d) * 0.125f;
    float c4 = 0.f;
    if (act) {
        float y4 = d * rsqrtf(var + 1e-5f) * g4[lane] + be4[lane];
        c4 = celu1(y4);
    }

    const float wh  = act ? Wh[lane] : 0.f;
    const float nrm = sqrtf(warp_sum(wh * wh));
    const float u0  = u[0];
    const float vden = fabsf(u0) * nrm + 1e-12f;
    const float t    = u0 * nrm * nrm / vden;
    const float u2n  = t / (fabsf(t) + 1e-12f);
    const float sigma = u2n * t;

    float p = warp_sum(c4 * wh / sigma);
    if (lane == 0) out[row] = p + bh[0];
}

// ---------------------------------------------------------------------------
extern "C" void kernel_launch(void* const* d_in, const int* in_sizes, int n_in,
                              void* d_out, int out_size)
{
    const float* x   = (const float*)d_in[0];
    const float* W1  = (const float*)d_in[1];
    const float* b1  = (const float*)d_in[2];
    const float* g1  = (const float*)d_in[3];
    const float* be1 = (const float*)d_in[4];
    const float* W2  = (const float*)d_in[5];
    const float* b2  = (const float*)d_in[6];
    const float* g2  = (const float*)d_in[7];
    const float* be2 = (const float*)d_in[8];
    const float* W3  = (const float*)d_in[9];
    const float* b3  = (const float*)d_in[10];
    const float* g3  = (const float*)d_in[11];
    const float* be3 = (const float*)d_in[12];
    const float* W4  = (const float*)d_in[13];
    const float* b4  = (const float*)d_in[14];
    const float* g4  = (const float*)d_in[15];
    const float* be4 = (const float*)d_in[16];
    const float* Wh  = (const float*)d_in[17];
    const float* bh  = (const float*)d_in[18];
    const float* u   = (const float*)d_in[19];
    float* out = (float*)d_out;

    const int M = in_sizes[0] / 512;   // 131072

    __half *xh, *w1hi, *w1lo, *w2hi, *w2lo;
    float *h1raw, *h2;
    float2* part;
    cudaGetSymbolAddress((void**)&xh,    g_xh);
    cudaGetSymbolAddress((void**)&h1raw, g_h1raw);
    cudaGetSymbolAddress((void**)&h2,    g_h2);
    cudaGetSymbolAddress((void**)&part,  g_part);
    cudaGetSymbolAddress((void**)&w1hi,  g_w1hi);
    cudaGetSymbolAddress((void**)&w1lo,  g_w1lo);
    cudaGetSymbolAddress((void**)&w2hi,  g_w2hi);
    cudaGetSymbolAddress((void**)&w2lo,  g_w2lo);

    cudaFuncSetAttribute(gemm1_kernel,
                         cudaFuncAttributeMaxDynamicSharedMemorySize, SMEM_G1);
    cudaFuncSetAttribute(gemm2_fused_kernel,
                         cudaFuncAttributeMaxDynamicSharedMemorySize, SMEM_G2);

    // Conversions: x -> fp16 (single), weights -> fp16 hi/lo
    const int n4x = M * 512 / 4;
    xcvt_kernel<<<(n4x + 255) / 256, 256>>>(x, xh, n4x);
    wsplit_kernel<<<(512 * 512 / 4 + 255) / 256, 256>>>(W1, w1hi, w1lo, 512 * 512 / 4);
    wsplit_kernel<<<(128 * 512 / 4 + 255) / 256, 256>>>(W2, w2hi, w2lo, 128 * 512 / 4);

    // Layer 1: pure cp.async GEMM -> h1raw fp32 + LN partials
    gemm1_kernel<<<dim3(4, M / 128), 256, SMEM_G1>>>(
        xh, w1hi, w1lo, b1, h1raw, part, M);

    // Layer 2: fused LN1+CELU+fp16 -> GEMM -> LN2+CELU -> h2
    gemm2_fused_kernel<<<M / 128, 256, SMEM_G2>>>(
        h1raw, part, g1, be1, w2hi, w2lo, b2, g2, be2, h2, M);

    // Layers 3+4 + spectral-norm head
    tail_kernel<<<M / 8, 256>>>(h2, W3, b3, g3, be3, W4, b4, g4, be4, Wh, bh, u, out);
}

// round 13
// speedup vs baseline: 1.3942x; 1.0243x over previous
#include <cuda_runtime.h>
#include <cuda_fp16.h>
#include <cstdint>

// ---------------------------------------------------------------------------
// B=131072, chain 512 ->(W1)512 ->(W2)128 ->(W3)32 ->(W4)8 ->(Wh)1
// fp16 asymmetric-split HMMA (2 passes): W = Whi + Wlo; activations fp16.
// GEMM1: fused x->fp16 (cp.async fp32 staging -> reg convert -> fp16 tile),
//        W1 hi/lo 3-ring, LN partials epilogue. 2 CTAs/SM, 1 barrier/stage.
// GEMM2: fused LN1+fastCELU+fp16 convert -> HMMA -> LN2+fastCELU epilogue.
// ---------------------------------------------------------------------------

#define BATCH 131072

__device__ __align__(256) float  g_h1raw[BATCH * 512];
__device__ __align__(256) float  g_h2   [BATCH * 128];
__device__ __align__(256) float2 g_part [4 * BATCH];
__device__ __align__(256) __half g_w1hi [512 * 512];
__device__ __align__(256) __half g_w1lo [512 * 512];
__device__ __align__(256) __half g_w2hi [128 * 512];
__device__ __align__(256) __half g_w2lo [128 * 512];

// ------------------------------ helpers ------------------------------------
__device__ __forceinline__ uint32_t smem_u32(const void* p) {
    uint32_t a;
    asm("{ .reg .u64 t; cvta.to.shared.u64 t, %1; cvt.u32.u64 %0, t; }"
        : "=r"(a) : "l"(p));
    return a;
}
__device__ __forceinline__ void cp_async16(uint32_t dst, const void* src) {
    asm volatile("cp.async.cg.shared.global [%0], [%1], 16;"
                 :: "r"(dst), "l"(src) : "memory");
}
#define CP_COMMIT() asm volatile("cp.async.commit_group;" ::: "memory")
#define CP_WAIT(n)  asm volatile("cp.async.wait_group %0;" :: "n"(n) : "memory")

__device__ __forceinline__ void ldmx4(uint32_t& r0, uint32_t& r1,
                                      uint32_t& r2, uint32_t& r3, uint32_t a) {
    asm volatile("ldmatrix.sync.aligned.m8n8.x4.shared.b16 {%0,%1,%2,%3}, [%4];"
                 : "=r"(r0), "=r"(r1), "=r"(r2), "=r"(r3) : "r"(a));
}
__device__ __forceinline__ void mma16816(float& c0, float& c1, float& c2, float& c3,
                                         uint32_t a0, uint32_t a1, uint32_t a2, uint32_t a3,
                                         uint32_t b0, uint32_t b1) {
    asm volatile("mma.sync.aligned.m16n8k16.row.col.f32.f16.f16.f32 "
                 "{%0,%1,%2,%3}, {%4,%5,%6,%7}, {%8,%9}, {%0,%1,%2,%3};"
                 : "+f"(c0), "+f"(c1), "+f"(c2), "+f"(c3)
                 : "r"(a0), "r"(a1), "r"(a2), "r"(a3), "r"(b0), "r"(b1));
}
__device__ __forceinline__ float warp_sum(float v) {
#pragma unroll
    for (int o = 16; o; o >>= 1) v += __shfl_xor_sync(0xffffffffu, v, o);
    return v;
}
__device__ __forceinline__ uint32_t swz(uint32_t row, uint32_t q) {
    return row * 64 + (q ^ ((row & 6u) >> 1)) * 16;
}
__device__ __forceinline__ uint32_t swzf(uint32_t row, uint32_t q) {
    return row * 128 + (q ^ (row & 7u)) * 16;
}
__device__ __forceinline__ float celu1(float y) {        // exact, tail only
    return (y > 0.f) ? y : expm1f(y);
}
__device__ __forceinline__ float celu_fast(float y) {    // MUFU-based
    return (y > 0.f) ? y : (__expf(y) - 1.f);
}
__device__ __forceinline__ uint32_t pack_half2(float a0, float a1) {
    __half2 t = __floats2half2_rn(a0, a1);
    return *reinterpret_cast<uint32_t*>(&t);
}
__device__ __forceinline__ void wsplit2(float a0, float a1, uint32_t& hp, uint32_t& lp) {
    __half h0 = __float2half_rn(a0), h1 = __float2half_rn(a1);
    __half2 hh; hh.x = h0; hh.y = h1;
    hp = *reinterpret_cast<uint32_t*>(&hh);
    lp = pack_half2(a0 - __half2float(h0), a1 - __half2float(h1));
}

// GEMM1 smem (98304 dynamic):
//  [0, 49152)      B ring: 3 x (Whi 8192 + Wlo 8192)
//  [49152, 81920)  A fp32 staging: 2 x 16384
//  [81920, 98304)  A fp16 tiles:   2 x 8192
#define B_STG     16384
#define OFF_BLO   8192
#define OFF_STAGE 49152
#define STAGE_SZ  16384
#define OFF_ABF   81920
#define A_STG     8192
#define SMEM_G1   98304
// GEMM2 smem (73728 dynamic): B ring 3x16K at 0, A fp16 ring 3x8K at 49152.
#define OFF_A2    49152
#define SMEM_G2   73728

// ---------------------------------------------------------------------------
// Both weight splits in one launch: i < n4a -> W1, else W2.
// ---------------------------------------------------------------------------
__global__ void __launch_bounds__(256)
wsplit2_kernel(const float* __restrict__ srcA, __half* __restrict__ hiA,
               __half* __restrict__ loA, int n4a,
               const float* __restrict__ srcB, __half* __restrict__ hiB,
               __half* __restrict__ loB, int n4b)
{
    int i = blockIdx.x * blockDim.x + threadIdx.x;
    const float* src; __half *hi, *lo;
    if (i < n4a) { src = srcA; hi = hiA; lo = loA; }
    else {
        i -= n4a;
        if (i >= n4b) return;
        src = srcB; hi = hiB; lo = loB;
    }
    float4 v = reinterpret_cast<const float4*>(src)[i];
    uint32_t h0, l0, h1, l1;
    wsplit2(v.x, v.y, h0, l0);
    wsplit2(v.z, v.w, h1, l1);
    reinterpret_cast<uint32_t*>(hi)[2 * i]     = h0;
    reinterpret_cast<uint32_t*>(hi)[2 * i + 1] = h1;
    reinterpret_cast<uint32_t*>(lo)[2 * i]     = l0;
    reinterpret_cast<uint32_t*>(lo)[2 * i + 1] = l1;
}

// ---------------------------------------------------------------------------
// MMA stage: A fp16 tile at sa; W hi at sbB, lo at sbB + blo_off.
// ---------------------------------------------------------------------------
__device__ __forceinline__ void mma_stage(uint32_t sa, uint32_t sbB, uint32_t blo_off,
                                          int lane, int warpM, int warpN,
                                          float acc[4][4][4])
{
#pragma unroll
    for (int ks = 0; ks < 2; ks++) {
        uint32_t a[4][4];
        const uint32_t arow = warpM * 64 + (lane & 15);
        const uint32_t aq   = ks * 2 + (lane >> 4);
#pragma unroll
        for (int mt = 0; mt < 4; mt++) {
            const uint32_t adr = sa + swz(arow + mt * 16, aq);
            ldmx4(a[mt][0], a[mt][1], a[mt][2], a[mt][3], adr);
        }
        const uint32_t brow0 = warpN * 32 + (lane & 7) + ((lane >> 4) & 1) * 8;
        const uint32_t bq    = ks * 2 + ((lane >> 3) & 1);
#pragma unroll
        for (int pr = 0; pr < 2; pr++) {
            uint32_t bh0, bh1, bh2, bh3, bl0, bl1, bl2, bl3;
            const uint32_t adr = sbB + swz(brow0 + pr * 16, bq);
            ldmx4(bh0, bh1, bh2, bh3, adr);
            ldmx4(bl0, bl1, bl2, bl3, adr + blo_off);
#pragma unroll
            for (int mt = 0; mt < 4; mt++) {
                float* c0 = acc[mt][2 * pr];
                mma16816(c0[0], c0[1], c0[2], c0[3],
                         a[mt][0], a[mt][1], a[mt][2], a[mt][3], bh0, bh1);
                mma16816(c0[0], c0[1], c0[2], c0[3],
                         a[mt][0], a[mt][1], a[mt][2], a[mt][3], bl0, bl1);
                float* c1 = acc[mt][2 * pr + 1];
                mma16816(c1[0], c1[1], c1[2], c1[3],
                         a[mt][0], a[mt][1], a[mt][2], a[mt][3], bh2, bh3);
                mma16816(c1[0], c1[1], c1[2], c1[3],
                         a[mt][0], a[mt][1], a[mt][2], a[mt][3], bl2, bl3);
            }
        }
    }
}

// ---------------------------------------------------------------------------
// GEMM1 fused-xcvt: h1raw = x @ W1^T + b1 (fp32) + per-colblock LN partials.
// A path: cp.async fp32 x -> staging(2) -> per-thread fp16 convert -> tile(2).
// Ordering (R10-proven): convert(t) pre-barrier touches thread-own staging
// chunks and A buffer t&1 whose last reader was mma(t-1) pre-barrier(t-1).
// ---------------------------------------------------------------------------
__global__ void __launch_bounds__(256, 2)
gemm1_fused_kernel(const float* __restrict__ X,
                   const __half* __restrict__ Bhi, const __half* __restrict__ Blo,
                   const float* __restrict__ bias, float* __restrict__ C,
                   float2* __restrict__ gpart, int Mtot)
{
    constexpr int K = 512;
    constexpr int NSTAGES = K / 32;
    extern __shared__ char smem[];
    __shared__ float2 sred[4][128];
    const uint32_t sb = smem_u32(smem);

    const int tid   = threadIdx.x;
    const int lane  = tid & 31;
    const int wid   = tid >> 5;
    const int warpM = wid >> 2;
    const int warpN = wid & 3;
    const size_t rowBase = (size_t)blockIdx.y * 128;
    const int    colBase = blockIdx.x * 128;

    const int c0r = tid >> 2,  cq = tid & 3;
    const int c1r = 64 + c0r;
    const uint32_t d0 = swz(c0r, cq);
    const uint32_t d1 = swz(c1r, cq);
    const uint32_t f00 = swzf(c0r, 2 * cq), f01 = swzf(c0r, 2 * cq + 1);
    const uint32_t f10 = swzf(c1r, 2 * cq), f11 = swzf(c1r, 2 * cq + 1);
    const float* x0p = X + (rowBase + c0r) * K + cq * 8;
    const float* x1p = X + (rowBase + c1r) * K + cq * 8;

    float acc[4][4][4];
#pragma unroll
    for (int i = 0; i < 4; i++)
#pragma unroll
        for (int j = 0; j < 4; j++)
#pragma unroll
            for (int q = 0; q < 4; q++) acc[i][j][q] = 0.f;

    auto load_stage = [&](int t) {
        const int k0 = t * 32;
        const uint32_t sA = sb + OFF_STAGE + (t & 1) * STAGE_SZ;
        cp_async16(sA + f00, x0p + k0);
        cp_async16(sA + f01, x0p + k0 + 4);
        cp_async16(sA + f10, x1p + k0);
        cp_async16(sA + f11, x1p + k0 + 4);
        const uint32_t sB = sb + (t % 3) * B_STG;
        const size_t g0 = (size_t)(colBase + c0r) * K + k0 + cq * 8;
        const size_t g1 = (size_t)(colBase + c1r) * K + k0 + cq * 8;
        cp_async16(sB + d0,           Bhi + g0);
        cp_async16(sB + d1,           Bhi + g1);
        cp_async16(sB + OFF_BLO + d0, Blo + g0);
        cp_async16(sB + OFF_BLO + d1, Blo + g1);
        CP_COMMIT();
    };

    load_stage(0);
    load_stage(1);

#pragma unroll 1
    for (int t = 0; t < NSTAGES; t++) {
        if (t + 1 < NSTAGES) { CP_WAIT(1); } else { CP_WAIT(0); }
        // convert A(t): staged fp32 (own chunks) -> fp16, one 16B STS per row
        {
            const char* stg = smem + OFF_STAGE + (t & 1) * STAGE_SZ;
            const uint32_t abase = OFF_ABF + (t & 1) * A_STG;
            const float4 v0 = *reinterpret_cast<const float4*>(stg + f00);
            const float4 v1 = *reinterpret_cast<const float4*>(stg + f01);
            const float4 v2 = *reinterpret_cast<const float4*>(stg + f10);
            const float4 v3 = *reinterpret_cast<const float4*>(stg + f11);
            *reinterpret_cast<uint4*>(smem + abase + d0) = make_uint4(
                pack_half2(v0.x, v0.y), pack_half2(v0.z, v0.w),
                pack_half2(v1.x, v1.y), pack_half2(v1.z, v1.w));
            *reinterpret_cast<uint4*>(smem + abase + d1) = make_uint4(
                pack_half2(v2.x, v2.y), pack_half2(v2.z, v2.w),
                pack_half2(v3.x, v3.y), pack_half2(v3.z, v3.w));
        }
        __syncthreads();
        if (t + 2 < NSTAGES) load_stage(t + 2);

        mma_stage(sb + OFF_ABF + (t & 1) * A_STG, sb + (t % 3) * B_STG, OFF_BLO,
                  lane, warpM, warpN, acc);
    }

    // ---- epilogue: + bias, fp32 out, per-row partial (sum, ssq) ----
#pragma unroll
    for (int mt = 0; mt < 4; mt++) {
        const int rloc = warpM * 64 + mt * 16 + (lane >> 2);
        const size_t r0 = rowBase + rloc;
        float s0 = 0.f, q0 = 0.f, s1 = 0.f, q1 = 0.f;
#pragma unroll
        for (int nt = 0; nt < 4; nt++) {
            const int col = colBase + warpN * 32 + nt * 8 + (lane & 3) * 2;
            const float b0 = bias[col], b1 = bias[col + 1];
            float* c = acc[mt][nt];
            const float v00 = c[0] + b0, v01 = c[1] + b1;
            const float v10 = c[2] + b0, v11 = c[3] + b1;
            *reinterpret_cast<float2*>(C + r0 * 512 + col)       = make_float2(v00, v01);
            *reinterpret_cast<float2*>(C + (r0 + 8) * 512 + col) = make_float2(v10, v11);
            s0 += v00 + v01; q0 += v00 * v00 + v01 * v01;
            s1 += v10 + v11; q1 += v10 * v10 + v11 * v11;
        }
#pragma unroll
        for (int o = 1; o <= 2; o <<= 1) {
            s0 += __shfl_xor_sync(0xffffffffu, s0, o);
            q0 += __shfl_xor_sync(0xffffffffu, q0, o);
            s1 += __shfl_xor_sync(0xffffffffu, s1, o);
            q1 += __shfl_xor_sync(0xffffffffu, q1, o);
        }
        if ((lane & 3) == 0) {
            sred[warpN][rloc]     = make_float2(s0, q0);
            sred[warpN][rloc + 8] = make_float2(s1, q1);
        }
    }
    __syncthreads();
    if (tid < 128) {
        float s = 0.f, q = 0.f;
#pragma unroll
        for (int w = 0; w < 4; w++) { s += sred[w][tid].x; q += sred[w][tid].y; }
        gpart[(size_t)blockIdx.x * Mtot + rowBase + tid] = make_float2(s, q);
    }
}

// ---------------------------------------------------------------------------
// GEMM2 fused (R12-proven): a1 = celu_fast(LN1(h1raw)) fp16 in regs -> HMMA ->
// LN2 + celu_fast epilogue -> h2.
// ---------------------------------------------------------------------------
__global__ void __launch_bounds__(256, 2)
gemm2_fused_kernel(const float* __restrict__ h1raw, const float2* __restrict__ gpart,
                   const float* __restrict__ g1, const float* __restrict__ be1,
                   const __half* __restrict__ Bhi, const __half* __restrict__ Blo,
                   const float* __restrict__ b2, const float* __restrict__ g2,
                   const float* __restrict__ be2,
                   float* __restrict__ h2, int Mtot)
{
    constexpr int K = 512;
    constexpr int NSTAGES = K / 32;
    extern __shared__ char smem[];
    __shared__ float  smu[128], srstd[128];
    __shared__ float  sg1[512], sbe1[512];
    __shared__ float  sg2[128], sbe2[128], sb2[128];
    __shared__ float2 sred[4][128];
    const uint32_t sb = smem_u32(smem);

    const int tid   = threadIdx.x;
    const int lane  = tid & 31;
    const int wid   = tid >> 5;
    const int warpM = wid >> 2;
    const int warpN = wid & 3;
    const size_t rowBase = (size_t)blockIdx.x * 128;

    if (tid < 128) {
        float s = 0.f, q = 0.f;
#pragma unroll
        for (int b = 0; b < 4; b++) {
            float2 p = gpart[(size_t)b * Mtot + rowBase + tid];
            s += p.x; q += p.y;
        }
        const float mu = s * (1.f / 512.f);
        smu[tid]   = mu;
        srstd[tid] = rsqrtf(q * (1.f / 512.f) - mu * mu + 1e-5f);
        sg2[tid] = g2[tid]; sbe2[tid] = be2[tid]; sb2[tid] = b2[tid];
    }
#pragma unroll
    for (int i = tid; i < 512; i += 256) { sg1[i] = g1[i]; sbe1[i] = be1[i]; }
    __syncthreads();

    const int c0r = tid >> 2,  cq = tid & 3;
    const int c1r = 64 + c0r;
    const uint32_t d0 = swz(c0r, cq);
    const uint32_t d1 = swz(c1r, cq);

    const float* a0p = h1raw + (rowBase + c0r) * K + cq * 8;
    const float* a1p = h1raw + (rowBase + c1r) * K + cq * 8;
    const float mu0 = smu[c0r], rs0 = srstd[c0r];
    const float mu1 = smu[c1r], rs1 = srstd[c1r];

    float acc[4][4][4];
#pragma unroll
    for (int i = 0; i < 4; i++)
#pragma unroll
        for (int j = 0; j < 4; j++)
#pragma unroll
            for (int q = 0; q < 4; q++) acc[i][j][q] = 0.f;

    float4 fA[4];
    auto prefetchA = [&](int t) {
        fA[0] = *reinterpret_cast<const float4*>(a0p + t * 32);
        fA[1] = *reinterpret_cast<const float4*>(a0p + t * 32 + 4);
        fA[2] = *reinterpret_cast<const float4*>(a1p + t * 32);
        fA[3] = *reinterpret_cast<const float4*>(a1p + t * 32 + 4);
    };
    auto load_B = [&](int t) {
        const int k0 = t * 32;
        const uint32_t s = sb + (t % 3) * B_STG;
        const size_t g0 = (size_t)c0r * K + k0 + cq * 8;
        const size_t g1 = (size_t)c1r * K + k0 + cq * 8;
        cp_async16(s + d0,           Bhi + g0);
        cp_async16(s + d1,           Bhi + g1);
        cp_async16(s + OFF_BLO + d0, Blo + g0);
        cp_async16(s + OFF_BLO + d1, Blo + g1);
        CP_COMMIT();
    };

    prefetchA(0);
    load_B(0);
    load_B(1);

#pragma unroll 1
    for (int t = 0; t < NSTAGES; t++) {
        // convert A(t): affine-LN1 + fast-CELU + fp16 -> A ring buffer t%3
        {
            const uint32_t abase = OFF_A2 + (t % 3) * A_STG;
            const int kcol = t * 32 + cq * 8;
            uint32_t p[4];
#pragma unroll
            for (int j = 0; j < 2; j++) {
                const float* v = (j == 0) ? &fA[0].x : &fA[1].x;
#pragma unroll
                for (int e = 0; e < 2; e++) {
                    const int col = kcol + j * 4 + e * 2;
                    const float a0c = rs0 * sg1[col],     b0c = sbe1[col]     - mu0 * a0c;
                    const float a1c = rs0 * sg1[col + 1], b1c = sbe1[col + 1] - mu0 * a1c;
                    float y0 = celu_fast(v[2*e]   * a0c + b0c);
                    float y1 = celu_fast(v[2*e+1] * a1c + b1c);
                    p[2 * j + e] = pack_half2(y0, y1);
                }
            }
            *reinterpret_cast<uint4*>(smem + abase + d0) = make_uint4(p[0], p[1], p[2], p[3]);
#pragma unroll
            for (int j = 0; j < 2; j++) {
                const float* v = (j == 0) ? &fA[2].x : &fA[3].x;
#pragma unroll
                for (int e = 0; e < 2; e++) {
                    const int col = kcol + j * 4 + e * 2;
                    const float a0c = rs1 * sg1[col],     b0c = sbe1[col]     - mu1 * a0c;
                    const float a1c = rs1 * sg1[col + 1], b1c = sbe1[col + 1] - mu1 * a1c;
                    float y0 = celu_fast(v[2*e]   * a0c + b0c);
                    float y1 = celu_fast(v[2*e+1] * a1c + b1c);
                    p[2 * j + e] = pack_half2(y0, y1);
                }
            }
            *reinterpret_cast<uint4*>(smem + abase + d1) = make_uint4(p[0], p[1], p[2], p[3]);
        }
        if (t + 1 < NSTAGES) prefetchA(t + 1);
        if (t + 1 < NSTAGES) { CP_WAIT(1); } else { CP_WAIT(0); }
        __syncthreads();
        if (t + 2 < NSTAGES) load_B(t + 2);

        mma_stage(sb + OFF_A2 + (t % 3) * A_STG, sb + (t % 3) * B_STG, OFF_BLO,
                  lane, warpM, warpN, acc);
    }

    // ---- epilogue: bias2, LN2 over full rows, fast CELU -> h2 ----
#pragma unroll
    for (int mt = 0; mt < 4; mt++) {
        const int rloc = warpM * 64 + mt * 16 + (lane >> 2);
        float s0 = 0.f, q0 = 0.f, s1 = 0.f, q1 = 0.f;
#pragma unroll
        for (int nt = 0; nt < 4; nt++) {
            const int col = warpN * 32 + nt * 8 + (lane & 3) * 2;
            const float b0 = sb2[col], b1 = sb2[col + 1];
            float* c = acc[mt][nt];
            const float v00 = c[0] + b0, v01 = c[1] + b1;
            const float v10 = c[2] + b0, v11 = c[3] + b1;
            s0 += v00 + v01; q0 += v00 * v00 + v01 * v01;
            s1 += v10 + v11; q1 += v10 * v10 + v11 * v11;
        }
#pragma unroll
        for (int o = 1; o <= 2; o <<= 1) {
            s0 += __shfl_xor_sync(0xffffffffu, s0, o);
            q0 += __shfl_xor_sync(0xffffffffu, q0, o);
            s1 += __shfl_xor_sync(0xffffffffu, s1, o);
            q1 += __shfl_xor_sync(0xffffffffu, q1, o);
        }
        if ((lane & 3) == 0) {
            sred[warpN][rloc]     = make_float2(s0, q0);
            sred[warpN][rloc + 8] = make_float2(s1, q1);
        }
    }
    __syncthreads();
    if (tid < 128) {
        float s = 0.f, q = 0.f;
#pragma unroll
        for (int w = 0; w < 4; w++) { s += sred[w][tid].x; q += sred[w][tid].y; }
        const float mu = s * (1.f / 128.f);
        smu[tid]   = mu;
        srstd[tid] = rsqrtf(q * (1.f / 128.f) - mu * mu + 1e-5f);
    }
    __syncthreads();
#pragma unroll
    for (int mt = 0; mt < 4; mt++) {
        const int rloc = warpM * 64 + mt * 16 + (lane >> 2);
        const float m0 = smu[rloc],     r0s = srstd[rloc];
        const float m1 = smu[rloc + 8], r1s = srstd[rloc + 8];
        const size_t r0 = rowBase + rloc;
#pragma unroll
        for (int nt = 0; nt < 4; nt++) {
            const int col = warpN * 32 + nt * 8 + (lane & 3) * 2;
            const float b0 = sb2[col], b1 = sb2[col + 1];
            float* c = acc[mt][nt];
            float y00 = (c[0] + b0 - m0) * r0s * sg2[col]     + sbe2[col];
            float y01 = (c[1] + b1 - m0) * r0s * sg2[col + 1] + sbe2[col + 1];
            float y10 = (c[2] + b0 - m1) * r1s * sg2[col]     + sbe2[col];
            float y11 = (c[3] + b1 - m1) * r1s * sg2[col + 1] + sbe2[col + 1];
            *reinterpret_cast<float2*>(h2 + r0 * 128 + col) =
                make_float2(celu_fast(y00), celu_fast(y01));
            *reinterpret_cast<float2*>(h2 + (r0 + 8) * 128 + col) =
                make_float2(celu_fast(y10), celu_fast(y11));
        }
    }
}

// ---------------------------------------------------------------------------
// Tail: layer3 (128->32)+LN+CELU, layer4 (32->8)+LN+CELU, spectral-norm head.
// ---------------------------------------------------------------------------
__global__ void __launch_bounds__(256)
tail_kernel(const float* __restrict__ h2,
            const float* __restrict__ W3, const float* __restrict__ b3,
            const float* __restrict__ g3, const float* __restrict__ be3,
            const float* __restrict__ W4, const float* __restrict__ b4,
            const float* __restrict__ g4, const float* __restrict__ be4,
            const float* __restrict__ Wh, const float* __restrict__ bh,
            const float* __restrict__ u, float* __restrict__ out)
{
    __shared__ float sW3[32 * 128];
    __shared__ float sW4[8 * 32];
    const int tid = threadIdx.x;
    for (int i = tid; i < 32 * 128; i += 256) sW3[i] = W3[i];
    if (tid < 8 * 32) sW4[tid] = W4[tid];
    __syncthreads();

    const int lane = tid & 31;
    const size_t row = (size_t)blockIdx.x * 8 + (tid >> 5);
    const float* rp = h2 + row * 128;
    const float r0 = rp[lane], r1 = rp[lane + 32], r2 = rp[lane + 64], r3 = rp[lane + 96];

    float h3 = 0.f;
#pragma unroll
    for (int j = 0; j < 32; j++) {
        const float* w = sW3 + j * 128;
        float p = r0 * w[lane] + r1 * w[lane + 32] + r2 * w[lane + 64] + r3 * w[lane + 96];
        p = warp_sum(p);
        if (lane == j) h3 = p + b3[j];
    }
    float mu  = warp_sum(h3) * (1.f / 32.f);
    float d   = h3 - mu;
    float var = warp_sum(d * d) * (1.f / 32.f);
    float y3  = d * rsqrtf(var + 1e-5f) * g3[lane] + be3[lane];
    const float c3 = celu1(y3);

    float h4 = 0.f;
#pragma unroll
    for (int j = 0; j < 8; j++) {
        float p = warp_sum(c3 * sW4[j * 32 + lane]);
        if (lane == j) h4 = p + b4[j];
    }
    const bool act = (lane < 8);
    float hv = act ? h4 : 0.f;
    mu  = warp_sum(hv) * 0.125f;
    d   = act ? (h4 - mu) : 0.f;
    var = warp_sum(d * d) * 0.125f;
    float c4 = 0.f;
    if (act) {
        float y4 = d * rsqrtf(var + 1e-5f) * g4[lane] + be4[lane];
        c4 = celu1(y4);
    }

    const float wh  = act ? Wh[lane] : 0.f;
    const float nrm = sqrtf(warp_sum(wh * wh));
    const float u0  = u[0];
    const float vden = fabsf(u0) * nrm + 1e-12f;
    const float t    = u0 * nrm * nrm / vden;
    const float u2n  = t / (fabsf(t) + 1e-12f);
    const float sigma = u2n * t;

    float p = warp_sum(c4 * wh / sigma);
    if (lane == 0) out[row] = p + bh[0];
}

// ---------------------------------------------------------------------------
extern "C" void kernel_launch(void* const* d_in, const int* in_sizes, int n_in,
                              void* d_out, int out_size)
{
    const float* x   = (const float*)d_in[0];
    const float* W1  = (const float*)d_in[1];
    const float* b1  = (const float*)d_in[2];
    const float* g1  = (const float*)d_in[3];
    const float* be1 = (const float*)d_in[4];
    const float* W2  = (const float*)d_in[5];
    const float* b2  = (const float*)d_in[6];
    const float* g2  = (const float*)d_in[7];
    const float* be2 = (const float*)d_in[8];
    const float* W3  = (const float*)d_in[9];
    const float* b3  = (const float*)d_in[10];
    const float* g3  = (const float*)d_in[11];
    const float* be3 = (const float*)d_in[12];
    const float* W4  = (const float*)d_in[13];
    const float* b4  = (const float*)d_in[14];
    const float* g4  = (const float*)d_in[15];
    const float* be4 = (const float*)d_in[16];
    const float* Wh  = (const float*)d_in[17];
    const float* bh  = (const float*)d_in[18];
    const float* u   = (const float*)d_in[19];
    float* out = (float*)d_out;

    const int M = in_sizes[0] / 512;   // 131072

    __half *w1hi, *w1lo, *w2hi, *w2lo;
    float *h1raw, *h2;
    float2* part;
    cudaGetSymbolAddress((void**)&h1raw, g_h1raw);
    cudaGetSymbolAddress((void**)&h2,    g_h2);
    cudaGetSymbolAddress((void**)&part,  g_part);
    cudaGetSymbolAddress((void**)&w1hi,  g_w1hi);
    cudaGetSymbolAddress((void**)&w1lo,  g_w1lo);
    cudaGetSymbolAddress((void**)&w2hi,  g_w2hi);
    cudaGetSymbolAddress((void**)&w2lo,  g_w2lo);

    cudaFuncSetAttribute(gemm1_fused_kernel,
                         cudaFuncAttributeMaxDynamicSharedMemorySize, SMEM_G1);
    cudaFuncSetAttribute(gemm2_fused_kernel,
                         cudaFuncAttributeMaxDynamicSharedMemorySize, SMEM_G2);

    // Weight splits (both in one launch)
    const int n4w1 = 512 * 512 / 4, n4w2 = 128 * 512 / 4;
    wsplit2_kernel<<<(n4w1 + n4w2 + 255) / 256, 256>>>(
        W1, w1hi, w1lo, n4w1, W2, w2hi, w2lo, n4w2);

    // Layer 1: fused x->fp16 GEMM -> h1raw fp32 + LN partials
    gemm1_fused_kernel<<<dim3(4, M / 128), 256, SMEM_G1>>>(
        x, w1hi, w1lo, b1, h1raw, part, M);

    // Layer 2: fused LN1+CELU+fp16 -> GEMM -> LN2+CELU -> h2
    gemm2_fused_kernel<<<M / 128, 256, SMEM_G2>>>(
        h1raw, part, g1, be1, w2hi, w2lo, b2, g2, be2, h2, M);

    // Layers 3+4 + spectral-norm head
    tail_kernel<<<M / 8, 256>>>(h2, W3, b3, g3, be3, W4, b4, g4, be4, Wh, bh, u, out);
}

// round 14
// speedup vs baseline: 1.4332x; 1.0279x over previous
#include <cuda_runtime.h>
#include <cuda_fp16.h>
#include <cstdint>

// ---------------------------------------------------------------------------
// B=131072, chain 512 ->(W1)512 ->(W2)128 ->(W3)32 ->(W4)8 ->(Wh)1
// fp16 asymmetric-split HMMA (2 passes): W = Whi + Wlo; activations fp16.
// GEMM1: fused x->fp16 (cp.async staging -> convert -> tile), LN partials.
// GEMM2: fused LN1+fastCELU+fp16 -> HMMA -> LN2+fastCELU -> h2.
// tail:  output-stationary (transposed smem weights, float4 LDS, no big
//        shuffle reductions) - R13 profile showed the old form LDS/SHFL-bound.
// ---------------------------------------------------------------------------

#define BATCH 131072

__device__ __align__(256) float  g_h1raw[BATCH * 512];
__device__ __align__(256) float  g_h2   [BATCH * 128];
__device__ __align__(256) float2 g_part [4 * BATCH];
__device__ __align__(256) __half g_w1hi [512 * 512];
__device__ __align__(256) __half g_w1lo [512 * 512];
__device__ __align__(256) __half g_w2hi [128 * 512];
__device__ __align__(256) __half g_w2lo [128 * 512];

// ------------------------------ helpers ------------------------------------
__device__ __forceinline__ uint32_t smem_u32(const void* p) {
    uint32_t a;
    asm("{ .reg .u64 t; cvta.to.shared.u64 t, %1; cvt.u32.u64 %0, t; }"
        : "=r"(a) : "l"(p));
    return a;
}
__device__ __forceinline__ void cp_async16(uint32_t dst, const void* src) {
    asm volatile("cp.async.cg.shared.global [%0], [%1], 16;"
                 :: "r"(dst), "l"(src) : "memory");
}
#define CP_COMMIT() asm volatile("cp.async.commit_group;" ::: "memory")
#define CP_WAIT(n)  asm volatile("cp.async.wait_group %0;" :: "n"(n) : "memory")

__device__ __forceinline__ void ldmx4(uint32_t& r0, uint32_t& r1,
                                      uint32_t& r2, uint32_t& r3, uint32_t a) {
    asm volatile("ldmatrix.sync.aligned.m8n8.x4.shared.b16 {%0,%1,%2,%3}, [%4];"
                 : "=r"(r0), "=r"(r1), "=r"(r2), "=r"(r3) : "r"(a));
}
__device__ __forceinline__ void mma16816(float& c0, float& c1, float& c2, float& c3,
                                         uint32_t a0, uint32_t a1, uint32_t a2, uint32_t a3,
                                         uint32_t b0, uint32_t b1) {
    asm volatile("mma.sync.aligned.m16n8k16.row.col.f32.f16.f16.f32 "
                 "{%0,%1,%2,%3}, {%4,%5,%6,%7}, {%8,%9}, {%0,%1,%2,%3};"
                 : "+f"(c0), "+f"(c1), "+f"(c2), "+f"(c3)
                 : "r"(a0), "r"(a1), "r"(a2), "r"(a3), "r"(b0), "r"(b1));
}
__device__ __forceinline__ float warp_sum(float v) {
#pragma unroll
    for (int o = 16; o; o >>= 1) v += __shfl_xor_sync(0xffffffffu, v, o);
    return v;
}
// 8-wide reduce (works per 8-lane group; groups hold replicated data)
__device__ __forceinline__ float sum8(float v) {
#pragma unroll
    for (int o = 1; o <= 4; o <<= 1) v += __shfl_xor_sync(0xffffffffu, v, o);
    return v;
}
__device__ __forceinline__ uint32_t swz(uint32_t row, uint32_t q) {
    return row * 64 + (q ^ ((row & 6u) >> 1)) * 16;
}
__device__ __forceinline__ uint32_t swzf(uint32_t row, uint32_t q) {
    return row * 128 + (q ^ (row & 7u)) * 16;
}
__device__ __forceinline__ float celu_fast(float y) {
    return (y > 0.f) ? y : (__expf(y) - 1.f);
}
__device__ __forceinline__ uint32_t pack_half2(float a0, float a1) {
    __half2 t = __floats2half2_rn(a0, a1);
    return *reinterpret_cast<uint32_t*>(&t);
}
__device__ __forceinline__ void wsplit2(float a0, float a1, uint32_t& hp, uint32_t& lp) {
    __half h0 = __float2half_rn(a0), h1 = __float2half_rn(a1);
    __half2 hh; hh.x = h0; hh.y = h1;
    hp = *reinterpret_cast<uint32_t*>(&hh);
    lp = pack_half2(a0 - __half2float(h0), a1 - __half2float(h1));
}

// GEMM1 smem (98304): B ring 3x16K @0, fp32 staging 2x16K @49152, A 2x8K @81920
#define B_STG     16384
#define OFF_BLO   8192
#define OFF_STAGE 49152
#define STAGE_SZ  16384
#define OFF_ABF   81920
#define A_STG     8192
#define SMEM_G1   98304
// GEMM2 smem (73728): B ring 3x16K @0, A fp16 ring 3x8K @49152
#define OFF_A2    49152
#define SMEM_G2   73728

// ---------------------------------------------------------------------------
__global__ void __launch_bounds__(256)
wsplit2_kernel(const float* __restrict__ srcA, __half* __restrict__ hiA,
               __half* __restrict__ loA, int n4a,
               const float* __restrict__ srcB, __half* __restrict__ hiB,
               __half* __restrict__ loB, int n4b)
{
    int i = blockIdx.x * blockDim.x + threadIdx.x;
    const float* src; __half *hi, *lo;
    if (i < n4a) { src = srcA; hi = hiA; lo = loA; }
    else {
        i -= n4a;
        if (i >= n4b) return;
        src = srcB; hi = hiB; lo = loB;
    }
    float4 v = reinterpret_cast<const float4*>(src)[i];
    uint32_t h0, l0, h1, l1;
    wsplit2(v.x, v.y, h0, l0);
    wsplit2(v.z, v.w, h1, l1);
    reinterpret_cast<uint32_t*>(hi)[2 * i]     = h0;
    reinterpret_cast<uint32_t*>(hi)[2 * i + 1] = h1;
    reinterpret_cast<uint32_t*>(lo)[2 * i]     = l0;
    reinterpret_cast<uint32_t*>(lo)[2 * i + 1] = l1;
}

// ---------------------------------------------------------------------------
__device__ __forceinline__ void mma_stage(uint32_t sa, uint32_t sbB, uint32_t blo_off,
                                          int lane, int warpM, int warpN,
                                          float acc[4][4][4])
{
#pragma unroll
    for (int ks = 0; ks < 2; ks++) {
        uint32_t a[4][4];
        const uint32_t arow = warpM * 64 + (lane & 15);
        const uint32_t aq   = ks * 2 + (lane >> 4);
#pragma unroll
        for (int mt = 0; mt < 4; mt++) {
            const uint32_t adr = sa + swz(arow + mt * 16, aq);
            ldmx4(a[mt][0], a[mt][1], a[mt][2], a[mt][3], adr);
        }
        const uint32_t brow0 = warpN * 32 + (lane & 7) + ((lane >> 4) & 1) * 8;
        const uint32_t bq    = ks * 2 + ((lane >> 3) & 1);
#pragma unroll
        for (int pr = 0; pr < 2; pr++) {
            uint32_t bh0, bh1, bh2, bh3, bl0, bl1, bl2, bl3;
            const uint32_t adr = sbB + swz(brow0 + pr * 16, bq);
            ldmx4(bh0, bh1, bh2, bh3, adr);
            ldmx4(bl0, bl1, bl2, bl3, adr + blo_off);
#pragma unroll
            for (int mt = 0; mt < 4; mt++) {
                float* c0 = acc[mt][2 * pr];
                mma16816(c0[0], c0[1], c0[2], c0[3],
                         a[mt][0], a[mt][1], a[mt][2], a[mt][3], bh0, bh1);
                mma16816(c0[0], c0[1], c0[2], c0[3],
                         a[mt][0], a[mt][1], a[mt][2], a[mt][3], bl0, bl1);
                float* c1 = acc[mt][2 * pr + 1];
                mma16816(c1[0], c1[1], c1[2], c1[3],
                         a[mt][0], a[mt][1], a[mt][2], a[mt][3], bh2, bh3);
                mma16816(c1[0], c1[1], c1[2], c1[3],
                         a[mt][0], a[mt][1], a[mt][2], a[mt][3], bl2, bl3);
            }
        }
    }
}

// ---------------------------------------------------------------------------
// GEMM1 fused-xcvt (R13-proven).
// ---------------------------------------------------------------------------
__global__ void __launch_bounds__(256, 2)
gemm1_fused_kernel(const float* __restrict__ X,
                   const __half* __restrict__ Bhi, const __half* __restrict__ Blo,
                   const float* __restrict__ bias, float* __restrict__ C,
                   float2* __restrict__ gpart, int Mtot)
{
    constexpr int K = 512;
    constexpr int NSTAGES = K / 32;
    extern __shared__ char smem[];
    __shared__ float2 sred[4][128];
    const uint32_t sb = smem_u32(smem);

    const int tid   = threadIdx.x;
    const int lane  = tid & 31;
    const int wid   = tid >> 5;
    const int warpM = wid >> 2;
    const int warpN = wid & 3;
    const size_t rowBase = (size_t)blockIdx.y * 128;
    const int    colBase = blockIdx.x * 128;

    const int c0r = tid >> 2,  cq = tid & 3;
    const int c1r = 64 + c0r;
    const uint32_t d0 = swz(c0r, cq);
    const uint32_t d1 = swz(c1r, cq);
    const uint32_t f00 = swzf(c0r, 2 * cq), f01 = swzf(c0r, 2 * cq + 1);
    const uint32_t f10 = swzf(c1r, 2 * cq), f11 = swzf(c1r, 2 * cq + 1);
    const float* x0p = X + (rowBase + c0r) * K + cq * 8;
    const float* x1p = X + (rowBase + c1r) * K + cq * 8;

    float acc[4][4][4];
#pragma unroll
    for (int i = 0; i < 4; i++)
#pragma unroll
        for (int j = 0; j < 4; j++)
#pragma unroll
            for (int q = 0; q < 4; q++) acc[i][j][q] = 0.f;

    auto load_stage = [&](int t) {
        const int k0 = t * 32;
        const uint32_t sA = sb + OFF_STAGE + (t & 1) * STAGE_SZ;
        cp_async16(sA + f00, x0p + k0);
        cp_async16(sA + f01, x0p + k0 + 4);
        cp_async16(sA + f10, x1p + k0);
        cp_async16(sA + f11, x1p + k0 + 4);
        const uint32_t sB = sb + (t % 3) * B_STG;
        const size_t g0 = (size_t)(colBase + c0r) * K + k0 + cq * 8;
        const size_t g1 = (size_t)(colBase + c1r) * K + k0 + cq * 8;
        cp_async16(sB + d0,           Bhi + g0);
        cp_async16(sB + d1,           Bhi + g1);
        cp_async16(sB + OFF_BLO + d0, Blo + g0);
        cp_async16(sB + OFF_BLO + d1, Blo + g1);
        CP_COMMIT();
    };

    load_stage(0);
    load_stage(1);

#pragma unroll 1
    for (int t = 0; t < NSTAGES; t++) {
        if (t + 1 < NSTAGES) { CP_WAIT(1); } else { CP_WAIT(0); }
        {
            const char* stg = smem + OFF_STAGE + (t & 1) * STAGE_SZ;
            const uint32_t abase = OFF_ABF + (t & 1) * A_STG;
            const float4 v0 = *reinterpret_cast<const float4*>(stg + f00);
            const float4 v1 = *reinterpret_cast<const float4*>(stg + f01);
            const float4 v2 = *reinterpret_cast<const float4*>(stg + f10);
            const float4 v3 = *reinterpret_cast<const float4*>(stg + f11);
            *reinterpret_cast<uint4*>(smem + abase + d0) = make_uint4(
                pack_half2(v0.x, v0.y), pack_half2(v0.z, v0.w),
                pack_half2(v1.x, v1.y), pack_half2(v1.z, v1.w));
            *reinterpret_cast<uint4*>(smem + abase + d1) = make_uint4(
                pack_half2(v2.x, v2.y), pack_half2(v2.z, v2.w),
                pack_half2(v3.x, v3.y), pack_half2(v3.z, v3.w));
        }
        __syncthreads();
        if (t + 2 < NSTAGES) load_stage(t + 2);

        mma_stage(sb + OFF_ABF + (t & 1) * A_STG, sb + (t % 3) * B_STG, OFF_BLO,
                  lane, warpM, warpN, acc);
    }

#pragma unroll
    for (int mt = 0; mt < 4; mt++) {
        const int rloc = warpM * 64 + mt * 16 + (lane >> 2);
        const size_t r0 = rowBase + rloc;
        float s0 = 0.f, q0 = 0.f, s1 = 0.f, q1 = 0.f;
#pragma unroll
        for (int nt = 0; nt < 4; nt++) {
            const int col = colBase + warpN * 32 + nt * 8 + (lane & 3) * 2;
            const float b0 = bias[col], b1 = bias[col + 1];
            float* c = acc[mt][nt];
            const float v00 = c[0] + b0, v01 = c[1] + b1;
            const float v10 = c[2] + b0, v11 = c[3] + b1;
            *reinterpret_cast<float2*>(C + r0 * 512 + col)       = make_float2(v00, v01);
            *reinterpret_cast<float2*>(C + (r0 + 8) * 512 + col) = make_float2(v10, v11);
            s0 += v00 + v01; q0 += v00 * v00 + v01 * v01;
            s1 += v10 + v11; q1 += v10 * v10 + v11 * v11;
        }
#pragma unroll
        for (int o = 1; o <= 2; o <<= 1) {
            s0 += __shfl_xor_sync(0xffffffffu, s0, o);
            q0 += __shfl_xor_sync(0xffffffffu, q0, o);
            s1 += __shfl_xor_sync(0xffffffffu, s1, o);
            q1 += __shfl_xor_sync(0xffffffffu, q1, o);
        }
        if ((lane & 3) == 0) {
            sred[warpN][rloc]     = make_float2(s0, q0);
            sred[warpN][rloc + 8] = make_float2(s1, q1);
        }
    }
    __syncthreads();
    if (tid < 128) {
        float s = 0.f, q = 0.f;
#pragma unroll
        for (int w = 0; w < 4; w++) { s += sred[w][tid].x; q += sred[w][tid].y; }
        gpart[(size_t)blockIdx.x * Mtot + rowBase + tid] = make_float2(s, q);
    }
}

// ---------------------------------------------------------------------------
// GEMM2 fused (R12/R13-proven).
// ---------------------------------------------------------------------------
__global__ void __launch_bounds__(256, 2)
gemm2_fused_kernel(const float* __restrict__ h1raw, const float2* __restrict__ gpart,
                   const float* __restrict__ g1, const float* __restrict__ be1,
                   const __half* __restrict__ Bhi, const __half* __restrict__ Blo,
                   const float* __restrict__ b2, const float* __restrict__ g2,
                   const float* __restrict__ be2,
                   float* __restrict__ h2, int Mtot)
{
    constexpr int K = 512;
    constexpr int NSTAGES = K / 32;
    extern __shared__ char smem[];
    __shared__ float  smu[128], srstd[128];
    __shared__ float  sg1[512], sbe1[512];
    __shared__ float  sg2[128], sbe2[128], sb2[128];
    __shared__ float2 sred[4][128];
    const uint32_t sb = smem_u32(smem);

    const int tid   = threadIdx.x;
    const int lane  = tid & 31;
    const int wid   = tid >> 5;
    const int warpM = wid >> 2;
    const int warpN = wid & 3;
    const size_t rowBase = (size_t)blockIdx.x * 128;

    if (tid < 128) {
        float s = 0.f, q = 0.f;
#pragma unroll
        for (int b = 0; b < 4; b++) {
            float2 p = gpart[(size_t)b * Mtot + rowBase + tid];
            s += p.x; q += p.y;
        }
        const float mu = s * (1.f / 512.f);
        smu[tid]   = mu;
        srstd[tid] = rsqrtf(q * (1.f / 512.f) - mu * mu + 1e-5f);
        sg2[tid] = g2[tid]; sbe2[tid] = be2[tid]; sb2[tid] = b2[tid];
    }
#pragma unroll
    for (int i = tid; i < 512; i += 256) { sg1[i] = g1[i]; sbe1[i] = be1[i]; }
    __syncthreads();

    const int c0r = tid >> 2,  cq = tid & 3;
    const int c1r = 64 + c0r;
    const uint32_t d0 = swz(c0r, cq);
    const uint32_t d1 = swz(c1r, cq);

    const float* a0p = h1raw + (rowBase + c0r) * K + cq * 8;
    const float* a1p = h1raw + (rowBase + c1r) * K + cq * 8;
    const float mu0 = smu[c0r], rs0 = srstd[c0r];
    const float mu1 = smu[c1r], rs1 = srstd[c1r];

    float acc[4][4][4];
#pragma unroll
    for (int i = 0; i < 4; i++)
#pragma unroll
        for (int j = 0; j < 4; j++)
#pragma unroll
            for (int q = 0; q < 4; q++) acc[i][j][q] = 0.f;

    float4 fA[4];
    auto prefetchA = [&](int t) {
        fA[0] = *reinterpret_cast<const float4*>(a0p + t * 32);
        fA[1] = *reinterpret_cast<const float4*>(a0p + t * 32 + 4);
        fA[2] = *reinterpret_cast<const float4*>(a1p + t * 32);
        fA[3] = *reinterpret_cast<const float4*>(a1p + t * 32 + 4);
    };
    auto load_B = [&](int t) {
        const int k0 = t * 32;
        const uint32_t s = sb + (t % 3) * B_STG;
        const size_t g0 = (size_t)c0r * K + k0 + cq * 8;
        const size_t g1 = (size_t)c1r * K + k0 + cq * 8;
        cp_async16(s + d0,           Bhi + g0);
        cp_async16(s + d1,           Bhi + g1);
        cp_async16(s + OFF_BLO + d0, Blo + g0);
        cp_async16(s + OFF_BLO + d1, Blo + g1);
        CP_COMMIT();
    };

    prefetchA(0);
    load_B(0);
    load_B(1);

#pragma unroll 1
    for (int t = 0; t < NSTAGES; t++) {
        {
            const uint32_t abase = OFF_A2 + (t % 3) * A_STG;
            const int kcol = t * 32 + cq * 8;
            uint32_t p[4];
#pragma unroll
            for (int j = 0; j < 2; j++) {
                const float* v = (j == 0) ? &fA[0].x : &fA[1].x;
#pragma unroll
                for (int e = 0; e < 2; e++) {
                    const int col = kcol + j * 4 + e * 2;
                    const float a0c = rs0 * sg1[col],     b0c = sbe1[col]     - mu0 * a0c;
                    const float a1c = rs0 * sg1[col + 1], b1c = sbe1[col + 1] - mu0 * a1c;
                    float y0 = celu_fast(v[2*e]   * a0c + b0c);
                    float y1 = celu_fast(v[2*e+1] * a1c + b1c);
                    p[2 * j + e] = pack_half2(y0, y1);
                }
            }
            *reinterpret_cast<uint4*>(smem + abase + d0) = make_uint4(p[0], p[1], p[2], p[3]);
#pragma unroll
            for (int j = 0; j < 2; j++) {
                const float* v = (j == 0) ? &fA[2].x : &fA[3].x;
#pragma unroll
                for (int e = 0; e < 2; e++) {
                    const int col = kcol + j * 4 + e * 2;
                    const float a0c = rs1 * sg1[col],     b0c = sbe1[col]     - mu1 * a0c;
                    const float a1c = rs1 * sg1[col + 1], b1c = sbe1[col + 1] - mu1 * a1c;
                    float y0 = celu_fast(v[2*e]   * a0c + b0c);
                    float y1 = celu_fast(v[2*e+1] * a1c + b1c);
                    p[2 * j + e] = pack_half2(y0, y1);
                }
            }
            *reinterpret_cast<uint4*>(smem + abase + d1) = make_uint4(p[0], p[1], p[2], p[3]);
        }
        if (t + 1 < NSTAGES) prefetchA(t + 1);
        if (t + 1 < NSTAGES) { CP_WAIT(1); } else { CP_WAIT(0); }
        __syncthreads();
        if (t + 2 < NSTAGES) load_B(t + 2);

        mma_stage(sb + OFF_A2 + (t % 3) * A_STG, sb + (t % 3) * B_STG, OFF_BLO,
                  lane, warpM, warpN, acc);
    }

#pragma unroll
    for (int mt = 0; mt < 4; mt++) {
        const int rloc = warpM * 64 + mt * 16 + (lane >> 2);
        float s0 = 0.f, q0 = 0.f, s1 = 0.f, q1 = 0.f;
#pragma unroll
        for (int nt = 0; nt < 4; nt++) {
            const int col = warpN * 32 + nt * 8 + (lane & 3) * 2;
            const float b0 = sb2[col], b1 = sb2[col + 1];
            float* c = acc[mt][nt];
            const float v00 = c[0] + b0, v01 = c[1] + b1;
            const float v10 = c[2] + b0, v11 = c[3] + b1;
            s0 += v00 + v01; q0 += v00 * v00 + v01 * v01;
            s1 += v10 + v11; q1 += v10 * v10 + v11 * v11;
        }
#pragma unroll
        for (int o = 1; o <= 2; o <<= 1) {
            s0 += __shfl_xor_sync(0xffffffffu, s0, o);
            q0 += __shfl_xor_sync(0xffffffffu, q0, o);
            s1 += __shfl_xor_sync(0xffffffffu, s1, o);
            q1 += __shfl_xor_sync(0xffffffffu, q1, o);
        }
        if ((lane & 3) == 0) {
            sred[warpN][rloc]     = make_float2(s0, q0);
            sred[warpN][rloc + 8] = make_float2(s1, q1);
        }
    }
    __syncthreads();
    if (tid < 128) {
        float s = 0.f, q = 0.f;
#pragma unroll
        for (int w = 0; w < 4; w++) { s += sred[w][tid].x; q += sred[w][tid].y; }
        const float mu = s * (1.f / 128.f);
        smu[tid]   = mu;
        srstd[tid] = rsqrtf(q * (1.f / 128.f) - mu * mu + 1e-5f);
    }
    __syncthreads();
#pragma unroll
    for (int mt = 0; mt < 4; mt++) {
        const int rloc = warpM * 64 + mt * 16 + (lane >> 2);
        const float m0 = smu[rloc],     r0s = srstd[rloc];
        const float m1 = smu[rloc + 8], r1s = srstd[rloc + 8];
        const size_t r0 = rowBase + rloc;
#pragma unroll
        for (int nt = 0; nt < 4; nt++) {
            const int col = warpN * 32 + nt * 8 + (lane & 3) * 2;
            const float b0 = sb2[col], b1 = sb2[col + 1];
            float* c = acc[mt][nt];
            float y00 = (c[0] + b0 - m0) * r0s * sg2[col]     + sbe2[col];
            float y01 = (c[1] + b1 - m0) * r0s * sg2[col + 1] + sbe2[col + 1];
            float y10 = (c[2] + b0 - m1) * r1s * sg2[col]     + sbe2[col];
            float y11 = (c[3] + b1 - m1) * r1s * sg2[col + 1] + sbe2[col + 1];
            *reinterpret_cast<float2*>(h2 + r0 * 128 + col) =
                make_float2(celu_fast(y00), celu_fast(y01));
            *reinterpret_cast<float2*>(h2 + (r0 + 8) * 128 + col) =
                make_float2(celu_fast(y10), celu_fast(y11));
        }
    }
}

// ---------------------------------------------------------------------------
// Tail (rewritten, output-stationary):
//  layer3: lane j owns output j; W3 transposed in smem as float4 [kg][j];
//          row staged once per warp -> 64 LDS.128 + 128 FMA, no shuffles.
//  layer4: lanes replicated x4 over 8 outputs, float4 reads.
//  LN(32) via warp_sum; LN(8)/head via 3-level shfl_xor within 8-groups.
// ---------------------------------------------------------------------------
__global__ void __launch_bounds__(256)
tail_kernel(const float* __restrict__ h2,
            const float* __restrict__ W3, const float* __restrict__ b3,
            const float* __restrict__ g3, const float* __restrict__ be3,
            const float* __restrict__ W4, const float* __restrict__ b4,
            const float* __restrict__ g4, const float* __restrict__ be4,
            const float* __restrict__ Wh, const float* __restrict__ bh,
            const float* __restrict__ u, float* __restrict__ out)
{
    __shared__ __align__(16) float4 sW3T[32 * 32];   // [kg][j] = W3[j][4kg..4kg+3]
    __shared__ __align__(16) float4 sW4T[8 * 8];     // [kg][j] = W4[j][4kg..4kg+3]
    __shared__ __align__(16) float  srow[8][128];    // per-warp row buffer

    const int tid = threadIdx.x;
    for (int idx = tid; idx < 1024; idx += 256) {
        const int kg = idx >> 5, j = idx & 31;
        sW3T[idx] = *reinterpret_cast<const float4*>(W3 + j * 128 + kg * 4);
    }
    if (tid < 64) {
        const int kg = tid >> 3, j = tid & 7;
        sW4T[tid] = *reinterpret_cast<const float4*>(W4 + j * 32 + kg * 4);
    }
    __syncthreads();

    const int lane = tid & 31;
    const int w    = tid >> 5;
    const size_t row = (size_t)blockIdx.x * 8 + w;
    const float* rp = h2 + row * 128;

    // stage row into per-warp smem buffer
    srow[w][lane]      = rp[lane];
    srow[w][lane + 32] = rp[lane + 32];
    srow[w][lane + 64] = rp[lane + 64];
    srow[w][lane + 96] = rp[lane + 96];
    __syncwarp();
    const float4* s4 = reinterpret_cast<const float4*>(srow[w]);

    // layer3: h3[lane]
    float h3 = 0.f;
#pragma unroll
    for (int kg = 0; kg < 32; kg++) {
        const float4 wv = sW3T[kg * 32 + lane];
        const float4 sv = s4[kg];                 // broadcast
        h3 += sv.x * wv.x + sv.y * wv.y + sv.z * wv.z + sv.w * wv.w;
    }
    h3 += b3[lane];

    // LN(32) + celu
    float mu  = warp_sum(h3) * (1.f / 32.f);
    float d   = h3 - mu;
    float var = warp_sum(d * d) * (1.f / 32.f);
    float y3  = d * rsqrtf(var + 1e-5f) * g3[lane] + be3[lane];
    const float c3 = celu_fast(y3);

    // stage c3, layer4 (lanes replicated x4 over 8 outputs)
    __syncwarp();
    srow[w][lane] = c3;
    __syncwarp();
    const int j8 = lane & 7;
    float h4 = 0.f;
#pragma unroll
    for (int kg = 0; kg < 8; kg++) {
        const float4 wv = sW4T[kg * 8 + j8];
        const float4 sv = s4[kg];                 // c3 values, broadcast
        h4 += sv.x * wv.x + sv.y * wv.y + sv.z * wv.z + sv.w * wv.w;
    }
    h4 += b4[j8];

    // LN(8) + celu (8-group reductions; every group holds all 8 outputs)
    mu  = sum8(h4) * 0.125f;
    d   = h4 - mu;
    var = sum8(d * d) * 0.125f;
    float y4 = d * rsqrtf(var + 1e-5f) * g4[j8] + be4[j8];
    const float c4 = celu_fast(y4);

    // spectral-norm head (eps-faithful sigma)
    const float wh   = Wh[j8];
    const float nrm  = sqrtf(sum8(wh * wh));
    const float u0   = u[0];
    const float vden = fabsf(u0) * nrm + 1e-12f;
    const float t    = u0 * nrm * nrm / vden;
    const float u2n  = t / (fabsf(t) + 1e-12f);
    const float sigma = u2n * t;

    const float p = sum8(c4 * wh / sigma);
    if (lane == 0) out[row] = p + bh[0];
}

// ---------------------------------------------------------------------------
extern "C" void kernel_launch(void* const* d_in, const int* in_sizes, int n_in,
                              void* d_out, int out_size)
{
    const float* x   = (const float*)d_in[0];
    const float* W1  = (const float*)d_in[1];
    const float* b1  = (const float*)d_in[2];
    const float* g1  = (const float*)d_in[3];
    const float* be1 = (const float*)d_in[4];
    const float* W2  = (const float*)d_in[5];
    const float* b2  = (const float*)d_in[6];
    const float* g2  = (const float*)d_in[7];
    const float* be2 = (const float*)d_in[8];
    const float* W3  = (const float*)d_in[9];
    const float* b3  = (const float*)d_in[10];
    const float* g3  = (const float*)d_in[11];
    const float* be3 = (const float*)d_in[12];
    const float* W4  = (const float*)d_in[13];
    const float* b4  = (const float*)d_in[14];
    const float* g4  = (const float*)d_in[15];
    const float* be4 = (const float*)d_in[16];
    const float* Wh  = (const float*)d_in[17];
    const float* bh  = (const float*)d_in[18];
    const float* u   = (const float*)d_in[19];
    float* out = (float*)d_out;

    const int M = in_sizes[0] / 512;   // 131072

    __half *w1hi, *w1lo, *w2hi, *w2lo;
    float *h1raw, *h2;
    float2* part;
    cudaGetSymbolAddress((void**)&h1raw, g_h1raw);
    cudaGetSymbolAddress((void**)&h2,    g_h2);
    cudaGetSymbolAddress((void**)&part,  g_part);
    cudaGetSymbolAddress((void**)&w1hi,  g_w1hi);
    cudaGetSymbolAddress((void**)&w1lo,  g_w1lo);
    cudaGetSymbolAddress((void**)&w2hi,  g_w2hi);
    cudaGetSymbolAddress((void**)&w2lo,  g_w2lo);

    cudaFuncSetAttribute(gemm1_fused_kernel,
                         cudaFuncAttributeMaxDynamicSharedMemorySize, SMEM_G1);
    cudaFuncSetAttribute(gemm2_fused_kernel,
                         cudaFuncAttributeMaxDynamicSharedMemorySize, SMEM_G2);

    const int n4w1 = 512 * 512 / 4, n4w2 = 128 * 512 / 4;
    wsplit2_kernel<<<(n4w1 + n4w2 + 255) / 256, 256>>>(
        W1, w1hi, w1lo, n4w1, W2, w2hi, w2lo, n4w2);

    gemm1_fused_kernel<<<dim3(4, M / 128), 256, SMEM_G1>>>(
        x, w1hi, w1lo, b1, h1raw, part, M);

    gemm2_fused_kernel<<<M / 128, 256, SMEM_G2>>>(
        h1raw, part, g1, be1, w2hi, w2lo, b2, g2, be2, h2, M);

    tail_kernel<<<M / 8, 256>>>(h2, W3, b3, g3, be3, W4, b4, g4, be4, Wh, bh, u, out);
}

// round 15
// speedup vs baseline: 1.6830x; 1.1743x over previous
#include <cuda_runtime.h>
#include <cuda_fp16.h>
#include <cstdint>

// ---------------------------------------------------------------------------
// B=131072, chain 512 ->(W1)512 ->(W2)128 ->(W3)32 ->(W4)8 ->(Wh)1
// fp16 asymmetric-split HMMA (2 passes): W = Whi + Wlo; activations fp16.
// GEMM1: fused x->fp16 (cp.async staging -> convert -> tile), LN partials.
// GEMM2: fused LN1+fastCELU+fp16 -> HMMA -> LN2+fastCELU -> h2.
// tail:  output-stationary, 4 rows/warp per weight fetch (R14 profile showed
//        the 1-row form saturates the smem crossbar re-reading W3 per row).
// ---------------------------------------------------------------------------

#define BATCH 131072

__device__ __align__(256) float  g_h1raw[BATCH * 512];
__device__ __align__(256) float  g_h2   [BATCH * 128];
__device__ __align__(256) float2 g_part [4 * BATCH];
__device__ __align__(256) __half g_w1hi [512 * 512];
__device__ __align__(256) __half g_w1lo [512 * 512];
__device__ __align__(256) __half g_w2hi [128 * 512];
__device__ __align__(256) __half g_w2lo [128 * 512];

// ------------------------------ helpers ------------------------------------
__device__ __forceinline__ uint32_t smem_u32(const void* p) {
    uint32_t a;
    asm("{ .reg .u64 t; cvta.to.shared.u64 t, %1; cvt.u32.u64 %0, t; }"
        : "=r"(a) : "l"(p));
    return a;
}
__device__ __forceinline__ void cp_async16(uint32_t dst, const void* src) {
    asm volatile("cp.async.cg.shared.global [%0], [%1], 16;"
                 :: "r"(dst), "l"(src) : "memory");
}
#define CP_COMMIT() asm volatile("cp.async.commit_group;" ::: "memory")
#define CP_WAIT(n)  asm volatile("cp.async.wait_group %0;" :: "n"(n) : "memory")

__device__ __forceinline__ void ldmx4(uint32_t& r0, uint32_t& r1,
                                      uint32_t& r2, uint32_t& r3, uint32_t a) {
    asm volatile("ldmatrix.sync.aligned.m8n8.x4.shared.b16 {%0,%1,%2,%3}, [%4];"
                 : "=r"(r0), "=r"(r1), "=r"(r2), "=r"(r3) : "r"(a));
}
__device__ __forceinline__ void mma16816(float& c0, float& c1, float& c2, float& c3,
                                         uint32_t a0, uint32_t a1, uint32_t a2, uint32_t a3,
                                         uint32_t b0, uint32_t b1) {
    asm volatile("mma.sync.aligned.m16n8k16.row.col.f32.f16.f16.f32 "
                 "{%0,%1,%2,%3}, {%4,%5,%6,%7}, {%8,%9}, {%0,%1,%2,%3};"
                 : "+f"(c0), "+f"(c1), "+f"(c2), "+f"(c3)
                 : "r"(a0), "r"(a1), "r"(a2), "r"(a3), "r"(b0), "r"(b1));
}
__device__ __forceinline__ float warp_sum(float v) {
#pragma unroll
    for (int o = 16; o; o >>= 1) v += __shfl_xor_sync(0xffffffffu, v, o);
    return v;
}
__device__ __forceinline__ float sum8(float v) {
#pragma unroll
    for (int o = 1; o <= 4; o <<= 1) v += __shfl_xor_sync(0xffffffffu, v, o);
    return v;
}
__device__ __forceinline__ uint32_t swz(uint32_t row, uint32_t q) {
    return row * 64 + (q ^ ((row & 6u) >> 1)) * 16;
}
__device__ __forceinline__ uint32_t swzf(uint32_t row, uint32_t q) {
    return row * 128 + (q ^ (row & 7u)) * 16;
}
__device__ __forceinline__ float celu_fast(float y) {
    return (y > 0.f) ? y : (__expf(y) - 1.f);
}
__device__ __forceinline__ uint32_t pack_half2(float a0, float a1) {
    __half2 t = __floats2half2_rn(a0, a1);
    return *reinterpret_cast<uint32_t*>(&t);
}
__device__ __forceinline__ void wsplit2(float a0, float a1, uint32_t& hp, uint32_t& lp) {
    __half h0 = __float2half_rn(a0), h1 = __float2half_rn(a1);
    __half2 hh; hh.x = h0; hh.y = h1;
    hp = *reinterpret_cast<uint32_t*>(&hh);
    lp = pack_half2(a0 - __half2float(h0), a1 - __half2float(h1));
}

// GEMM1 smem (98304): B ring 3x16K @0, fp32 staging 2x16K @49152, A 2x8K @81920
#define B_STG     16384
#define OFF_BLO   8192
#define OFF_STAGE 49152
#define STAGE_SZ  16384
#define OFF_ABF   81920
#define A_STG     8192
#define SMEM_G1   98304
// GEMM2 smem (73728): B ring 3x16K @0, A fp16 ring 3x8K @49152
#define OFF_A2    49152
#define SMEM_G2   73728

// ---------------------------------------------------------------------------
__global__ void __launch_bounds__(256)
wsplit2_kernel(const float* __restrict__ srcA, __half* __restrict__ hiA,
               __half* __restrict__ loA, int n4a,
               const float* __restrict__ srcB, __half* __restrict__ hiB,
               __half* __restrict__ loB, int n4b)
{
    int i = blockIdx.x * blockDim.x + threadIdx.x;
    const float* src; __half *hi, *lo;
    if (i < n4a) { src = srcA; hi = hiA; lo = loA; }
    else {
        i -= n4a;
        if (i >= n4b) return;
        src = srcB; hi = hiB; lo = loB;
    }
    float4 v = reinterpret_cast<const float4*>(src)[i];
    uint32_t h0, l0, h1, l1;
    wsplit2(v.x, v.y, h0, l0);
    wsplit2(v.z, v.w, h1, l1);
    reinterpret_cast<uint32_t*>(hi)[2 * i]     = h0;
    reinterpret_cast<uint32_t*>(hi)[2 * i + 1] = h1;
    reinterpret_cast<uint32_t*>(lo)[2 * i]     = l0;
    reinterpret_cast<uint32_t*>(lo)[2 * i + 1] = l1;
}

// ---------------------------------------------------------------------------
__device__ __forceinline__ void mma_stage(uint32_t sa, uint32_t sbB, uint32_t blo_off,
                                          int lane, int warpM, int warpN,
                                          float acc[4][4][4])
{
#pragma unroll
    for (int ks = 0; ks < 2; ks++) {
        uint32_t a[4][4];
        const uint32_t arow = warpM * 64 + (lane & 15);
        const uint32_t aq   = ks * 2 + (lane >> 4);
#pragma unroll
        for (int mt = 0; mt < 4; mt++) {
            const uint32_t adr = sa + swz(arow + mt * 16, aq);
            ldmx4(a[mt][0], a[mt][1], a[mt][2], a[mt][3], adr);
        }
        const uint32_t brow0 = warpN * 32 + (lane & 7) + ((lane >> 4) & 1) * 8;
        const uint32_t bq    = ks * 2 + ((lane >> 3) & 1);
#pragma unroll
        for (int pr = 0; pr < 2; pr++) {
            uint32_t bh0, bh1, bh2, bh3, bl0, bl1, bl2, bl3;
            const uint32_t adr = sbB + swz(brow0 + pr * 16, bq);
            ldmx4(bh0, bh1, bh2, bh3, adr);
            ldmx4(bl0, bl1, bl2, bl3, adr + blo_off);
#pragma unroll
            for (int mt = 0; mt < 4; mt++) {
                float* c0 = acc[mt][2 * pr];
                mma16816(c0[0], c0[1], c0[2], c0[3],
                         a[mt][0], a[mt][1], a[mt][2], a[mt][3], bh0, bh1);
                mma16816(c0[0], c0[1], c0[2], c0[3],
                         a[mt][0], a[mt][1], a[mt][2], a[mt][3], bl0, bl1);
                float* c1 = acc[mt][2 * pr + 1];
                mma16816(c1[0], c1[1], c1[2], c1[3],
                         a[mt][0], a[mt][1], a[mt][2], a[mt][3], bh2, bh3);
                mma16816(c1[0], c1[1], c1[2], c1[3],
                         a[mt][0], a[mt][1], a[mt][2], a[mt][3], bl2, bl3);
            }
        }
    }
}

// ---------------------------------------------------------------------------
// GEMM1 fused-xcvt (R13-proven).
// ---------------------------------------------------------------------------
__global__ void __launch_bounds__(256, 2)
gemm1_fused_kernel(const float* __restrict__ X,
                   const __half* __restrict__ Bhi, const __half* __restrict__ Blo,
                   const float* __restrict__ bias, float* __restrict__ C,
                   float2* __restrict__ gpart, int Mtot)
{
    constexpr int K = 512;
    constexpr int NSTAGES = K / 32;
    extern __shared__ char smem[];
    __shared__ float2 sred[4][128];
    const uint32_t sb = smem_u32(smem);

    const int tid   = threadIdx.x;
    const int lane  = tid & 31;
    const int wid   = tid >> 5;
    const int warpM = wid >> 2;
    const int warpN = wid & 3;
    const size_t rowBase = (size_t)blockIdx.y * 128;
    const int    colBase = blockIdx.x * 128;

    const int c0r = tid >> 2,  cq = tid & 3;
    const int c1r = 64 + c0r;
    const uint32_t d0 = swz(c0r, cq);
    const uint32_t d1 = swz(c1r, cq);
    const uint32_t f00 = swzf(c0r, 2 * cq), f01 = swzf(c0r, 2 * cq + 1);
    const uint32_t f10 = swzf(c1r, 2 * cq), f11 = swzf(c1r, 2 * cq + 1);
    const float* x0p = X + (rowBase + c0r) * K + cq * 8;
    const float* x1p = X + (rowBase + c1r) * K + cq * 8;

    float acc[4][4][4];
#pragma unroll
    for (int i = 0; i < 4; i++)
#pragma unroll
        for (int j = 0; j < 4; j++)
#pragma unroll
            for (int q = 0; q < 4; q++) acc[i][j][q] = 0.f;

    auto load_stage = [&](int t) {
        const int k0 = t * 32;
        const uint32_t sA = sb + OFF_STAGE + (t & 1) * STAGE_SZ;
        cp_async16(sA + f00, x0p + k0);
        cp_async16(sA + f01, x0p + k0 + 4);
        cp_async16(sA + f10, x1p + k0);
        cp_async16(sA + f11, x1p + k0 + 4);
        const uint32_t sB = sb + (t % 3) * B_STG;
        const size_t g0 = (size_t)(colBase + c0r) * K + k0 + cq * 8;
        const size_t g1 = (size_t)(colBase + c1r) * K + k0 + cq * 8;
        cp_async16(sB + d0,           Bhi + g0);
        cp_async16(sB + d1,           Bhi + g1);
        cp_async16(sB + OFF_BLO + d0, Blo + g0);
        cp_async16(sB + OFF_BLO + d1, Blo + g1);
        CP_COMMIT();
    };

    load_stage(0);
    load_stage(1);

#pragma unroll 1
    for (int t = 0; t < NSTAGES; t++) {
        if (t + 1 < NSTAGES) { CP_WAIT(1); } else { CP_WAIT(0); }
        {
            const char* stg = smem + OFF_STAGE + (t & 1) * STAGE_SZ;
            const uint32_t abase = OFF_ABF + (t & 1) * A_STG;
            const float4 v0 = *reinterpret_cast<const float4*>(stg + f00);
            const float4 v1 = *reinterpret_cast<const float4*>(stg + f01);
            const float4 v2 = *reinterpret_cast<const float4*>(stg + f10);
            const float4 v3 = *reinterpret_cast<const float4*>(stg + f11);
            *reinterpret_cast<uint4*>(smem + abase + d0) = make_uint4(
                pack_half2(v0.x, v0.y), pack_half2(v0.z, v0.w),
                pack_half2(v1.x, v1.y), pack_half2(v1.z, v1.w));
            *reinterpret_cast<uint4*>(smem + abase + d1) = make_uint4(
                pack_half2(v2.x, v2.y), pack_half2(v2.z, v2.w),
                pack_half2(v3.x, v3.y), pack_half2(v3.z, v3.w));
        }
        __syncthreads();
        if (t + 2 < NSTAGES) load_stage(t + 2);

        mma_stage(sb + OFF_ABF + (t & 1) * A_STG, sb + (t % 3) * B_STG, OFF_BLO,
                  lane, warpM, warpN, acc);
    }

#pragma unroll
    for (int mt = 0; mt < 4; mt++) {
        const int rloc = warpM * 64 + mt * 16 + (lane >> 2);
        const size_t r0 = rowBase + rloc;
        float s0 = 0.f, q0 = 0.f, s1 = 0.f, q1 = 0.f;
#pragma unroll
        for (int nt = 0; nt < 4; nt++) {
            const int col = colBase + warpN * 32 + nt * 8 + (lane & 3) * 2;
            const float b0 = bias[col], b1 = bias[col + 1];
            float* c = acc[mt][nt];
            const float v00 = c[0] + b0, v01 = c[1] + b1;
            const float v10 = c[2] + b0, v11 = c[3] + b1;
            *reinterpret_cast<float2*>(C + r0 * 512 + col)       = make_float2(v00, v01);
            *reinterpret_cast<float2*>(C + (r0 + 8) * 512 + col) = make_float2(v10, v11);
            s0 += v00 + v01; q0 += v00 * v00 + v01 * v01;
            s1 += v10 + v11; q1 += v10 * v10 + v11 * v11;
        }
#pragma unroll
        for (int o = 1; o <= 2; o <<= 1) {
            s0 += __shfl_xor_sync(0xffffffffu, s0, o);
            q0 += __shfl_xor_sync(0xffffffffu, q0, o);
            s1 += __shfl_xor_sync(0xffffffffu, s1, o);
            q1 += __shfl_xor_sync(0xffffffffu, q1, o);
        }
        if ((lane & 3) == 0) {
            sred[warpN][rloc]     = make_float2(s0, q0);
            sred[warpN][rloc + 8] = make_float2(s1, q1);
        }
    }
    __syncthreads();
    if (tid < 128) {
        float s = 0.f, q = 0.f;
#pragma unroll
        for (int w = 0; w < 4; w++) { s += sred[w][tid].x; q += sred[w][tid].y; }
        gpart[(size_t)blockIdx.x * Mtot + rowBase + tid] = make_float2(s, q);
    }
}

// ---------------------------------------------------------------------------
// GEMM2 fused (R12/R13-proven).
// ---------------------------------------------------------------------------
__global__ void __launch_bounds__(256, 2)
gemm2_fused_kernel(const float* __restrict__ h1raw, const float2* __restrict__ gpart,
                   const float* __restrict__ g1, const float* __restrict__ be1,
                   const __half* __restrict__ Bhi, const __half* __restrict__ Blo,
                   const float* __restrict__ b2, const float* __restrict__ g2,
                   const float* __restrict__ be2,
                   float* __restrict__ h2, int Mtot)
{
    constexpr int K = 512;
    constexpr int NSTAGES = K / 32;
    extern __shared__ char smem[];
    __shared__ float  smu[128], srstd[128];
    __shared__ float  sg1[512], sbe1[512];
    __shared__ float  sg2[128], sbe2[128], sb2[128];
    __shared__ float2 sred[4][128];
    const uint32_t sb = smem_u32(smem);

    const int tid   = threadIdx.x;
    const int lane  = tid & 31;
    const int wid   = tid >> 5;
    const int warpM = wid >> 2;
    const int warpN = wid & 3;
    const size_t rowBase = (size_t)blockIdx.x * 128;

    if (tid < 128) {
        float s = 0.f, q = 0.f;
#pragma unroll
        for (int b = 0; b < 4; b++) {
            float2 p = gpart[(size_t)b * Mtot + rowBase + tid];
            s += p.x; q += p.y;
        }
        const float mu = s * (1.f / 512.f);
        smu[tid]   = mu;
        srstd[tid] = rsqrtf(q * (1.f / 512.f) - mu * mu + 1e-5f);
        sg2[tid] = g2[tid]; sbe2[tid] = be2[tid]; sb2[tid] = b2[tid];
    }
#pragma unroll
    for (int i = tid; i < 512; i += 256) { sg1[i] = g1[i]; sbe1[i] = be1[i]; }
    __syncthreads();

    const int c0r = tid >> 2,  cq = tid & 3;
    const int c1r = 64 + c0r;
    const uint32_t d0 = swz(c0r, cq);
    const uint32_t d1 = swz(c1r, cq);

    const float* a0p = h1raw + (rowBase + c0r) * K + cq * 8;
    const float* a1p = h1raw + (rowBase + c1r) * K + cq * 8;
    const float mu0 = smu[c0r], rs0 = srstd[c0r];
    const float mu1 = smu[c1r], rs1 = srstd[c1r];

    float acc[4][4][4];
#pragma unroll
    for (int i = 0; i < 4; i++)
#pragma unroll
        for (int j = 0; j < 4; j++)
#pragma unroll
            for (int q = 0; q < 4; q++) acc[i][j][q] = 0.f;

    float4 fA[4];
    auto prefetchA = [&](int t) {
        fA[0] = *reinterpret_cast<const float4*>(a0p + t * 32);
        fA[1] = *reinterpret_cast<const float4*>(a0p + t * 32 + 4);
        fA[2] = *reinterpret_cast<const float4*>(a1p + t * 32);
        fA[3] = *reinterpret_cast<const float4*>(a1p + t * 32 + 4);
    };
    auto load_B = [&](int t) {
        const int k0 = t * 32;
        const uint32_t s = sb + (t % 3) * B_STG;
        const size_t g0 = (size_t)c0r * K + k0 + cq * 8;
        const size_t g1 = (size_t)c1r * K + k0 + cq * 8;
        cp_async16(s + d0,           Bhi + g0);
        cp_async16(s + d1,           Bhi + g1);
        cp_async16(s + OFF_BLO + d0, Blo + g0);
        cp_async16(s + OFF_BLO + d1, Blo + g1);
        CP_COMMIT();
    };

    prefetchA(0);
    load_B(0);
    load_B(1);

#pragma unroll 1
    for (int t = 0; t < NSTAGES; t++) {
        {
            const uint32_t abase = OFF_A2 + (t % 3) * A_STG;
            const int kcol = t * 32 + cq * 8;
            uint32_t p[4];
#pragma unroll
            for (int j = 0; j < 2; j++) {
                const float* v = (j == 0) ? &fA[0].x : &fA[1].x;
#pragma unroll
                for (int e = 0; e < 2; e++) {
                    const int col = kcol + j * 4 + e * 2;
                    const float a0c = rs0 * sg1[col],     b0c = sbe1[col]     - mu0 * a0c;
                    const float a1c = rs0 * sg1[col + 1], b1c = sbe1[col + 1] - mu0 * a1c;
                    float y0 = celu_fast(v[2*e]   * a0c + b0c);
                    float y1 = celu_fast(v[2*e+1] * a1c + b1c);
                    p[2 * j + e] = pack_half2(y0, y1);
                }
            }
            *reinterpret_cast<uint4*>(smem + abase + d0) = make_uint4(p[0], p[1], p[2], p[3]);
#pragma unroll
            for (int j = 0; j < 2; j++) {
                const float* v = (j == 0) ? &fA[2].x : &fA[3].x;
#pragma unroll
                for (int e = 0; e < 2; e++) {
                    const int col = kcol + j * 4 + e * 2;
                    const float a0c = rs1 * sg1[col],     b0c = sbe1[col]     - mu1 * a0c;
                    const float a1c = rs1 * sg1[col + 1], b1c = sbe1[col + 1] - mu1 * a1c;
                    float y0 = celu_fast(v[2*e]   * a0c + b0c);
                    float y1 = celu_fast(v[2*e+1] * a1c + b1c);
                    p[2 * j + e] = pack_half2(y0, y1);
                }
            }
            *reinterpret_cast<uint4*>(smem + abase + d1) = make_uint4(p[0], p[1], p[2], p[3]);
        }
        if (t + 1 < NSTAGES) prefetchA(t + 1);
        if (t + 1 < NSTAGES) { CP_WAIT(1); } else { CP_WAIT(0); }
        __syncthreads();
        if (t + 2 < NSTAGES) load_B(t + 2);

        mma_stage(sb + OFF_A2 + (t % 3) * A_STG, sb + (t % 3) * B_STG, OFF_BLO,
                  lane, warpM, warpN, acc);
    }

#pragma unroll
    for (int mt = 0; mt < 4; mt++) {
        const int rloc = warpM * 64 + mt * 16 + (lane >> 2);
        float s0 = 0.f, q0 = 0.f, s1 = 0.f, q1 = 0.f;
#pragma unroll
        for (int nt = 0; nt < 4; nt++) {
            const int col = warpN * 32 + nt * 8 + (lane & 3) * 2;
            const float b0 = sb2[col], b1 = sb2[col + 1];
            float* c = acc[mt][nt];
            const float v00 = c[0] + b0, v01 = c[1] + b1;
            const float v10 = c[2] + b0, v11 = c[3] + b1;
            s0 += v00 + v01; q0 += v00 * v00 + v01 * v01;
            s1 += v10 + v11; q1 += v10 * v10 + v11 * v11;
        }
#pragma unroll
        for (int o = 1; o <= 2; o <<= 1) {
            s0 += __shfl_xor_sync(0xffffffffu, s0, o);
            q0 += __shfl_xor_sync(0xffffffffu, q0, o);
            s1 += __shfl_xor_sync(0xffffffffu, s1, o);
            q1 += __shfl_xor_sync(0xffffffffu, q1, o);
        }
        if ((lane & 3) == 0) {
            sred[warpN][rloc]     = make_float2(s0, q0);
            sred[warpN][rloc + 8] = make_float2(s1, q1);
        }
    }
    __syncthreads();
    if (tid < 128) {
        float s = 0.f, q = 0.f;
#pragma unroll
        for (int w = 0; w < 4; w++) { s += sred[w][tid].x; q += sred[w][tid].y; }
        const float mu = s * (1.f / 128.f);
        smu[tid]   = mu;
        srstd[tid] = rsqrtf(q * (1.f / 128.f) - mu * mu + 1e-5f);
    }
    __syncthreads();
#pragma unroll
    for (int mt = 0; mt < 4; mt++) {
        const int rloc = warpM * 64 + mt * 16 + (lane >> 2);
        const float m0 = smu[rloc],     r0s = srstd[rloc];
        const float m1 = smu[rloc + 8], r1s = srstd[rloc + 8];
        const size_t r0 = rowBase + rloc;
#pragma unroll
        for (int nt = 0; nt < 4; nt++) {
            const int col = warpN * 32 + nt * 8 + (lane & 3) * 2;
            const float b0 = sb2[col], b1 = sb2[col + 1];
            float* c = acc[mt][nt];
            float y00 = (c[0] + b0 - m0) * r0s * sg2[col]     + sbe2[col];
            float y01 = (c[1] + b1 - m0) * r0s * sg2[col + 1] + sbe2[col + 1];
            float y10 = (c[2] + b0 - m1) * r1s * sg2[col]     + sbe2[col];
            float y11 = (c[3] + b1 - m1) * r1s * sg2[col + 1] + sbe2[col + 1];
            *reinterpret_cast<float2*>(h2 + r0 * 128 + col) =
                make_float2(celu_fast(y00), celu_fast(y01));
            *reinterpret_cast<float2*>(h2 + (r0 + 8) * 128 + col) =
                make_float2(celu_fast(y10), celu_fast(y11));
        }
    }
}

// ---------------------------------------------------------------------------
// Tail v3: 4 rows per warp per weight fetch.
//  layer3: per kg, 1 weight LDS.128 serves 4 rows (broadcast row reads),
//          cutting smem crossbar traffic ~3.7x vs R14 (which was L1=96.6%).
//  layer4/LN/head: per-row, same as R14 but x4 in registers.
// ---------------------------------------------------------------------------
__global__ void __launch_bounds__(256)
tail_kernel(const float* __restrict__ h2,
            const float* __restrict__ W3, const float* __restrict__ b3,
            const float* __restrict__ g3, const float* __restrict__ be3,
            const float* __restrict__ W4, const float* __restrict__ b4,
            const float* __restrict__ g4, const float* __restrict__ be4,
            const float* __restrict__ Wh, const float* __restrict__ bh,
            const float* __restrict__ u, float* __restrict__ out)
{
    __shared__ __align__(16) float4 sW3T[32 * 32];   // [kg][j] = W3[j][4kg..]
    __shared__ __align__(16) float4 sW4T[8 * 8];     // [kg][j] = W4[j][4kg..]
    __shared__ __align__(16) float  srow[8][4][128]; // per-warp 4-row buffer

    const int tid = threadIdx.x;
    for (int idx = tid; idx < 1024; idx += 256) {
        const int kg = idx >> 5, j = idx & 31;
        sW3T[idx] = *reinterpret_cast<const float4*>(W3 + j * 128 + kg * 4);
    }
    if (tid < 64) {
        const int kg = tid >> 3, j = tid & 7;
        sW4T[tid] = *reinterpret_cast<const float4*>(W4 + j * 32 + kg * 4);
    }
    __syncthreads();

    const int lane = tid & 31;
    const int w    = tid >> 5;
    const size_t rowBase = (size_t)blockIdx.x * 32 + w * 4;

    // stage 4 rows into per-warp smem
#pragma unroll
    for (int r = 0; r < 4; r++) {
        const float* rp = h2 + (rowBase + r) * 128;
        srow[w][r][lane]      = rp[lane];
        srow[w][r][lane + 32] = rp[lane + 32];
        srow[w][r][lane + 64] = rp[lane + 64];
        srow[w][r][lane + 96] = rp[lane + 96];
    }
    __syncwarp();

    // layer3: h3[r] for output j = lane; 1 weight fetch serves 4 rows
    float h3[4] = {0.f, 0.f, 0.f, 0.f};
#pragma unroll
    for (int kg = 0; kg < 32; kg++) {
        const float4 wv = sW3T[kg * 32 + lane];
#pragma unroll
        for (int r = 0; r < 4; r++) {
            const float4 sv = reinterpret_cast<const float4*>(srow[w][r])[kg];
            h3[r] += sv.x * wv.x + sv.y * wv.y + sv.z * wv.z + sv.w * wv.w;
        }
    }
    const float bb3 = b3[lane], gg3 = g3[lane], bbe3 = be3[lane];
    float c3[4];
#pragma unroll
    for (int r = 0; r < 4; r++) {
        const float h = h3[r] + bb3;
        const float mu  = warp_sum(h) * (1.f / 32.f);
        const float d   = h - mu;
        const float var = warp_sum(d * d) * (1.f / 32.f);
        c3[r] = celu_fast(d * rsqrtf(var + 1e-5f) * gg3 + bbe3);
    }

    // stage c3 (4 rows x 32)
    __syncwarp();
#pragma unroll
    for (int r = 0; r < 4; r++) srow[w][r][lane] = c3[r];
    __syncwarp();

    // layer4: 8 outputs, lanes replicated x4; 1 weight fetch serves 4 rows
    const int j8 = lane & 7;
    float h4[4] = {0.f, 0.f, 0.f, 0.f};
#pragma unroll
    for (int kg = 0; kg < 8; kg++) {
        const float4 wv = sW4T[kg * 8 + j8];
#pragma unroll
        for (int r = 0; r < 4; r++) {
            const float4 sv = reinterpret_cast<const float4*>(srow[w][r])[kg];
            h4[r] += sv.x * wv.x + sv.y * wv.y + sv.z * wv.z + sv.w * wv.w;
        }
    }

    // spectral-norm sigma (row-independent)
    const float wh   = Wh[j8];
    const float nrm  = sqrtf(sum8(wh * wh));
    const float u0   = u[0];
    const float vden = fabsf(u0) * nrm + 1e-12f;
    const float t    = u0 * nrm * nrm / vden;
    const float u2n  = t / (fabsf(t) + 1e-12f);
    const float sigma = u2n * t;
    const float whs  = wh / sigma;
    const float bb4 = b4[j8], gg4 = g4[j8], bbe4 = be4[j8], bh0 = bh[0];

#pragma unroll
    for (int r = 0; r < 4; r++) {
        const float h = h4[r] + bb4;
        const float mu  = sum8(h) * 0.125f;
        const float d   = h - mu;
        const float var = sum8(d * d) * 0.125f;
        const float c4  = celu_fast(d * rsqrtf(var + 1e-5f) * gg4 + bbe4);
        const float p   = sum8(c4 * whs);
        if (lane == 0) out[rowBase + r] = p + bh0;
    }
}

// ---------------------------------------------------------------------------
extern "C" void kernel_launch(void* const* d_in, const int* in_sizes, int n_in,
                              void* d_out, int out_size)
{
    const float* x   = (const float*)d_in[0];
    const float* W1  = (const float*)d_in[1];
    const float* b1  = (const float*)d_in[2];
    const float* g1  = (const float*)d_in[3];
    const float* be1 = (const float*)d_in[4];
    const float* W2  = (const float*)d_in[5];
    const float* b2  = (const float*)d_in[6];
    const float* g2  = (const float*)d_in[7];
    const float* be2 = (const float*)d_in[8];
    const float* W3  = (const float*)d_in[9];
    const float* b3  = (const float*)d_in[10];
    const float* g3  = (const float*)d_in[11];
    const float* be3 = (const float*)d_in[12];
    const float* W4  = (const float*)d_in[13];
    const float* b4  = (const float*)d_in[14];
    const float* g4  = (const float*)d_in[15];
    const float* be4 = (const float*)d_in[16];
    const float* Wh  = (const float*)d_in[17];
    const float* bh  = (const float*)d_in[18];
    const float* u   = (const float*)d_in[19];
    float* out = (float*)d_out;

    const int M = in_sizes[0] / 512;   // 131072

    __half *w1hi, *w1lo, *w2hi, *w2lo;
    float *h1raw, *h2;
    float2* part;
    cudaGetSymbolAddress((void**)&h1raw, g_h1raw);
    cudaGetSymbolAddress((void**)&h2,    g_h2);
    cudaGetSymbolAddress((void**)&part,  g_part);
    cudaGetSymbolAddress((void**)&w1hi,  g_w1hi);
    cudaGetSymbolAddress((void**)&w1lo,  g_w1lo);
    cudaGetSymbolAddress((void**)&w2hi,  g_w2hi);
    cudaGetSymbolAddress((void**)&w2lo,  g_w2lo);

    cudaFuncSetAttribute(gemm1_fused_kernel,
                         cudaFuncAttributeMaxDynamicSharedMemorySize, SMEM_G1);
    cudaFuncSetAttribute(gemm2_fused_kernel,
                         cudaFuncAttributeMaxDynamicSharedMemorySize, SMEM_G2);

    const int n4w1 = 512 * 512 / 4, n4w2 = 128 * 512 / 4;
    wsplit2_kernel<<<(n4w1 + n4w2 + 255) / 256, 256>>>(
        W1, w1hi, w1lo, n4w1, W2, w2hi, w2lo, n4w2);

    gemm1_fused_kernel<<<dim3(4, M / 128), 256, SMEM_G1>>>(
        x, w1hi, w1lo, b1, h1raw, part, M);

    gemm2_fused_kernel<<<M / 128, 256, SMEM_G2>>>(
        h1raw, part, g1, be1, w2hi, w2lo, b2, g2, be2, h2, M);

    tail_kernel<<<M / 32, 256>>>(h2, W3, b3, g3, be3, W4, b4, g4, be4, Wh, bh, u, out);
}

// round 16
// speedup vs baseline: 2.0852x; 1.2389x over previous
#include <cuda_runtime.h>
#include <cuda_fp16.h>
#include <cstdint>

// ---------------------------------------------------------------------------
// B=131072, chain 512 ->(W1)512 ->(W2)128 ->(W3)32 ->(W4)8 ->(Wh)1
// GEMM1: SINGLE-pass fp16 HMMA (W1 single fp16; precision budget spent here),
//        fused x->fp16 staging convert, LN partials. 2 CTAs/SM.
// GEMM2: fp16 asymmetric-split (W2 = hi+lo, 2 passes) fused LN1+CELU+LN2.
// tail:  4-rows-per-weight-fetch output-stationary (R15-proven, 87us).
// ---------------------------------------------------------------------------

#define BATCH 131072

__device__ __align__(256) float  g_h1raw[BATCH * 512];
__device__ __align__(256) float  g_h2   [BATCH * 128];
__device__ __align__(256) float2 g_part [4 * BATCH];
__device__ __align__(256) __half g_w1h  [512 * 512];
__device__ __align__(256) __half g_w2hi [128 * 512];
__device__ __align__(256) __half g_w2lo [128 * 512];

// ------------------------------ helpers ------------------------------------
__device__ __forceinline__ uint32_t smem_u32(const void* p) {
    uint32_t a;
    asm("{ .reg .u64 t; cvta.to.shared.u64 t, %1; cvt.u32.u64 %0, t; }"
        : "=r"(a) : "l"(p));
    return a;
}
__device__ __forceinline__ void cp_async16(uint32_t dst, const void* src) {
    asm volatile("cp.async.cg.shared.global [%0], [%1], 16;"
                 :: "r"(dst), "l"(src) : "memory");
}
#define CP_COMMIT() asm volatile("cp.async.commit_group;" ::: "memory")
#define CP_WAIT(n)  asm volatile("cp.async.wait_group %0;" :: "n"(n) : "memory")

__device__ __forceinline__ void ldmx4(uint32_t& r0, uint32_t& r1,
                                      uint32_t& r2, uint32_t& r3, uint32_t a) {
    asm volatile("ldmatrix.sync.aligned.m8n8.x4.shared.b16 {%0,%1,%2,%3}, [%4];"
                 : "=r"(r0), "=r"(r1), "=r"(r2), "=r"(r3) : "r"(a));
}
__device__ __forceinline__ void mma16816(float& c0, float& c1, float& c2, float& c3,
                                         uint32_t a0, uint32_t a1, uint32_t a2, uint32_t a3,
                                         uint32_t b0, uint32_t b1) {
    asm volatile("mma.sync.aligned.m16n8k16.row.col.f32.f16.f16.f32 "
                 "{%0,%1,%2,%3}, {%4,%5,%6,%7}, {%8,%9}, {%0,%1,%2,%3};"
                 : "+f"(c0), "+f"(c1), "+f"(c2), "+f"(c3)
                 : "r"(a0), "r"(a1), "r"(a2), "r"(a3), "r"(b0), "r"(b1));
}
__device__ __forceinline__ float warp_sum(float v) {
#pragma unroll
    for (int o = 16; o; o >>= 1) v += __shfl_xor_sync(0xffffffffu, v, o);
    return v;
}
__device__ __forceinline__ float sum8(float v) {
#pragma unroll
    for (int o = 1; o <= 4; o <<= 1) v += __shfl_xor_sync(0xffffffffu, v, o);
    return v;
}
__device__ __forceinline__ uint32_t swz(uint32_t row, uint32_t q) {
    return row * 64 + (q ^ ((row & 6u) >> 1)) * 16;
}
__device__ __forceinline__ uint32_t swzf(uint32_t row, uint32_t q) {
    return row * 128 + (q ^ (row & 7u)) * 16;
}
__device__ __forceinline__ float celu_fast(float y) {
    return (y > 0.f) ? y : (__expf(y) - 1.f);
}
__device__ __forceinline__ uint32_t pack_half2(float a0, float a1) {
    __half2 t = __floats2half2_rn(a0, a1);
    return *reinterpret_cast<uint32_t*>(&t);
}
__device__ __forceinline__ void wsplit2(float a0, float a1, uint32_t& hp, uint32_t& lp) {
    __half h0 = __float2half_rn(a0), h1 = __float2half_rn(a1);
    __half2 hh; hh.x = h0; hh.y = h1;
    hp = *reinterpret_cast<uint32_t*>(&hh);
    lp = pack_half2(a0 - __half2float(h0), a1 - __half2float(h1));
}

// GEMM1 smem (73728): B ring 3x8K @0, fp32 staging 2x16K @24576, A 2x8K @57344
#define G1_BSTG   8192
#define G1_STAGE  24576
#define STAGE_SZ  16384
#define G1_ABF    57344
#define A_STG     8192
#define SMEM_G1   73728
// GEMM2 smem (73728): B ring 3x16K @0, A fp16 ring 3x8K @49152
#define B_STG     16384
#define OFF_BLO   8192
#define OFF_A2    49152
#define SMEM_G2   73728

// ---------------------------------------------------------------------------
// Weight prep: W1 -> single fp16; W2 -> fp16 hi + lo. One launch.
// ---------------------------------------------------------------------------
__global__ void __launch_bounds__(256)
wprep_kernel(const float* __restrict__ W1, __half* __restrict__ w1h, int n41,
             const float* __restrict__ W2, __half* __restrict__ hi2,
             __half* __restrict__ lo2, int n42)
{
    int i = blockIdx.x * blockDim.x + threadIdx.x;
    if (i < n41) {
        float4 v = reinterpret_cast<const float4*>(W1)[i];
        uint2 o;
        o.x = pack_half2(v.x, v.y);
        o.y = pack_half2(v.z, v.w);
        reinterpret_cast<uint2*>(w1h)[i] = o;
        return;
    }
    i -= n41;
    if (i >= n42) return;
    float4 v = reinterpret_cast<const float4*>(W2)[i];
    uint32_t h0, l0, h1, l1;
    wsplit2(v.x, v.y, h0, l0);
    wsplit2(v.z, v.w, h1, l1);
    reinterpret_cast<uint32_t*>(hi2)[2 * i]     = h0;
    reinterpret_cast<uint32_t*>(hi2)[2 * i + 1] = h1;
    reinterpret_cast<uint32_t*>(lo2)[2 * i]     = l0;
    reinterpret_cast<uint32_t*>(lo2)[2 * i + 1] = l1;
}

// ---------------------------------------------------------------------------
// Single-B-pass MMA stage (GEMM1).
// ---------------------------------------------------------------------------
__device__ __forceinline__ void mma_stage_1w(uint32_t sa, uint32_t sbB,
                                             int lane, int warpM, int warpN,
                                             float acc[4][4][4])
{
#pragma unroll
    for (int ks = 0; ks < 2; ks++) {
        uint32_t a[4][4];
        const uint32_t arow = warpM * 64 + (lane & 15);
        const uint32_t aq   = ks * 2 + (lane >> 4);
#pragma unroll
        for (int mt = 0; mt < 4; mt++) {
            const uint32_t adr = sa + swz(arow + mt * 16, aq);
            ldmx4(a[mt][0], a[mt][1], a[mt][2], a[mt][3], adr);
        }
        const uint32_t brow0 = warpN * 32 + (lane & 7) + ((lane >> 4) & 1) * 8;
        const uint32_t bq    = ks * 2 + ((lane >> 3) & 1);
#pragma unroll
        for (int pr = 0; pr < 2; pr++) {
            uint32_t bh0, bh1, bh2, bh3;
            ldmx4(bh0, bh1, bh2, bh3, sbB + swz(brow0 + pr * 16, bq));
#pragma unroll
            for (int mt = 0; mt < 4; mt++) {
                float* c0 = acc[mt][2 * pr];
                mma16816(c0[0], c0[1], c0[2], c0[3],
                         a[mt][0], a[mt][1], a[mt][2], a[mt][3], bh0, bh1);
                float* c1 = acc[mt][2 * pr + 1];
                mma16816(c1[0], c1[1], c1[2], c1[3],
                         a[mt][0], a[mt][1], a[mt][2], a[mt][3], bh2, bh3);
            }
        }
    }
}

// Two-pass (hi/lo) MMA stage (GEMM2, proven).
__device__ __forceinline__ void mma_stage_2w(uint32_t sa, uint32_t sbB, uint32_t blo_off,
                                             int lane, int warpM, int warpN,
                                             float acc[4][4][4])
{
#pragma unroll
    for (int ks = 0; ks < 2; ks++) {
        uint32_t a[4][4];
        const uint32_t arow = warpM * 64 + (lane & 15);
        const uint32_t aq   = ks * 2 + (lane >> 4);
#pragma unroll
        for (int mt = 0; mt < 4; mt++) {
            const uint32_t adr = sa + swz(arow + mt * 16, aq);
            ldmx4(a[mt][0], a[mt][1], a[mt][2], a[mt][3], adr);
        }
        const uint32_t brow0 = warpN * 32 + (lane & 7) + ((lane >> 4) & 1) * 8;
        const uint32_t bq    = ks * 2 + ((lane >> 3) & 1);
#pragma unroll
        for (int pr = 0; pr < 2; pr++) {
            uint32_t bh0, bh1, bh2, bh3, bl0, bl1, bl2, bl3;
            const uint32_t adr = sbB + swz(brow0 + pr * 16, bq);
            ldmx4(bh0, bh1, bh2, bh3, adr);
            ldmx4(bl0, bl1, bl2, bl3, adr + blo_off);
#pragma unroll
            for (int mt = 0; mt < 4; mt++) {
                float* c0 = acc[mt][2 * pr];
                mma16816(c0[0], c0[1], c0[2], c0[3],
                         a[mt][0], a[mt][1], a[mt][2], a[mt][3], bh0, bh1);
                mma16816(c0[0], c0[1], c0[2], c0[3],
                         a[mt][0], a[mt][1], a[mt][2], a[mt][3], bl0, bl1);
                float* c1 = acc[mt][2 * pr + 1];
                mma16816(c1[0], c1[1], c1[2], c1[3],
                         a[mt][0], a[mt][1], a[mt][2], a[mt][3], bh2, bh3);
                mma16816(c1[0], c1[1], c1[2], c1[3],
                         a[mt][0], a[mt][1], a[mt][2], a[mt][3], bl2, bl3);
            }
        }
    }
}

// ---------------------------------------------------------------------------
// GEMM1: h1raw = x @ W1^T + b1 (fp32) + LN partials.  W1 single fp16.
// A: cp.async fp32 staging -> fp16 convert -> tile (R13/R15-proven path).
// ---------------------------------------------------------------------------
__global__ void __launch_bounds__(256, 2)
gemm1_fused_kernel(const float* __restrict__ X,
                   const __half* __restrict__ Bh,
                   const float* __restrict__ bias, float* __restrict__ C,
                   float2* __restrict__ gpart, int Mtot)
{
    constexpr int K = 512;
    constexpr int NSTAGES = K / 32;
    extern __shared__ char smem[];
    __shared__ float2 sred[4][128];
    const uint32_t sb = smem_u32(smem);

    const int tid   = threadIdx.x;
    const int lane  = tid & 31;
    const int wid   = tid >> 5;
    const int warpM = wid >> 2;
    const int warpN = wid & 3;
    const size_t rowBase = (size_t)blockIdx.y * 128;
    const int    colBase = blockIdx.x * 128;

    const int c0r = tid >> 2,  cq = tid & 3;
    const int c1r = 64 + c0r;
    const uint32_t d0 = swz(c0r, cq);
    const uint32_t d1 = swz(c1r, cq);
    const uint32_t f00 = swzf(c0r, 2 * cq), f01 = swzf(c0r, 2 * cq + 1);
    const uint32_t f10 = swzf(c1r, 2 * cq), f11 = swzf(c1r, 2 * cq + 1);
    const float* x0p = X + (rowBase + c0r) * K + cq * 8;
    const float* x1p = X + (rowBase + c1r) * K + cq * 8;

    float acc[4][4][4];
#pragma unroll
    for (int i = 0; i < 4; i++)
#pragma unroll
        for (int j = 0; j < 4; j++)
#pragma unroll
            for (int q = 0; q < 4; q++) acc[i][j][q] = 0.f;

    auto load_stage = [&](int t) {
        const int k0 = t * 32;
        const uint32_t sA = sb + G1_STAGE + (t & 1) * STAGE_SZ;
        cp_async16(sA + f00, x0p + k0);
        cp_async16(sA + f01, x0p + k0 + 4);
        cp_async16(sA + f10, x1p + k0);
        cp_async16(sA + f11, x1p + k0 + 4);
        const uint32_t sB = sb + (t % 3) * G1_BSTG;
        cp_async16(sB + d0, Bh + (size_t)(colBase + c0r) * K + k0 + cq * 8);
        cp_async16(sB + d1, Bh + (size_t)(colBase + c1r) * K + k0 + cq * 8);
        CP_COMMIT();
    };

    load_stage(0);
    load_stage(1);

#pragma unroll 1
    for (int t = 0; t < NSTAGES; t++) {
        if (t + 1 < NSTAGES) { CP_WAIT(1); } else { CP_WAIT(0); }
        {
            const char* stg = smem + G1_STAGE + (t & 1) * STAGE_SZ;
            const uint32_t abase = G1_ABF + (t & 1) * A_STG;
            const float4 v0 = *reinterpret_cast<const float4*>(stg + f00);
            const float4 v1 = *reinterpret_cast<const float4*>(stg + f01);
            const float4 v2 = *reinterpret_cast<const float4*>(stg + f10);
            const float4 v3 = *reinterpret_cast<const float4*>(stg + f11);
            *reinterpret_cast<uint4*>(smem + abase + d0) = make_uint4(
                pack_half2(v0.x, v0.y), pack_half2(v0.z, v0.w),
                pack_half2(v1.x, v1.y), pack_half2(v1.z, v1.w));
            *reinterpret_cast<uint4*>(smem + abase + d1) = make_uint4(
                pack_half2(v2.x, v2.y), pack_half2(v2.z, v2.w),
                pack_half2(v3.x, v3.y), pack_half2(v3.z, v3.w));
        }
        __syncthreads();
        if (t + 2 < NSTAGES) load_stage(t + 2);

        mma_stage_1w(sb + G1_ABF + (t & 1) * A_STG, sb + (t % 3) * G1_BSTG,
                     lane, warpM, warpN, acc);
    }

#pragma unroll
    for (int mt = 0; mt < 4; mt++) {
        const int rloc = warpM * 64 + mt * 16 + (lane >> 2);
        const size_t r0 = rowBase + rloc;
        float s0 = 0.f, q0 = 0.f, s1 = 0.f, q1 = 0.f;
#pragma unroll
        for (int nt = 0; nt < 4; nt++) {
            const int col = colBase + warpN * 32 + nt * 8 + (lane & 3) * 2;
            const float b0 = bias[col], b1 = bias[col + 1];
            float* c = acc[mt][nt];
            const float v00 = c[0] + b0, v01 = c[1] + b1;
            const float v10 = c[2] + b0, v11 = c[3] + b1;
            *reinterpret_cast<float2*>(C + r0 * 512 + col)       = make_float2(v00, v01);
            *reinterpret_cast<float2*>(C + (r0 + 8) * 512 + col) = make_float2(v10, v11);
            s0 += v00 + v01; q0 += v00 * v00 + v01 * v01;
            s1 += v10 + v11; q1 += v10 * v10 + v11 * v11;
        }
#pragma unroll
        for (int o = 1; o <= 2; o <<= 1) {
            s0 += __shfl_xor_sync(0xffffffffu, s0, o);
            q0 += __shfl_xor_sync(0xffffffffu, q0, o);
            s1 += __shfl_xor_sync(0xffffffffu, s1, o);
            q1 += __shfl_xor_sync(0xffffffffu, q1, o);
        }
        if ((lane & 3) == 0) {
            sred[warpN][rloc]     = make_float2(s0, q0);
            sred[warpN][rloc + 8] = make_float2(s1, q1);
        }
    }
    __syncthreads();
    if (tid < 128) {
        float s = 0.f, q = 0.f;
#pragma unroll
        for (int w = 0; w < 4; w++) { s += sred[w][tid].x; q += sred[w][tid].y; }
        gpart[(size_t)blockIdx.x * Mtot + rowBase + tid] = make_float2(s, q);
    }
}

// ---------------------------------------------------------------------------
// GEMM2 fused (R12/R15-proven, W2 hi/lo kept for accuracy).
// ---------------------------------------------------------------------------
__global__ void __launch_bounds__(256, 2)
gemm2_fused_kernel(const float* __restrict__ h1raw, const float2* __restrict__ gpart,
                   const float* __restrict__ g1, const float* __restrict__ be1,
                   const __half* __restrict__ Bhi, const __half* __restrict__ Blo,
                   const float* __restrict__ b2, const float* __restrict__ g2,
                   const float* __restrict__ be2,
                   float* __restrict__ h2, int Mtot)
{
    constexpr int K = 512;
    constexpr int NSTAGES = K / 32;
    extern __shared__ char smem[];
    __shared__ float  smu[128], srstd[128];
    __shared__ float  sg1[512], sbe1[512];
    __shared__ float  sg2[128], sbe2[128], sb2[128];
    __shared__ float2 sred[4][128];
    const uint32_t sb = smem_u32(smem);

    const int tid   = threadIdx.x;
    const int lane  = tid & 31;
    const int wid   = tid >> 5;
    const int warpM = wid >> 2;
    const int warpN = wid & 3;
    const size_t rowBase = (size_t)blockIdx.x * 128;

    if (tid < 128) {
        float s = 0.f, q = 0.f;
#pragma unroll
        for (int b = 0; b < 4; b++) {
            float2 p = gpart[(size_t)b * Mtot + rowBase + tid];
            s += p.x; q += p.y;
        }
        const float mu = s * (1.f / 512.f);
        smu[tid]   = mu;
        srstd[tid] = rsqrtf(q * (1.f / 512.f) - mu * mu + 1e-5f);
        sg2[tid] = g2[tid]; sbe2[tid] = be2[tid]; sb2[tid] = b2[tid];
    }
#pragma unroll
    for (int i = tid; i < 512; i += 256) { sg1[i] = g1[i]; sbe1[i] = be1[i]; }
    __syncthreads();

    const int c0r = tid >> 2,  cq = tid & 3;
    const int c1r = 64 + c0r;
    const uint32_t d0 = swz(c0r, cq);
    const uint32_t d1 = swz(c1r, cq);

    const float* a0p = h1raw + (rowBase + c0r) * K + cq * 8;
    const float* a1p = h1raw + (rowBase + c1r) * K + cq * 8;
    const float mu0 = smu[c0r], rs0 = srstd[c0r];
    const float mu1 = smu[c1r], rs1 = srstd[c1r];

    float acc[4][4][4];
#pragma unroll
    for (int i = 0; i < 4; i++)
#pragma unroll
        for (int j = 0; j < 4; j++)
#pragma unroll
            for (int q = 0; q < 4; q++) acc[i][j][q] = 0.f;

    float4 fA[4];
    auto prefetchA = [&](int t) {
        fA[0] = *reinterpret_cast<const float4*>(a0p + t * 32);
        fA[1] = *reinterpret_cast<const float4*>(a0p + t * 32 + 4);
        fA[2] = *reinterpret_cast<const float4*>(a1p + t * 32);
        fA[3] = *reinterpret_cast<const float4*>(a1p + t * 32 + 4);
    };
    auto load_B = [&](int t) {
        const int k0 = t * 32;
        const uint32_t s = sb + (t % 3) * B_STG;
        const size_t g0 = (size_t)c0r * K + k0 + cq * 8;
        const size_t g1 = (size_t)c1r * K + k0 + cq * 8;
        cp_async16(s + d0,           Bhi + g0);
        cp_async16(s + d1,           Bhi + g1);
        cp_async16(s + OFF_BLO + d0, Blo + g0);
        cp_async16(s + OFF_BLO + d1, Blo + g1);
        CP_COMMIT();
    };

    prefetchA(0);
    load_B(0);
    load_B(1);

#pragma unroll 1
    for (int t = 0; t < NSTAGES; t++) {
        {
            const uint32_t abase = OFF_A2 + (t % 3) * A_STG;
            const int kcol = t * 32 + cq * 8;
            uint32_t p[4];
#pragma unroll
            for (int j = 0; j < 2; j++) {
                const float* v = (j == 0) ? &fA[0].x : &fA[1].x;
#pragma unroll
                for (int e = 0; e < 2; e++) {
                    const int col = kcol + j * 4 + e * 2;
                    const float a0c = rs0 * sg1[col],     b0c = sbe1[col]     - mu0 * a0c;
                    const float a1c = rs0 * sg1[col + 1], b1c = sbe1[col + 1] - mu0 * a1c;
                    float y0 = celu_fast(v[2*e]   * a0c + b0c);
                    float y1 = celu_fast(v[2*e+1] * a1c + b1c);
                    p[2 * j + e] = pack_half2(y0, y1);
                }
            }
            *reinterpret_cast<uint4*>(smem + abase + d0) = make_uint4(p[0], p[1], p[2], p[3]);
#pragma unroll
            for (int j = 0; j < 2; j++) {
                const float* v = (j == 0) ? &fA[2].x : &fA[3].x;
#pragma unroll
                for (int e = 0; e < 2; e++) {
                    const int col = kcol + j * 4 + e * 2;
                    const float a0c = rs1 * sg1[col],     b0c = sbe1[col]     - mu1 * a0c;
                    const float a1c = rs1 * sg1[col + 1], b1c = sbe1[col + 1] - mu1 * a1c;
                    float y0 = celu_fast(v[2*e]   * a0c + b0c);
                    float y1 = celu_fast(v[2*e+1] * a1c + b1c);
                    p[2 * j + e] = pack_half2(y0, y1);
                }
            }
            *reinterpret_cast<uint4*>(smem + abase + d1) = make_uint4(p[0], p[1], p[2], p[3]);
        }
        if (t + 1 < NSTAGES) prefetchA(t + 1);
        if (t + 1 < NSTAGES) { CP_WAIT(1); } else { CP_WAIT(0); }
        __syncthreads();
        if (t + 2 < NSTAGES) load_B(t + 2);

        mma_stage_2w(sb + OFF_A2 + (t % 3) * A_STG, sb + (t % 3) * B_STG, OFF_BLO,
                     lane, warpM, warpN, acc);
    }

#pragma unroll
    for (int mt = 0; mt < 4; mt++) {
        const int rloc = warpM * 64 + mt * 16 + (lane >> 2);
        float s0 = 0.f, q0 = 0.f, s1 = 0.f, q1 = 0.f;
#pragma unroll
        for (int nt = 0; nt < 4; nt++) {
            const int col = warpN * 32 + nt * 8 + (lane & 3) * 2;
            const float b0 = sb2[col], b1 = sb2[col + 1];
            float* c = acc[mt][nt];
            const float v00 = c[0] + b0, v01 = c[1] + b1;
            const float v10 = c[2] + b0, v11 = c[3] + b1;
            s0 += v00 + v01; q0 += v00 * v00 + v01 * v01;
            s1 += v10 + v11; q1 += v10 * v10 + v11 * v11;
        }
#pragma unroll
        for (int o = 1; o <= 2; o <<= 1) {
            s0 += __shfl_xor_sync(0xffffffffu, s0, o);
            q0 += __shfl_xor_sync(0xffffffffu, q0, o);
            s1 += __shfl_xor_sync(0xffffffffu, s1, o);
            q1 += __shfl_xor_sync(0xffffffffu, q1, o);
        }
        if ((lane & 3) == 0) {
            sred[warpN][rloc]     = make_float2(s0, q0);
            sred[warpN][rloc + 8] = make_float2(s1, q1);
        }
    }
    __syncthreads();
    if (tid < 128) {
        float s = 0.f, q = 0.f;
#pragma unroll
        for (int w = 0; w < 4; w++) { s += sred[w][tid].x; q += sred[w][tid].y; }
        const float mu = s * (1.f / 128.f);
        smu[tid]   = mu;
        srstd[tid] = rsqrtf(q * (1.f / 128.f) - mu * mu + 1e-5f);
    }
    __syncthreads();
#pragma unroll
    for (int mt = 0; mt < 4; mt++) {
        const int rloc = warpM * 64 + mt * 16 + (lane >> 2);
        const float m0 = smu[rloc],     r0s = srstd[rloc];
        const float m1 = smu[rloc + 8], r1s = srstd[rloc + 8];
        const size_t r0 = rowBase + rloc;
#pragma unroll
        for (int nt = 0; nt < 4; nt++) {
            const int col = warpN * 32 + nt * 8 + (lane & 3) * 2;
            const float b0 = sb2[col], b1 = sb2[col + 1];
            float* c = acc[mt][nt];
            float y00 = (c[0] + b0 - m0) * r0s * sg2[col]     + sbe2[col];
            float y01 = (c[1] + b1 - m0) * r0s * sg2[col + 1] + sbe2[col + 1];
            float y10 = (c[2] + b0 - m1) * r1s * sg2[col]     + sbe2[col];
            float y11 = (c[3] + b1 - m1) * r1s * sg2[col + 1] + sbe2[col + 1];
            *reinterpret_cast<float2*>(h2 + r0 * 128 + col) =
                make_float2(celu_fast(y00), celu_fast(y01));
            *reinterpret_cast<float2*>(h2 + (r0 + 8) * 128 + col) =
                make_float2(celu_fast(y10), celu_fast(y11));
        }
    }
}

// ---------------------------------------------------------------------------
// Tail v3 (R15-proven): 4 rows per warp per weight fetch.
// ---------------------------------------------------------------------------
__global__ void __launch_bounds__(256)
tail_kernel(const float* __restrict__ h2,
            const float* __restrict__ W3, const float* __restrict__ b3,
            const float* __restrict__ g3, const float* __restrict__ be3,
            const float* __restrict__ W4, const float* __restrict__ b4,
            const float* __restrict__ g4, const float* __restrict__ be4,
            const float* __restrict__ Wh, const float* __restrict__ bh,
            const float* __restrict__ u, float* __restrict__ out)
{
    __shared__ __align__(16) float4 sW3T[32 * 32];
    __shared__ __align__(16) float4 sW4T[8 * 8];
    __shared__ __align__(16) float  srow[8][4][128];

    const int tid = threadIdx.x;
    for (int idx = tid; idx < 1024; idx += 256) {
        const int kg = idx >> 5, j = idx & 31;
        sW3T[idx] = *reinterpret_cast<const float4*>(W3 + j * 128 + kg * 4);
    }
    if (tid < 64) {
        const int kg = tid >> 3, j = tid & 7;
        sW4T[tid] = *reinterpret_cast<const float4*>(W4 + j * 32 + kg * 4);
    }
    __syncthreads();

    const int lane = tid & 31;
    const int w    = tid >> 5;
    const size_t rowBase = (size_t)blockIdx.x * 32 + w * 4;

#pragma unroll
    for (int r = 0; r < 4; r++) {
        const float* rp = h2 + (rowBase + r) * 128;
        srow[w][r][lane]      = rp[lane];
        srow[w][r][lane + 32] = rp[lane + 32];
        srow[w][r][lane + 64] = rp[lane + 64];
        srow[w][r][lane + 96] = rp[lane + 96];
    }
    __syncwarp();

    float h3[4] = {0.f, 0.f, 0.f, 0.f};
#pragma unroll
    for (int kg = 0; kg < 32; kg++) {
        const float4 wv = sW3T[kg * 32 + lane];
#pragma unroll
        for (int r = 0; r < 4; r++) {
            const float4 sv = reinterpret_cast<const float4*>(srow[w][r])[kg];
            h3[r] += sv.x * wv.x + sv.y * wv.y + sv.z * wv.z + sv.w * wv.w;
        }
    }
    const float bb3 = b3[lane], gg3 = g3[lane], bbe3 = be3[lane];
    float c3[4];
#pragma unroll
    for (int r = 0; r < 4; r++) {
        const float h = h3[r] + bb3;
        const float mu  = warp_sum(h) * (1.f / 32.f);
        const float d   = h - mu;
        const float var = warp_sum(d * d) * (1.f / 32.f);
        c3[r] = celu_fast(d * rsqrtf(var + 1e-5f) * gg3 + bbe3);
    }

    __syncwarp();
#pragma unroll
    for (int r = 0; r < 4; r++) srow[w][r][lane] = c3[r];
    __syncwarp();

    const int j8 = lane & 7;
    float h4[4] = {0.f, 0.f, 0.f, 0.f};
#pragma unroll
    for (int kg = 0; kg < 8; kg++) {
        const float4 wv = sW4T[kg * 8 + j8];
#pragma unroll
        for (int r = 0; r < 4; r++) {
            const float4 sv = reinterpret_cast<const float4*>(srow[w][r])[kg];
            h4[r] += sv.x * wv.x + sv.y * wv.y + sv.z * wv.z + sv.w * wv.w;
        }
    }

    const float wh   = Wh[j8];
    const float nrm  = sqrtf(sum8(wh * wh));
    const float u0   = u[0];
    const float vden = fabsf(u0) * nrm + 1e-12f;
    const float t    = u0 * nrm * nrm / vden;
    const float u2n  = t / (fabsf(t) + 1e-12f);
    const float sigma = u2n * t;
    const float whs  = wh / sigma;
    const float bb4 = b4[j8], gg4 = g4[j8], bbe4 = be4[j8], bh0 = bh[0];

#pragma unroll
    for (int r = 0; r < 4; r++) {
        const float h = h4[r] + bb4;
        const float mu  = sum8(h) * 0.125f;
        const float d   = h - mu;
        const float var = sum8(d * d) * 0.125f;
        const float c4  = celu_fast(d * rsqrtf(var + 1e-5f) * gg4 + bbe4);
        const float p   = sum8(c4 * whs);
        if (lane == 0) out[rowBase + r] = p + bh0;
    }
}

// ---------------------------------------------------------------------------
extern "C" void kernel_launch(void* const* d_in, const int* in_sizes, int n_in,
                              void* d_out, int out_size)
{
    const float* x   = (const float*)d_in[0];
    const float* W1  = (const float*)d_in[1];
    const float* b1  = (const float*)d_in[2];
    const float* g1  = (const float*)d_in[3];
    const float* be1 = (const float*)d_in[4];
    const float* W2  = (const float*)d_in[5];
    const float* b2  = (const float*)d_in[6];
    const float* g2  = (const float*)d_in[7];
    const float* be2 = (const float*)d_in[8];
    const float* W3  = (const float*)d_in[9];
    const float* b3  = (const float*)d_in[10];
    const float* g3  = (const float*)d_in[11];
    const float* be3 = (const float*)d_in[12];
    const float* W4  = (const float*)d_in[13];
    const float* b4  = (const float*)d_in[14];
    const float* g4  = (const float*)d_in[15];
    const float* be4 = (const float*)d_in[16];
    const float* Wh  = (const float*)d_in[17];
    const float* bh  = (const float*)d_in[18];
    const float* u   = (const float*)d_in[19];
    float* out = (float*)d_out;

    const int M = in_sizes[0] / 512;   // 131072

    __half *w1h, *w2hi, *w2lo;
    float *h1raw, *h2;
    float2* part;
    cudaGetSymbolAddress((void**)&h1raw, g_h1raw);
    cudaGetSymbolAddress((void**)&h2,    g_h2);
    cudaGetSymbolAddress((void**)&part,  g_part);
    cudaGetSymbolAddress((void**)&w1h,   g_w1h);
    cudaGetSymbolAddress((void**)&w2hi,  g_w2hi);
    cudaGetSymbolAddress((void**)&w2lo,  g_w2lo);

    cudaFuncSetAttribute(gemm1_fused_kernel,
                         cudaFuncAttributeMaxDynamicSharedMemorySize, SMEM_G1);
    cudaFuncSetAttribute(gemm2_fused_kernel,
                         cudaFuncAttributeMaxDynamicSharedMemorySize, SMEM_G2);

    const int n4w1 = 512 * 512 / 4, n4w2 = 128 * 512 / 4;
    wprep_kernel<<<(n4w1 + n4w2 + 255) / 256, 256>>>(
        W1, w1h, n4w1, W2, w2hi, w2lo, n4w2);

    gemm1_fused_kernel<<<dim3(4, M / 128), 256, SMEM_G1>>>(
        x, w1h, b1, h1raw, part, M);

    gemm2_fused_kernel<<<M / 128, 256, SMEM_G2>>>(
        h1raw, part, g1, be1, w2hi, w2lo, b2, g2, be2, h2, M);

    tail_kernel<<<M / 32, 256>>>(h2, W3, b3, g3, be3, W4, b4, g4, be4, Wh, bh, u, out);
}

// round 17
// speedup vs baseline: 2.2991x; 1.1026x over previous
#include <cuda_runtime.h>
#include <cuda_fp16.h>
#include <cstdint>

// ---------------------------------------------------------------------------
// B=131072, chain 512 ->(W1)512 ->(W2)128 ->(W3)32 ->(W4)8 ->(Wh)1
// Both GEMMs: single-pass fp16 HMMA (weights single fp16; measured error
// budget: 3.77e-4 act-quant + 2.6e-4 per dropped W-lo, quadrature ~5.4e-4).
// GEMM1: fused x->fp16 staging convert + LN partials.
// GEMM2: fused LN1+fastCELU+fp16 -> HMMA -> LN2+fastCELU -> h2.
// tail:  8 rows per warp per weight fetch (crossbar law, R15/R16-validated).
// ---------------------------------------------------------------------------

#define BATCH 131072

__device__ __align__(256) float  g_h1raw[BATCH * 512];
__device__ __align__(256) float  g_h2   [BATCH * 128];
__device__ __align__(256) float2 g_part [4 * BATCH];
__device__ __align__(256) __half g_w1h  [512 * 512];
__device__ __align__(256) __half g_w2h  [128 * 512];

// ------------------------------ helpers ------------------------------------
__device__ __forceinline__ uint32_t smem_u32(const void* p) {
    uint32_t a;
    asm("{ .reg .u64 t; cvta.to.shared.u64 t, %1; cvt.u32.u64 %0, t; }"
        : "=r"(a) : "l"(p));
    return a;
}
__device__ __forceinline__ void cp_async16(uint32_t dst, const void* src) {
    asm volatile("cp.async.cg.shared.global [%0], [%1], 16;"
                 :: "r"(dst), "l"(src) : "memory");
}
#define CP_COMMIT() asm volatile("cp.async.commit_group;" ::: "memory")
#define CP_WAIT(n)  asm volatile("cp.async.wait_group %0;" :: "n"(n) : "memory")

__device__ __forceinline__ void ldmx4(uint32_t& r0, uint32_t& r1,
                                      uint32_t& r2, uint32_t& r3, uint32_t a) {
    asm volatile("ldmatrix.sync.aligned.m8n8.x4.shared.b16 {%0,%1,%2,%3}, [%4];"
                 : "=r"(r0), "=r"(r1), "=r"(r2), "=r"(r3) : "r"(a));
}
__device__ __forceinline__ void mma16816(float& c0, float& c1, float& c2, float& c3,
                                         uint32_t a0, uint32_t a1, uint32_t a2, uint32_t a3,
                                         uint32_t b0, uint32_t b1) {
    asm volatile("mma.sync.aligned.m16n8k16.row.col.f32.f16.f16.f32 "
                 "{%0,%1,%2,%3}, {%4,%5,%6,%7}, {%8,%9}, {%0,%1,%2,%3};"
                 : "+f"(c0), "+f"(c1), "+f"(c2), "+f"(c3)
                 : "r"(a0), "r"(a1), "r"(a2), "r"(a3), "r"(b0), "r"(b1));
}
__device__ __forceinline__ float warp_sum(float v) {
#pragma unroll
    for (int o = 16; o; o >>= 1) v += __shfl_xor_sync(0xffffffffu, v, o);
    return v;
}
__device__ __forceinline__ float sum8(float v) {
#pragma unroll
    for (int o = 1; o <= 4; o <<= 1) v += __shfl_xor_sync(0xffffffffu, v, o);
    return v;
}
__device__ __forceinline__ uint32_t swz(uint32_t row, uint32_t q) {
    return row * 64 + (q ^ ((row & 6u) >> 1)) * 16;
}
__device__ __forceinline__ uint32_t swzf(uint32_t row, uint32_t q) {
    return row * 128 + (q ^ (row & 7u)) * 16;
}
__device__ __forceinline__ float celu_fast(float y) {
    return (y > 0.f) ? y : (__expf(y) - 1.f);
}
__device__ __forceinline__ uint32_t pack_half2(float a0, float a1) {
    __half2 t = __floats2half2_rn(a0, a1);
    return *reinterpret_cast<uint32_t*>(&t);
}

// GEMM1 smem (73728): B ring 3x8K @0, fp32 staging 2x16K @24576, A 2x8K @57344
#define G1_BSTG   8192
#define G1_STAGE  24576
#define STAGE_SZ  16384
#define G1_ABF    57344
#define A_STG     8192
#define SMEM_G1   73728
// GEMM2 smem (49152): B ring 3x8K @0, A fp16 ring 3x8K @24576
#define G2_BSTG   8192
#define OFF_A2    24576
#define SMEM_G2   49152

// ---------------------------------------------------------------------------
// Weight prep: W1 and W2 -> single fp16. One launch.
// ---------------------------------------------------------------------------
__global__ void __launch_bounds__(256)
wprep_kernel(const float* __restrict__ W1, __half* __restrict__ w1h, int n41,
             const float* __restrict__ W2, __half* __restrict__ w2h, int n42)
{
    int i = blockIdx.x * blockDim.x + threadIdx.x;
    const float* src; __half* dst;
    if (i < n41) { src = W1; dst = w1h; }
    else {
        i -= n41;
        if (i >= n42) return;
        src = W2; dst = w2h;
    }
    float4 v = reinterpret_cast<const float4*>(src)[i];
    uint2 o;
    o.x = pack_half2(v.x, v.y);
    o.y = pack_half2(v.z, v.w);
    reinterpret_cast<uint2*>(dst)[i] = o;
}

// ---------------------------------------------------------------------------
// Single-B-pass MMA stage.
// ---------------------------------------------------------------------------
__device__ __forceinline__ void mma_stage_1w(uint32_t sa, uint32_t sbB,
                                             int lane, int warpM, int warpN,
                                             float acc[4][4][4])
{
#pragma unroll
    for (int ks = 0; ks < 2; ks++) {
        uint32_t a[4][4];
        const uint32_t arow = warpM * 64 + (lane & 15);
        const uint32_t aq   = ks * 2 + (lane >> 4);
#pragma unroll
        for (int mt = 0; mt < 4; mt++) {
            const uint32_t adr = sa + swz(arow + mt * 16, aq);
            ldmx4(a[mt][0], a[mt][1], a[mt][2], a[mt][3], adr);
        }
        const uint32_t brow0 = warpN * 32 + (lane & 7) + ((lane >> 4) & 1) * 8;
        const uint32_t bq    = ks * 2 + ((lane >> 3) & 1);
#pragma unroll
        for (int pr = 0; pr < 2; pr++) {
            uint32_t bh0, bh1, bh2, bh3;
            ldmx4(bh0, bh1, bh2, bh3, sbB + swz(brow0 + pr * 16, bq));
#pragma unroll
            for (int mt = 0; mt < 4; mt++) {
                float* c0 = acc[mt][2 * pr];
                mma16816(c0[0], c0[1], c0[2], c0[3],
                         a[mt][0], a[mt][1], a[mt][2], a[mt][3], bh0, bh1);
                float* c1 = acc[mt][2 * pr + 1];
                mma16816(c1[0], c1[1], c1[2], c1[3],
                         a[mt][0], a[mt][1], a[mt][2], a[mt][3], bh2, bh3);
            }
        }
    }
}

// ---------------------------------------------------------------------------
// GEMM1 (R16-proven): h1raw = x @ W1^T + b1 (fp32) + LN partials.
// ---------------------------------------------------------------------------
__global__ void __launch_bounds__(256, 2)
gemm1_fused_kernel(const float* __restrict__ X,
                   const __half* __restrict__ Bh,
                   const float* __restrict__ bias, float* __restrict__ C,
                   float2* __restrict__ gpart, int Mtot)
{
    constexpr int K = 512;
    constexpr int NSTAGES = K / 32;
    extern __shared__ char smem[];
    __shared__ float2 sred[4][128];
    const uint32_t sb = smem_u32(smem);

    const int tid   = threadIdx.x;
    const int lane  = tid & 31;
    const int wid   = tid >> 5;
    const int warpM = wid >> 2;
    const int warpN = wid & 3;
    const size_t rowBase = (size_t)blockIdx.y * 128;
    const int    colBase = blockIdx.x * 128;

    const int c0r = tid >> 2,  cq = tid & 3;
    const int c1r = 64 + c0r;
    const uint32_t d0 = swz(c0r, cq);
    const uint32_t d1 = swz(c1r, cq);
    const uint32_t f00 = swzf(c0r, 2 * cq), f01 = swzf(c0r, 2 * cq + 1);
    const uint32_t f10 = swzf(c1r, 2 * cq), f11 = swzf(c1r, 2 * cq + 1);
    const float* x0p = X + (rowBase + c0r) * K + cq * 8;
    const float* x1p = X + (rowBase + c1r) * K + cq * 8;

    float acc[4][4][4];
#pragma unroll
    for (int i = 0; i < 4; i++)
#pragma unroll
        for (int j = 0; j < 4; j++)
#pragma unroll
            for (int q = 0; q < 4; q++) acc[i][j][q] = 0.f;

    auto load_stage = [&](int t) {
        const int k0 = t * 32;
        const uint32_t sA = sb + G1_STAGE + (t & 1) * STAGE_SZ;
        cp_async16(sA + f00, x0p + k0);
        cp_async16(sA + f01, x0p + k0 + 4);
        cp_async16(sA + f10, x1p + k0);
        cp_async16(sA + f11, x1p + k0 + 4);
        const uint32_t sB = sb + (t % 3) * G1_BSTG;
        cp_async16(sB + d0, Bh + (size_t)(colBase + c0r) * K + k0 + cq * 8);
        cp_async16(sB + d1, Bh + (size_t)(colBase + c1r) * K + k0 + cq * 8);
        CP_COMMIT();
    };

    load_stage(0);
    load_stage(1);

#pragma unroll 1
    for (int t = 0; t < NSTAGES; t++) {
        if (t + 1 < NSTAGES) { CP_WAIT(1); } else { CP_WAIT(0); }
        {
            const char* stg = smem + G1_STAGE + (t & 1) * STAGE_SZ;
            const uint32_t abase = G1_ABF + (t & 1) * A_STG;
            const float4 v0 = *reinterpret_cast<const float4*>(stg + f00);
            const float4 v1 = *reinterpret_cast<const float4*>(stg + f01);
            const float4 v2 = *reinterpret_cast<const float4*>(stg + f10);
            const float4 v3 = *reinterpret_cast<const float4*>(stg + f11);
            *reinterpret_cast<uint4*>(smem + abase + d0) = make_uint4(
                pack_half2(v0.x, v0.y), pack_half2(v0.z, v0.w),
                pack_half2(v1.x, v1.y), pack_half2(v1.z, v1.w));
            *reinterpret_cast<uint4*>(smem + abase + d1) = make_uint4(
                pack_half2(v2.x, v2.y), pack_half2(v2.z, v2.w),
                pack_half2(v3.x, v3.y), pack_half2(v3.z, v3.w));
        }
        __syncthreads();
        if (t + 2 < NSTAGES) load_stage(t + 2);

        mma_stage_1w(sb + G1_ABF + (t & 1) * A_STG, sb + (t % 3) * G1_BSTG,
                     lane, warpM, warpN, acc);
    }

#pragma unroll
    for (int mt = 0; mt < 4; mt++) {
        const int rloc = warpM * 64 + mt * 16 + (lane >> 2);
        const size_t r0 = rowBase + rloc;
        float s0 = 0.f, q0 = 0.f, s1 = 0.f, q1 = 0.f;
#pragma unroll
        for (int nt = 0; nt < 4; nt++) {
            const int col = colBase + warpN * 32 + nt * 8 + (lane & 3) * 2;
            const float b0 = bias[col], b1 = bias[col + 1];
            float* c = acc[mt][nt];
            const float v00 = c[0] + b0, v01 = c[1] + b1;
            const float v10 = c[2] + b0, v11 = c[3] + b1;
            *reinterpret_cast<float2*>(C + r0 * 512 + col)       = make_float2(v00, v01);
            *reinterpret_cast<float2*>(C + (r0 + 8) * 512 + col) = make_float2(v10, v11);
            s0 += v00 + v01; q0 += v00 * v00 + v01 * v01;
            s1 += v10 + v11; q1 += v10 * v10 + v11 * v11;
        }
#pragma unroll
        for (int o = 1; o <= 2; o <<= 1) {
            s0 += __shfl_xor_sync(0xffffffffu, s0, o);
            q0 += __shfl_xor_sync(0xffffffffu, q0, o);
            s1 += __shfl_xor_sync(0xffffffffu, s1, o);
            q1 += __shfl_xor_sync(0xffffffffu, q1, o);
        }
        if ((lane & 3) == 0) {
            sred[warpN][rloc]     = make_float2(s0, q0);
            sred[warpN][rloc + 8] = make_float2(s1, q1);
        }
    }
    __syncthreads();
    if (tid < 128) {
        float s = 0.f, q = 0.f;
#pragma unroll
        for (int w = 0; w < 4; w++) { s += sred[w][tid].x; q += sred[w][tid].y; }
        gpart[(size_t)blockIdx.x * Mtot + rowBase + tid] = make_float2(s, q);
    }
}

// ---------------------------------------------------------------------------
// GEMM2 fused, single-pass W2: a1 = celu_fast(LN1(h1raw)) fp16 -> HMMA ->
// LN2 + celu_fast -> h2.
// ---------------------------------------------------------------------------
__global__ void __launch_bounds__(256, 2)
gemm2_fused_kernel(const float* __restrict__ h1raw, const float2* __restrict__ gpart,
                   const float* __restrict__ g1, const float* __restrict__ be1,
                   const __half* __restrict__ Bh,
                   const float* __restrict__ b2, const float* __restrict__ g2,
                   const float* __restrict__ be2,
                   float* __restrict__ h2, int Mtot)
{
    constexpr int K = 512;
    constexpr int NSTAGES = K / 32;
    extern __shared__ char smem[];
    __shared__ float  smu[128], srstd[128];
    __shared__ float  sg1[512], sbe1[512];
    __shared__ float  sg2[128], sbe2[128], sb2[128];
    __shared__ float2 sred[4][128];
    const uint32_t sb = smem_u32(smem);

    const int tid   = threadIdx.x;
    const int lane  = tid & 31;
    const int wid   = tid >> 5;
    const int warpM = wid >> 2;
    const int warpN = wid & 3;
    const size_t rowBase = (size_t)blockIdx.x * 128;

    if (tid < 128) {
        float s = 0.f, q = 0.f;
#pragma unroll
        for (int b = 0; b < 4; b++) {
            float2 p = gpart[(size_t)b * Mtot + rowBase + tid];
            s += p.x; q += p.y;
        }
        const float mu = s * (1.f / 512.f);
        smu[tid]   = mu;
        srstd[tid] = rsqrtf(q * (1.f / 512.f) - mu * mu + 1e-5f);
        sg2[tid] = g2[tid]; sbe2[tid] = be2[tid]; sb2[tid] = b2[tid];
    }
#pragma unroll
    for (int i = tid; i < 512; i += 256) { sg1[i] = g1[i]; sbe1[i] = be1[i]; }
    __syncthreads();

    const int c0r = tid >> 2,  cq = tid & 3;
    const int c1r = 64 + c0r;
    const uint32_t d0 = swz(c0r, cq);
    const uint32_t d1 = swz(c1r, cq);

    const float* a0p = h1raw + (rowBase + c0r) * K + cq * 8;
    const float* a1p = h1raw + (rowBase + c1r) * K + cq * 8;
    const float mu0 = smu[c0r], rs0 = srstd[c0r];
    const float mu1 = smu[c1r], rs1 = srstd[c1r];

    float acc[4][4][4];
#pragma unroll
    for (int i = 0; i < 4; i++)
#pragma unroll
        for (int j = 0; j < 4; j++)
#pragma unroll
            for (int q = 0; q < 4; q++) acc[i][j][q] = 0.f;

    float4 fA[4];
    auto prefetchA = [&](int t) {
        fA[0] = *reinterpret_cast<const float4*>(a0p + t * 32);
        fA[1] = *reinterpret_cast<const float4*>(a0p + t * 32 + 4);
        fA[2] = *reinterpret_cast<const float4*>(a1p + t * 32);
        fA[3] = *reinterpret_cast<const float4*>(a1p + t * 32 + 4);
    };
    auto load_B = [&](int t) {
        const int k0 = t * 32;
        const uint32_t s = sb + (t % 3) * G2_BSTG;
        cp_async16(s + d0, Bh + (size_t)c0r * K + k0 + cq * 8);
        cp_async16(s + d1, Bh + (size_t)c1r * K + k0 + cq * 8);
        CP_COMMIT();
    };

    prefetchA(0);
    load_B(0);
    load_B(1);

#pragma unroll 1
    for (int t = 0; t < NSTAGES; t++) {
        {
            const uint32_t abase = OFF_A2 + (t % 3) * A_STG;
            const int kcol = t * 32 + cq * 8;
            uint32_t p[4];
#pragma unroll
            for (int j = 0; j < 2; j++) {
                const float* v = (j == 0) ? &fA[0].x : &fA[1].x;
#pragma unroll
                for (int e = 0; e < 2; e++) {
                    const int col = kcol + j * 4 + e * 2;
                    const float a0c = rs0 * sg1[col],     b0c = sbe1[col]     - mu0 * a0c;
                    const float a1c = rs0 * sg1[col + 1], b1c = sbe1[col + 1] - mu0 * a1c;
                    float y0 = celu_fast(v[2*e]   * a0c + b0c);
                    float y1 = celu_fast(v[2*e+1] * a1c + b1c);
                    p[2 * j + e] = pack_half2(y0, y1);
                }
            }
            *reinterpret_cast<uint4*>(smem + abase + d0) = make_uint4(p[0], p[1], p[2], p[3]);
#pragma unroll
            for (int j = 0; j < 2; j++) {
                const float* v = (j == 0) ? &fA[2].x : &fA[3].x;
#pragma unroll
                for (int e = 0; e < 2; e++) {
                    const int col = kcol + j * 4 + e * 2;
                    const float a0c = rs1 * sg1[col],     b0c = sbe1[col]     - mu1 * a0c;
                    const float a1c = rs1 * sg1[col + 1], b1c = sbe1[col + 1] - mu1 * a1c;
                    float y0 = celu_fast(v[2*e]   * a0c + b0c);
                    float y1 = celu_fast(v[2*e+1] * a1c + b1c);
                    p[2 * j + e] = pack_half2(y0, y1);
                }
            }
            *reinterpret_cast<uint4*>(smem + abase + d1) = make_uint4(p[0], p[1], p[2], p[3]);
        }
        if (t + 1 < NSTAGES) prefetchA(t + 1);
        if (t + 1 < NSTAGES) { CP_WAIT(1); } else { CP_WAIT(0); }
        __syncthreads();
        if (t + 2 < NSTAGES) load_B(t + 2);

        mma_stage_1w(sb + OFF_A2 + (t % 3) * A_STG, sb + (t % 3) * G2_BSTG,
                     lane, warpM, warpN, acc);
    }

#pragma unroll
    for (int mt = 0; mt < 4; mt++) {
        const int rloc = warpM * 64 + mt * 16 + (lane >> 2);
        float s0 = 0.f, q0 = 0.f, s1 = 0.f, q1 = 0.f;
#pragma unroll
        for (int nt = 0; nt < 4; nt++) {
            const int col = warpN * 32 + nt * 8 + (lane & 3) * 2;
            const float b0 = sb2[col], b1 = sb2[col + 1];
            float* c = acc[mt][nt];
            const float v00 = c[0] + b0, v01 = c[1] + b1;
            const float v10 = c[2] + b0, v11 = c[3] + b1;
            s0 += v00 + v01; q0 += v00 * v00 + v01 * v01;
            s1 += v10 + v11; q1 += v10 * v10 + v11 * v11;
        }
#pragma unroll
        for (int o = 1; o <= 2; o <<= 1) {
            s0 += __shfl_xor_sync(0xffffffffu, s0, o);
            q0 += __shfl_xor_sync(0xffffffffu, q0, o);
            s1 += __shfl_xor_sync(0xffffffffu, s1, o);
            q1 += __shfl_xor_sync(0xffffffffu, q1, o);
        }
        if ((lane & 3) == 0) {
            sred[warpN][rloc]     = make_float2(s0, q0);
            sred[warpN][rloc + 8] = make_float2(s1, q1);
        }
    }
    __syncthreads();
    if (tid < 128) {
        float s = 0.f, q = 0.f;
#pragma unroll
        for (int w = 0; w < 4; w++) { s += sred[w][tid].x; q += sred[w][tid].y; }
        const float mu = s * (1.f / 128.f);
        smu[tid]   = mu;
        srstd[tid] = rsqrtf(q * (1.f / 128.f) - mu * mu + 1e-5f);
    }
    __syncthreads();
#pragma unroll
    for (int mt = 0; mt < 4; mt++) {
        const int rloc = warpM * 64 + mt * 16 + (lane >> 2);
        const float m0 = smu[rloc],     r0s = srstd[rloc];
        const float m1 = smu[rloc + 8], r1s = srstd[rloc + 8];
        const size_t r0 = rowBase + rloc;
#pragma unroll
        for (int nt = 0; nt < 4; nt++) {
            const int col = warpN * 32 + nt * 8 + (lane & 3) * 2;
            const float b0 = sb2[col], b1 = sb2[col + 1];
            float* c = acc[mt][nt];
            float y00 = (c[0] + b0 - m0) * r0s * sg2[col]     + sbe2[col];
            float y01 = (c[1] + b1 - m0) * r0s * sg2[col + 1] + sbe2[col + 1];
            float y10 = (c[2] + b0 - m1) * r1s * sg2[col]     + sbe2[col];
            float y11 = (c[3] + b1 - m1) * r1s * sg2[col + 1] + sbe2[col + 1];
            *reinterpret_cast<float2*>(h2 + r0 * 128 + col) =
                make_float2(celu_fast(y00), celu_fast(y01));
            *reinterpret_cast<float2*>(h2 + (r0 + 8) * 128 + col) =
                make_float2(celu_fast(y10), celu_fast(y11));
        }
    }
}

// ---------------------------------------------------------------------------
// Tail v4: 8 rows per warp per weight fetch (crossbar traffic ~80 B/row/kg).
// ---------------------------------------------------------------------------
__global__ void __launch_bounds__(256)
tail_kernel(const float* __restrict__ h2,
            const float* __restrict__ W3, const float* __restrict__ b3,
            const float* __restrict__ g3, const float* __restrict__ be3,
            const float* __restrict__ W4, const float* __restrict__ b4,
            const float* __restrict__ g4, const float* __restrict__ be4,
            const float* __restrict__ Wh, const float* __restrict__ bh,
            const float* __restrict__ u, float* __restrict__ out)
{
    __shared__ __align__(16) float4 sW3T[32 * 32];    // [kg][j]
    __shared__ __align__(16) float4 sW4T[8 * 8];      // [kg][j]
    __shared__ __align__(16) float  srow[8][8][128];  // per-warp 8-row buffer

    const int tid = threadIdx.x;
    for (int idx = tid; idx < 1024; idx += 256) {
        const int kg = idx >> 5, j = idx & 31;
        sW3T[idx] = *reinterpret_cast<const float4*>(W3 + j * 128 + kg * 4);
    }
    if (tid < 64) {
        const int kg = tid >> 3, j = tid & 7;
        sW4T[tid] = *reinterpret_cast<const float4*>(W4 + j * 32 + kg * 4);
    }
    __syncthreads();

    const int lane = tid & 31;
    const int w    = tid >> 5;
    const size_t rowBase = (size_t)blockIdx.x * 64 + w * 8;

#pragma unroll
    for (int r = 0; r < 8; r++) {
        const float* rp = h2 + (rowBase + r) * 128;
        srow[w][r][lane]      = rp[lane];
        srow[w][r][lane + 32] = rp[lane + 32];
        srow[w][r][lane + 64] = rp[lane + 64];
        srow[w][r][lane + 96] = rp[lane + 96];
    }
    __syncwarp();

    float h3[8] = {0.f, 0.f, 0.f, 0.f, 0.f, 0.f, 0.f, 0.f};
#pragma unroll
    for (int kg = 0; kg < 32; kg++) {
        const float4 wv = sW3T[kg * 32 + lane];
#pragma unroll
        for (int r = 0; r < 8; r++) {
            const float4 sv = reinterpret_cast<const float4*>(srow[w][r])[kg];
            h3[r] += sv.x * wv.x + sv.y * wv.y + sv.z * wv.z + sv.w * wv.w;
        }
    }
    const float bb3 = b3[lane], gg3 = g3[lane], bbe3 = be3[lane];
    float c3[8];
#pragma unroll
    for (int r = 0; r < 8; r++) {
        const float h = h3[r] + bb3;
        const float mu  = warp_sum(h) * (1.f / 32.f);
        const float d   = h - mu;
        const float var = warp_sum(d * d) * (1.f / 32.f);
        c3[r] = celu_fast(d * rsqrtf(var + 1e-5f) * gg3 + bbe3);
    }

    __syncwarp();
#pragma unroll
    for (int r = 0; r < 8; r++) srow[w][r][lane] = c3[r];
    __syncwarp();

    const int j8 = lane & 7;
    float h4[8] = {0.f, 0.f, 0.f, 0.f, 0.f, 0.f, 0.f, 0.f};
#pragma unroll
    for (int kg = 0; kg < 8; kg++) {
        const float4 wv = sW4T[kg * 8 + j8];
#pragma unroll
        for (int r = 0; r < 8; r++) {
            const float4 sv = reinterpret_cast<const float4*>(srow[w][r])[kg];
            h4[r] += sv.x * wv.x + sv.y * wv.y + sv.z * wv.z + sv.w * wv.w;
        }
    }

    const float wh   = Wh[j8];
    const float nrm  = sqrtf(sum8(wh * wh));
    const float u0   = u[0];
    const float vden = fabsf(u0) * nrm + 1e-12f;
    const float t    = u0 * nrm * nrm / vden;
    const float u2n  = t / (fabsf(t) + 1e-12f);
    const float sigma = u2n * t;
    const float whs  = wh / sigma;
    const float bb4 = b4[j8], gg4 = g4[j8], bbe4 = be4[j8], bh0 = bh[0];

#pragma unroll
    for (int r = 0; r < 8; r++) {
        const float h = h4[r] + bb4;
        const float mu  = sum8(h) * 0.125f;
        const float d   = h - mu;
        const float var = sum8(d * d) * 0.125f;
        const float c4  = celu_fast(d * rsqrtf(var + 1e-5f) * gg4 + bbe4);
        const float p   = sum8(c4 * whs);
        if (lane == 0) out[rowBase + r] = p + bh0;
    }
}

// ---------------------------------------------------------------------------
extern "C" void kernel_launch(void* const* d_in, const int* in_sizes, int n_in,
                              void* d_out, int out_size)
{
    const float* x   = (const float*)d_in[0];
    const float* W1  = (const float*)d_in[1];
    const float* b1  = (const float*)d_in[2];
    const float* g1  = (const float*)d_in[3];
    const float* be1 = (const float*)d_in[4];
    const float* W2  = (const float*)d_in[5];
    const float* b2  = (const float*)d_in[6];
    const float* g2  = (const float*)d_in[7];
    const float* be2 = (const float*)d_in[8];
    const float* W3  = (const float*)d_in[9];
    const float* b3  = (const float*)d_in[10];
    const float* g3  = (const float*)d_in[11];
    const float* be3 = (const float*)d_in[12];
    const float* W4  = (const float*)d_in[13];
    const float* b4  = (const float*)d_in[14];
    const float* g4  = (const float*)d_in[15];
    const float* be4 = (const float*)d_in[16];
    const float* Wh  = (const float*)d_in[17];
    const float* bh  = (const float*)d_in[18];
    const float* u   = (const float*)d_in[19];
    float* out = (float*)d_out;

    const int M = in_sizes[0] / 512;   // 131072

    __half *w1h, *w2h;
    float *h1raw, *h2;
    float2* part;
    cudaGetSymbolAddress((void**)&h1raw, g_h1raw);
    cudaGetSymbolAddress((void**)&h2,    g_h2);
    cudaGetSymbolAddress((void**)&part,  g_part);
    cudaGetSymbolAddress((void**)&w1h,   g_w1h);
    cudaGetSymbolAddress((void**)&w2h,   g_w2h);

    cudaFuncSetAttribute(gemm1_fused_kernel,
                         cudaFuncAttributeMaxDynamicSharedMemorySize, SMEM_G1);
    cudaFuncSetAttribute(gemm2_fused_kernel,
                         cudaFuncAttributeMaxDynamicSharedMemorySize, SMEM_G2);

    const int n4w1 = 512 * 512 / 4, n4w2 = 128 * 512 / 4;
    wprep_kernel<<<(n4w1 + n4w2 + 255) / 256, 256>>>(W1, w1h, n4w1, W2, w2h, n4w2);

    gemm1_fused_kernel<<<dim3(4, M / 128), 256, SMEM_G1>>>(
        x, w1h, b1, h1raw, part, M);

    gemm2_fused_kernel<<<M / 128, 256, SMEM_G2>>>(
        h1raw, part, g1, be1, w2h, b2, g2, be2, h2, M);

    tail_kernel<<<M / 64, 256>>>(h2, W3, b3, g3, be3, W4, b4, g4, be4, Wh, bh, u, out);
}